// round 1
// baseline (speedup 1.0000x reference)
#include <cuda_runtime.h>
#include <math.h>

#define N_NODES 4096
#define F_DIM   512
#define H_DIM   256
#define H2_DIM  512

// ---------------- scratch (static device allocations; no runtime alloc) ----------
__device__ __align__(128) float g_xm[N_NODES * F_DIM];
__device__ __align__(128) float g_xs[N_NODES * F_DIM];
__device__ __align__(128) float g_m [N_NODES * F_DIM];
__device__ __align__(128) float g_cs[N_NODES * F_DIM];
__device__ __align__(128) float g_t0[N_NODES * H2_DIM];
__device__ __align__(128) float g_t1[N_NODES * H2_DIM];
__device__ __align__(128) float g_t2[N_NODES * H_DIM];
__device__ __align__(128) float g_M1[(size_t)N_NODES * N_NODES];
__device__ __align__(128) float g_M2[(size_t)N_NODES * N_NODES];
__device__ __align__(128) float g_sq[N_NODES];
__device__ __align__(128) float g_csum[N_NODES];
__device__ __align__(128) float g_rn[N_NODES];
__device__ __align__(128) float g_dis[N_NODES];
__device__ __align__(128) float g_degpart[32 * N_NODES];

// ---------------- block reduction ----------------
__device__ __forceinline__ float blockReduceSum(float v, float* sh) {
    __syncthreads();
    int lane = threadIdx.x & 31, wid = threadIdx.x >> 5;
    #pragma unroll
    for (int o = 16; o; o >>= 1) v += __shfl_down_sync(0xffffffffu, v, o);
    if (lane == 0) sh[wid] = v;
    __syncthreads();
    if (wid == 0) {
        float r = (lane < ((blockDim.x + 31) >> 5)) ? sh[lane] : 0.f;
        #pragma unroll
        for (int o = 16; o; o >>= 1) r += __shfl_down_sync(0xffffffffu, r, o);
        if (lane == 0) sh[0] = r;
    }
    __syncthreads();
    return sh[0];
}

// ---------------- tiled SGEMM ----------------
// MODE 0: C[M,N] = A[M,K] @ B[K,N]
// MODE 1: C[M,N] = A[M,K] @ B[N,K]^T   (NT: C_ij = A_i . B_j)
// MODE 2: C[M,N] = A[K,M]^T @ B[K,N]   (TN: C_jk = sum_i A_ij B_ik)
// All dims assumed: M%128==0, N%128==0 or N==256, K%16==0 (true for this problem).
template<int MODE, bool BIAS, bool RELU>
__global__ __launch_bounds__(256)
void gemm_k(const float* __restrict__ A, const float* __restrict__ B,
            float* __restrict__ C, int M, int N, int K,
            const float* __restrict__ bias)
{
    __shared__ float As[16][132];
    __shared__ float Bs[16][132];
    const int tid = threadIdx.x;
    const int tx = tid & 15;
    const int ty = tid >> 4;
    const int bm = blockIdx.y * 128;
    const int bn = blockIdx.x * 128;

    float acc[8][8];
    #pragma unroll
    for (int i = 0; i < 8; ++i)
        #pragma unroll
        for (int j = 0; j < 8; ++j) acc[i][j] = 0.f;

    for (int k0 = 0; k0 < K; k0 += 16) {
        // ---- load A tile into As[k][m] ----
        if (MODE == 2) {
            #pragma unroll
            for (int t = 0; t < 2; ++t) {
                int idx = tid + t * 256;
                int c = idx >> 5, m4 = (idx & 31) << 2;
                float4 v = *(const float4*)(A + (size_t)(k0 + c) * M + bm + m4);
                *(float4*)&As[c][m4] = v;
            }
        } else {
            #pragma unroll
            for (int t = 0; t < 2; ++t) {
                int idx = tid + t * 256;
                int r = idx >> 2, c4 = (idx & 3) << 2;
                float4 v = *(const float4*)(A + (size_t)(bm + r) * K + k0 + c4);
                As[c4 + 0][r] = v.x; As[c4 + 1][r] = v.y;
                As[c4 + 2][r] = v.z; As[c4 + 3][r] = v.w;
            }
        }
        // ---- load B tile into Bs[k][n] ----
        if (MODE == 1) {
            #pragma unroll
            for (int t = 0; t < 2; ++t) {
                int idx = tid + t * 256;
                int n = idx >> 2, c4 = (idx & 3) << 2;
                float4 v = *(const float4*)(B + (size_t)(bn + n) * K + k0 + c4);
                Bs[c4 + 0][n] = v.x; Bs[c4 + 1][n] = v.y;
                Bs[c4 + 2][n] = v.z; Bs[c4 + 3][n] = v.w;
            }
        } else {
            #pragma unroll
            for (int t = 0; t < 2; ++t) {
                int idx = tid + t * 256;
                int c = idx >> 5, n4 = (idx & 31) << 2;
                float4 v = *(const float4*)(B + (size_t)(k0 + c) * N + bn + n4);
                *(float4*)&Bs[c][n4] = v;
            }
        }
        __syncthreads();
        #pragma unroll
        for (int k = 0; k < 16; ++k) {
            float a[8], b[8];
            *(float4*)&a[0] = *(const float4*)&As[k][ty * 8];
            *(float4*)&a[4] = *(const float4*)&As[k][ty * 8 + 4];
            *(float4*)&b[0] = *(const float4*)&Bs[k][tx * 8];
            *(float4*)&b[4] = *(const float4*)&Bs[k][tx * 8 + 4];
            #pragma unroll
            for (int i = 0; i < 8; ++i)
                #pragma unroll
                for (int j = 0; j < 8; ++j)
                    acc[i][j] = fmaf(a[i], b[j], acc[i][j]);
        }
        __syncthreads();
    }

    #pragma unroll
    for (int i = 0; i < 8; ++i) {
        size_t row = (size_t)(bm + ty * 8 + i);
        float* Cp = C + row * (size_t)N + bn + tx * 8;
        #pragma unroll
        for (int jv = 0; jv < 2; ++jv) {
            float vv[4];
            #pragma unroll
            for (int j = 0; j < 4; ++j) {
                float val = acc[i][jv * 4 + j];
                if (BIAS) val += bias[bn + tx * 8 + jv * 4 + j];
                if (RELU) val = fmaxf(val, 0.f);
                vv[j] = val;
            }
            float4 v; v.x = vv[0]; v.y = vv[1]; v.z = vv[2]; v.w = vv[3];
            *(float4*)(Cp + jv * 4) = v;
        }
    }
}

// ---------------- per-row stats: m = l2norm(xm), c = l2norm(exp(xs)), cs=sqrt(c) ----
__global__ void rowstats_kernel(const float* __restrict__ xm, const float* __restrict__ xs,
                                float* __restrict__ m, float* __restrict__ cs,
                                float* __restrict__ sq, float* __restrict__ csum)
{
    __shared__ float sh[32];
    int row = blockIdx.x;
    const float* xmr = xm + (size_t)row * F_DIM;
    const float* xsr = xs + (size_t)row * F_DIM;
    float s1 = 0.f, s2 = 0.f, s3 = 0.f;
    for (int j = threadIdx.x; j < F_DIM; j += blockDim.x) {
        float a = xmr[j]; s1 = fmaf(a, a, s1);
        float e = expf(xsr[j]); s2 = fmaf(e, e, s2); s3 += e;
    }
    s1 = blockReduceSum(s1, sh);
    s2 = blockReduceSum(s2, sh);
    s3 = blockReduceSum(s3, sh);
    float dm = fmaxf(sqrtf(s1), 1e-12f);
    float dc = fmaxf(sqrtf(s2), 1e-12f);
    if (threadIdx.x == 0) {
        sq[row] = s1 / (dm * dm);
        csum[row] = s3 / dc;
    }
    for (int j = threadIdx.x; j < F_DIM; j += blockDim.x) {
        m[(size_t)row * F_DIM + j] = xmr[j] / dm;
        cs[(size_t)row * F_DIM + j] = sqrtf(expf(xsr[j]) / dc);
    }
}

// ---------------- ws = exp(-(max(sq_i+sq_j-2*G1,0) + csum_i+csum_j-2*G2)) in place ----
__global__ void ws_kernel(float* __restrict__ M1, const float* __restrict__ M2,
                          const float* __restrict__ sq, const float* __restrict__ csum)
{
    size_t idx = (size_t)blockIdx.x * 256 + threadIdx.x;
    int i = (int)(idx >> 12), j = (int)(idx & 4095);
    float d2 = fmaxf(sq[i] + sq[j] - 2.f * M1[idx], 0.f);
    float res = d2 + csum[i] + csum[j] - 2.f * M2[idx];
    M1[idx] = expf(-res);
}

__global__ void rownorm_kernel(const float* __restrict__ M1, float* __restrict__ rn) {
    __shared__ float sh[32];
    int row = blockIdx.x;
    const float* r = M1 + (size_t)row * N_NODES;
    float s = 0.f;
    for (int j = threadIdx.x; j < N_NODES; j += blockDim.x) { float v = r[j]; s = fmaf(v, v, s); }
    s = blockReduceSum(s, sh);
    if (threadIdx.x == 0) rn[row] = fmaxf(sqrtf(s), 1e-12f);
}

// ---------------- adjacency: mix with new_edge, logit trick, sigmoid, threshold, self-loops
__global__ void adj_kernel(float* __restrict__ M1, const float* __restrict__ rn,
                           const float* __restrict__ ne, const float* __restrict__ epsm,
                           const float* __restrict__ beta, const float* __restrict__ delta)
{
    size_t idx = (size_t)blockIdx.x * 256 + threadIdx.x;
    int i = (int)(idx >> 12), j = (int)(idx & 4095);
    float b = beta[0], d = delta[0];
    float w = M1[idx] / rn[i];
    float t = (1.f - b) * w + b * ne[idx];
    t = fminf(fmaxf(t, 1e-6f), 1.f - 1e-6f);
    float e = fminf(fmaxf(epsm[idx], 1e-6f), 1.f - 1e-6f);
    // sigmoid(logit(t) + logit(e)) == t*e / (t*e + (1-t)*(1-e))
    float num = t * e;
    float s = num / (num + (1.f - t) * (1.f - e));
    float a = (s > d) ? s : 0.f;
    if (i == j && !(a > 0.f)) a += 1.f;   // add_remaining_self_loops(fill=1)
    M1[idx] = a;
}

// ---------------- column sums (deterministic two-pass, no atomics) ----------------
__global__ void colsum1_kernel(const float* __restrict__ A, float* __restrict__ part) {
    int j = blockIdx.x * 256 + threadIdx.x;
    int i0 = blockIdx.y * 128;
    float s = 0.f;
    for (int i = 0; i < 128; ++i) s += A[(size_t)(i0 + i) * N_NODES + j];
    part[(size_t)blockIdx.y * N_NODES + j] = s;
}

__global__ void colsum2_kernel(const float* __restrict__ part, float* __restrict__ dis) {
    int j = blockIdx.x * 256 + threadIdx.x;
    float s = 0.f;
    #pragma unroll
    for (int p = 0; p < 32; ++p) s += part[(size_t)p * N_NODES + j];
    dis[j] = (s > 0.f) ? (1.f / sqrtf(s)) : 0.f;
}

__global__ void scale_kernel(float* __restrict__ M1, const float* __restrict__ dis) {
    size_t idx = (size_t)blockIdx.x * 256 + threadIdx.x;
    int i = (int)(idx >> 12), j = (int)(idx & 4095);
    M1[idx] = dis[i] * M1[idx] * dis[j];
}

// ---------------- host ----------------
extern "C" void kernel_launch(void* const* d_in, const int* in_sizes, int n_in,
                              void* d_out, int out_size)
{
    const float* x        = (const float*)d_in[0];
    const float* new_edge = (const float*)d_in[1];
    const float* beta     = (const float*)d_in[2];
    const float* delta    = (const float*)d_in[3];
    const float* eps      = (const float*)d_in[4];
    const float* Wm       = (const float*)d_in[5];
    const float* bm       = (const float*)d_in[6];
    const float* Ws       = (const float*)d_in[7];
    const float* bs       = (const float*)d_in[8];
    const float* mW0      = (const float*)d_in[9];
    const float* mb0      = (const float*)d_in[10];
    const float* mW1      = (const float*)d_in[11];
    const float* mb1      = (const float*)d_in[12];
    const float* sW0      = (const float*)d_in[13];
    const float* sb0      = (const float*)d_in[14];
    const float* sW1      = (const float*)d_in[15];
    const float* sb1      = (const float*)d_in[16];
    float* out = (float*)d_out;

    float *xm, *xs, *m, *cs, *t0, *t1, *t2, *M1, *M2, *sq, *csum, *rn, *dis, *degpart;
    cudaGetSymbolAddress((void**)&xm, g_xm);
    cudaGetSymbolAddress((void**)&xs, g_xs);
    cudaGetSymbolAddress((void**)&m,  g_m);
    cudaGetSymbolAddress((void**)&cs, g_cs);
    cudaGetSymbolAddress((void**)&t0, g_t0);
    cudaGetSymbolAddress((void**)&t1, g_t1);
    cudaGetSymbolAddress((void**)&t2, g_t2);
    cudaGetSymbolAddress((void**)&M1, g_M1);
    cudaGetSymbolAddress((void**)&M2, g_M2);
    cudaGetSymbolAddress((void**)&sq, g_sq);
    cudaGetSymbolAddress((void**)&csum, g_csum);
    cudaGetSymbolAddress((void**)&rn, g_rn);
    cudaGetSymbolAddress((void**)&dis, g_dis);
    cudaGetSymbolAddress((void**)&degpart, g_degpart);

    dim3 blk(256);
    const int EW_BLOCKS = (N_NODES * (size_t)N_NODES) / 256;   // 65536

    // 1) feature projections
    gemm_k<0, true, false><<<dim3(F_DIM / 128, N_NODES / 128), blk>>>(x, Wm, xm, N_NODES, F_DIM, F_DIM, bm);
    gemm_k<0, true, false><<<dim3(F_DIM / 128, N_NODES / 128), blk>>>(x, Ws, xs, N_NODES, F_DIM, F_DIM, bs);

    // 2) row statistics / normalizations
    rowstats_kernel<<<N_NODES, 256>>>(xm, xs, m, cs, sq, csum);

    // 3) pairwise gram matrices
    gemm_k<1, false, false><<<dim3(N_NODES / 128, N_NODES / 128), blk>>>(m, m, M1, N_NODES, N_NODES, F_DIM, nullptr);
    gemm_k<1, false, false><<<dim3(N_NODES / 128, N_NODES / 128), blk>>>(cs, cs, M2, N_NODES, N_NODES, F_DIM, nullptr);

    // 4) ws = exp(-res), row-normalize, adjacency construction
    ws_kernel<<<EW_BLOCKS, 256>>>(M1, M2, sq, csum);
    rownorm_kernel<<<N_NODES, 256>>>(M1, rn);
    adj_kernel<<<EW_BLOCKS, 256>>>(M1, rn, new_edge, eps, beta, delta);

    // 5) GCN degree normalization (deterministic column sums)
    colsum1_kernel<<<dim3(N_NODES / 256, 32), blk>>>(M1, degpart);
    colsum2_kernel<<<N_NODES / 256, blk>>>(degpart, dis);
    scale_kernel<<<EW_BLOCKS, 256>>>(M1, dis);   // M1 is now An

    // 6) mean encoder
    gemm_k<0, false, false><<<dim3(H2_DIM / 128, N_NODES / 128), blk>>>(xm, mW0, t0, N_NODES, H2_DIM, F_DIM, nullptr);
    gemm_k<2, true, true ><<<dim3(H2_DIM / 128, N_NODES / 128), blk>>>(M1, t0, t1, N_NODES, H2_DIM, N_NODES, mb0);
    gemm_k<0, false, false><<<dim3(H_DIM / 128, N_NODES / 128), blk>>>(t1, mW1, t2, N_NODES, H_DIM, H2_DIM, nullptr);
    gemm_k<2, true, true ><<<dim3(H_DIM / 128, N_NODES / 128), blk>>>(M1, t2, out, N_NODES, H_DIM, N_NODES, mb1);

    // 7) std encoder
    gemm_k<0, false, false><<<dim3(H2_DIM / 128, N_NODES / 128), blk>>>(xs, sW0, t0, N_NODES, H2_DIM, F_DIM, nullptr);
    gemm_k<2, true, true ><<<dim3(H2_DIM / 128, N_NODES / 128), blk>>>(M1, t0, t1, N_NODES, H2_DIM, N_NODES, sb0);
    gemm_k<0, false, false><<<dim3(H_DIM / 128, N_NODES / 128), blk>>>(t1, sW1, t2, N_NODES, H_DIM, H2_DIM, nullptr);
    gemm_k<2, true, true ><<<dim3(H_DIM / 128, N_NODES / 128), blk>>>(M1, t2, out + (size_t)N_NODES * H_DIM, N_NODES, H_DIM, N_NODES, sb1);
}

// round 3
// speedup vs baseline: 3.0780x; 3.0780x over previous
#include <cuda_runtime.h>
#include <cuda_bf16.h>
#include <math.h>
#include <stdint.h>

#define N_NODES 4096
#define F_DIM   512
#define H_DIM   256
#define H2_DIM  512

// ---------------- scratch (static device allocations; no runtime alloc) ----------
__device__ __align__(128) float g_xm[N_NODES * F_DIM];
__device__ __align__(128) float g_xs[N_NODES * F_DIM];
__device__ __align__(128) __nv_bfloat16 g_mb [N_NODES * F_DIM];
__device__ __align__(128) __nv_bfloat16 g_csb[N_NODES * F_DIM];
__device__ __align__(128) float g_t0[N_NODES * H2_DIM];
__device__ __align__(128) float g_t1[N_NODES * H2_DIM];
__device__ __align__(128) float g_t2[N_NODES * H_DIM];
__device__ __align__(128) __nv_bfloat16 g_t0T[H2_DIM * N_NODES];
__device__ __align__(128) __nv_bfloat16 g_t2T[H_DIM * N_NODES];
__device__ __align__(128) __nv_bfloat16 g_AnT[(size_t)N_NODES * N_NODES];
__device__ __align__(128) float g_M1[(size_t)N_NODES * N_NODES];
__device__ __align__(128) float g_M2[(size_t)N_NODES * N_NODES];
__device__ __align__(128) float g_sq[N_NODES];
__device__ __align__(128) float g_csum[N_NODES];
__device__ __align__(128) float g_rn[N_NODES];
__device__ __align__(128) float g_dis[N_NODES];
__device__ __align__(128) float g_degpart[32 * N_NODES];

// ================= low-level helpers (sm_80+ features only) =================
__device__ __forceinline__ uint32_t smem_u32(const void* p) {
    uint32_t a;
    asm("{ .reg .u64 t; cvta.to.shared.u64 t, %1; cvt.u32.u64 %0, t; }" : "=r"(a) : "l"(p));
    return a;
}

#define CP_ASYNC_CG(dst, src) \
    asm volatile("cp.async.cg.shared.global [%0], [%1], 16;" :: "r"(dst), "l"(src))
#define CP_COMMIT() asm volatile("cp.async.commit_group;" ::: "memory")
#define CP_WAIT(n)  asm volatile("cp.async.wait_group %0;" :: "n"(n) : "memory")

__device__ __forceinline__ void ldmat_x4(uint32_t& r0, uint32_t& r1, uint32_t& r2, uint32_t& r3,
                                         uint32_t addr) {
    asm volatile("ldmatrix.sync.aligned.m8n8.x4.shared.b16 {%0,%1,%2,%3}, [%4];"
                 : "=r"(r0), "=r"(r1), "=r"(r2), "=r"(r3) : "r"(addr));
}

__device__ __forceinline__ void mma16816(float* c, const uint32_t* a, const uint32_t* b) {
    asm volatile(
        "mma.sync.aligned.m16n8k16.row.col.f32.bf16.bf16.f32 "
        "{%0,%1,%2,%3}, {%4,%5,%6,%7}, {%8,%9}, {%0,%1,%2,%3};"
        : "+f"(c[0]), "+f"(c[1]), "+f"(c[2]), "+f"(c[3])
        : "r"(a[0]), "r"(a[1]), "r"(a[2]), "r"(a[3]), "r"(b[0]), "r"(b[1]));
}

// ================= bf16 HMMA GEMM: C[M,N] = A[M,K] @ B[N,K]^T (+bias, relu) ==========
// A, B bf16 K-major. M,N multiples of 128 (N=256/512/4096 ok), K multiple of 32.
#define BM 128
#define BN 128
#define BK 32
#define LDSH 40   // BK + 8 halves padding

template<bool BIAS, bool RELU>
__global__ __launch_bounds__(256)
void mma_gemm_nt(const __nv_bfloat16* __restrict__ A, const __nv_bfloat16* __restrict__ B,
                 float* __restrict__ C, int M, int N, int K, const float* __restrict__ bias)
{
    __shared__ __nv_bfloat16 As[2][BM * LDSH];
    __shared__ __nv_bfloat16 Bs[2][BN * LDSH];
    const int tid  = threadIdx.x;
    const int wid  = tid >> 5;
    const int lane = tid & 31;
    const int wm = (wid & 1) * 64;     // warp M offset (2 warps in M)
    const int wn = (wid >> 1) * 32;    // warp N offset (4 warps in N)
    const int bm = blockIdx.y * BM;
    const int bn = blockIdx.x * BN;

    const __nv_bfloat16* Ag = A + (size_t)bm * K;
    const __nv_bfloat16* Bg = B + (size_t)bn * K;

    const uint32_t s_a = smem_u32(As);
    const uint32_t s_b = smem_u32(Bs);

    // per-thread global->smem coords: 16B chunks, 4 chunks/row, 64 rows per pass, 2 passes
    const int lr0 = tid >> 2;
    const int lc  = (tid & 3) * 8;

    float acc[4][4][4];
    #pragma unroll
    for (int i = 0; i < 4; ++i)
        #pragma unroll
        for (int j = 0; j < 4; ++j)
            #pragma unroll
            for (int q = 0; q < 4; ++q) acc[i][j][q] = 0.f;

    const int nt = K / BK;

    // ---- stage loader ----
    auto load_stage = [&](int st, int t) {
        const size_t kb = (size_t)t * BK + lc;
        #pragma unroll
        for (int h = 0; h < 2; ++h) {
            const int r = lr0 + h * 64;
            uint32_t da = s_a + (uint32_t)((st * BM * LDSH) + r * LDSH + lc) * 2;
            CP_ASYNC_CG(da, Ag + (size_t)r * K + kb);
            uint32_t db = s_b + (uint32_t)((st * BN * LDSH) + r * LDSH + lc) * 2;
            CP_ASYNC_CG(db, Bg + (size_t)r * K + kb);
        }
    };

    load_stage(0, 0);
    CP_COMMIT();

    for (int t = 0; t < nt; ++t) {
        if (t + 1 < nt) {
            load_stage((t + 1) & 1, t + 1);
            CP_COMMIT();
            CP_WAIT(1);
        } else {
            CP_WAIT(0);
        }
        __syncthreads();

        const int st = t & 1;
        #pragma unroll
        for (int kk = 0; kk < BK; kk += 16) {
            uint32_t a[4][4];
            #pragma unroll
            for (int mf = 0; mf < 4; ++mf) {
                int row = wm + mf * 16 + (lane & 15);
                uint32_t addr = s_a +
                    (uint32_t)((st * BM * LDSH) + row * LDSH + kk + ((lane >> 4) << 3)) * 2;
                ldmat_x4(a[mf][0], a[mf][1], a[mf][2], a[mf][3], addr);
            }
            uint32_t b[4][2];
            #pragma unroll
            for (int nf2 = 0; nf2 < 2; ++nf2) {
                int row = wn + nf2 * 16 + (lane & 7) + (((lane >> 4) & 1) << 3);
                uint32_t addr = s_b +
                    (uint32_t)((st * BN * LDSH) + row * LDSH + kk + (((lane >> 3) & 1) << 3)) * 2;
                uint32_t r0, r1, r2, r3;
                ldmat_x4(r0, r1, r2, r3, addr);
                b[nf2 * 2 + 0][0] = r0; b[nf2 * 2 + 0][1] = r1;
                b[nf2 * 2 + 1][0] = r2; b[nf2 * 2 + 1][1] = r3;
            }
            #pragma unroll
            for (int mf = 0; mf < 4; ++mf)
                #pragma unroll
                for (int nf = 0; nf < 4; ++nf)
                    mma16816(acc[mf][nf], a[mf], b[nf]);
        }
        __syncthreads();
    }

    // ---- epilogue ----
    #pragma unroll
    for (int mf = 0; mf < 4; ++mf) {
        #pragma unroll
        for (int nf = 0; nf < 4; ++nf) {
            int rg = bm + wm + mf * 16 + (lane >> 2);
            int cg = bn + wn + nf * 8 + (lane & 3) * 2;
            float b0 = 0.f, b1 = 0.f;
            if (BIAS) { b0 = bias[cg]; b1 = bias[cg + 1]; }
            float v0 = acc[mf][nf][0] + b0;
            float v1 = acc[mf][nf][1] + b1;
            float v2 = acc[mf][nf][2] + b0;
            float v3 = acc[mf][nf][3] + b1;
            if (RELU) {
                v0 = fmaxf(v0, 0.f); v1 = fmaxf(v1, 0.f);
                v2 = fmaxf(v2, 0.f); v3 = fmaxf(v3, 0.f);
            }
            float2 p0; p0.x = v0; p0.y = v1;
            float2 p1; p1.x = v2; p1.y = v3;
            *(float2*)(C + (size_t)rg * N + cg) = p0;
            *(float2*)(C + (size_t)(rg + 8) * N + cg) = p1;
        }
    }
}

// ================= fp32 SIMT GEMM (feature projections): C = A[M,K] @ B[K,N] (+bias) ======
template<bool BIAS>
__global__ __launch_bounds__(256)
void gemm_nn(const float* __restrict__ A, const float* __restrict__ B,
             float* __restrict__ C, int M, int N, int K, const float* __restrict__ bias)
{
    __shared__ float As[16][132];
    __shared__ float Bs[16][132];
    const int tid = threadIdx.x;
    const int tx = tid & 15;
    const int ty = tid >> 4;
    const int bm = blockIdx.y * 128;
    const int bn = blockIdx.x * 128;

    float acc[8][8];
    #pragma unroll
    for (int i = 0; i < 8; ++i)
        #pragma unroll
        for (int j = 0; j < 8; ++j) acc[i][j] = 0.f;

    for (int k0 = 0; k0 < K; k0 += 16) {
        #pragma unroll
        for (int t = 0; t < 2; ++t) {
            int idx = tid + t * 256;
            int r = idx >> 2, c4 = (idx & 3) << 2;
            float4 v = *(const float4*)(A + (size_t)(bm + r) * K + k0 + c4);
            As[c4 + 0][r] = v.x; As[c4 + 1][r] = v.y;
            As[c4 + 2][r] = v.z; As[c4 + 3][r] = v.w;
        }
        #pragma unroll
        for (int t = 0; t < 2; ++t) {
            int idx = tid + t * 256;
            int c = idx >> 5, n4 = (idx & 31) << 2;
            float4 v = *(const float4*)(B + (size_t)(k0 + c) * N + bn + n4);
            *(float4*)&Bs[c][n4] = v;
        }
        __syncthreads();
        #pragma unroll
        for (int k = 0; k < 16; ++k) {
            float a[8], b[8];
            *(float4*)&a[0] = *(const float4*)&As[k][ty * 8];
            *(float4*)&a[4] = *(const float4*)&As[k][ty * 8 + 4];
            *(float4*)&b[0] = *(const float4*)&Bs[k][tx * 8];
            *(float4*)&b[4] = *(const float4*)&Bs[k][tx * 8 + 4];
            #pragma unroll
            for (int i = 0; i < 8; ++i)
                #pragma unroll
                for (int j = 0; j < 8; ++j)
                    acc[i][j] = fmaf(a[i], b[j], acc[i][j]);
        }
        __syncthreads();
    }

    #pragma unroll
    for (int i = 0; i < 8; ++i) {
        size_t row = (size_t)(bm + ty * 8 + i);
        float* Cp = C + row * (size_t)N + bn + tx * 8;
        #pragma unroll
        for (int jv = 0; jv < 2; ++jv) {
            float vv[4];
            #pragma unroll
            for (int j = 0; j < 4; ++j) {
                float val = acc[i][jv * 4 + j];
                if (BIAS) val += bias[bn + tx * 8 + jv * 4 + j];
                vv[j] = val;
            }
            float4 v; v.x = vv[0]; v.y = vv[1]; v.z = vv[2]; v.w = vv[3];
            *(float4*)(Cp + jv * 4) = v;
        }
    }
}

// ---------------- block reduction ----------------
__device__ __forceinline__ float blockReduceSum(float v, float* sh) {
    __syncthreads();
    int lane = threadIdx.x & 31, wid = threadIdx.x >> 5;
    #pragma unroll
    for (int o = 16; o; o >>= 1) v += __shfl_down_sync(0xffffffffu, v, o);
    if (lane == 0) sh[wid] = v;
    __syncthreads();
    if (wid == 0) {
        float r = (lane < ((blockDim.x + 31) >> 5)) ? sh[lane] : 0.f;
        #pragma unroll
        for (int o = 16; o; o >>= 1) r += __shfl_down_sync(0xffffffffu, r, o);
        if (lane == 0) sh[0] = r;
    }
    __syncthreads();
    return sh[0];
}

// ---------------- per-row stats: m = l2norm(xm) (bf16), cs = sqrt(l2norm(exp(xs))) (bf16) ----
__global__ void rowstats_kernel(const float* __restrict__ xm, const float* __restrict__ xs,
                                __nv_bfloat16* __restrict__ m, __nv_bfloat16* __restrict__ cs,
                                float* __restrict__ sq, float* __restrict__ csum)
{
    __shared__ float sh[32];
    int row = blockIdx.x;
    const float* xmr = xm + (size_t)row * F_DIM;
    const float* xsr = xs + (size_t)row * F_DIM;
    float s1 = 0.f, s2 = 0.f, s3 = 0.f;
    for (int j = threadIdx.x; j < F_DIM; j += blockDim.x) {
        float a = xmr[j]; s1 = fmaf(a, a, s1);
        float e = expf(xsr[j]); s2 = fmaf(e, e, s2); s3 += e;
    }
    s1 = blockReduceSum(s1, sh);
    s2 = blockReduceSum(s2, sh);
    s3 = blockReduceSum(s3, sh);
    float dm = fmaxf(sqrtf(s1), 1e-12f);
    float dc = fmaxf(sqrtf(s2), 1e-12f);
    if (threadIdx.x == 0) {
        sq[row] = s1 / (dm * dm);
        csum[row] = s3 / dc;
    }
    for (int j = threadIdx.x; j < F_DIM; j += blockDim.x) {
        m[(size_t)row * F_DIM + j]  = __float2bfloat16(xmr[j] / dm);
        cs[(size_t)row * F_DIM + j] = __float2bfloat16(sqrtf(expf(xsr[j]) / dc));
    }
}

// ---------------- ws = exp(-(max(sq_i+sq_j-2*G1,0) + csum_i+csum_j-2*G2)) in place ----
__global__ void ws_kernel(float* __restrict__ M1, const float* __restrict__ M2,
                          const float* __restrict__ sq, const float* __restrict__ csum)
{
    size_t idx = (size_t)blockIdx.x * 256 + threadIdx.x;
    int i = (int)(idx >> 12), j = (int)(idx & 4095);
    float d2 = fmaxf(sq[i] + sq[j] - 2.f * M1[idx], 0.f);
    float res = d2 + csum[i] + csum[j] - 2.f * M2[idx];
    M1[idx] = expf(-res);
}

__global__ void rownorm_kernel(const float* __restrict__ M1, float* __restrict__ rn) {
    __shared__ float sh[32];
    int row = blockIdx.x;
    const float* r = M1 + (size_t)row * N_NODES;
    float s = 0.f;
    for (int j = threadIdx.x; j < N_NODES; j += blockDim.x) { float v = r[j]; s = fmaf(v, v, s); }
    s = blockReduceSum(s, sh);
    if (threadIdx.x == 0) rn[row] = fmaxf(sqrtf(s), 1e-12f);
}

// ---------------- adjacency: mix with new_edge, logit trick, sigmoid, threshold, self-loops
__global__ void adj_kernel(float* __restrict__ M1, const float* __restrict__ rn,
                           const float* __restrict__ ne, const float* __restrict__ epsm,
                           const float* __restrict__ beta, const float* __restrict__ delta)
{
    size_t idx = (size_t)blockIdx.x * 256 + threadIdx.x;
    int i = (int)(idx >> 12), j = (int)(idx & 4095);
    float b = beta[0], d = delta[0];
    float w = M1[idx] / rn[i];
    float t = (1.f - b) * w + b * ne[idx];
    t = fminf(fmaxf(t, 1e-6f), 1.f - 1e-6f);
    float e = fminf(fmaxf(epsm[idx], 1e-6f), 1.f - 1e-6f);
    float num = t * e;
    float s = num / (num + (1.f - t) * (1.f - e));
    float a = (s > d) ? s : 0.f;
    if (i == j && !(a > 0.f)) a += 1.f;   // add_remaining_self_loops(fill=1)
    M1[idx] = a;
}

// ---------------- column sums (deterministic two-pass, no atomics) ----------------
__global__ void colsum1_kernel(const float* __restrict__ A, float* __restrict__ part) {
    int j = blockIdx.x * 256 + threadIdx.x;
    int i0 = blockIdx.y * 128;
    float s = 0.f;
    for (int i = 0; i < 128; ++i) s += A[(size_t)(i0 + i) * N_NODES + j];
    part[(size_t)blockIdx.y * N_NODES + j] = s;
}

__global__ void colsum2_kernel(const float* __restrict__ part, float* __restrict__ dis) {
    int j = blockIdx.x * 256 + threadIdx.x;
    float s = 0.f;
    #pragma unroll
    for (int p = 0; p < 32; ++p) s += part[(size_t)p * N_NODES + j];
    dis[j] = (s > 0.f) ? (1.f / sqrtf(s)) : 0.f;
}

// ---------------- fuse: An = dis_i * M1 * dis_j, write TRANSPOSED bf16 (AnT[j][i]) ----
__global__ void scaleT_kernel(const float* __restrict__ M1, const float* __restrict__ dis,
                              __nv_bfloat16* __restrict__ AnT)
{
    __shared__ float t[32][33];
    int r0 = blockIdx.y * 32, c0 = blockIdx.x * 32;
    int tx = threadIdx.x, ty = threadIdx.y;
    float dj = dis[c0 + tx];
    #pragma unroll
    for (int j = 0; j < 4; ++j) {
        int r = r0 + ty + j * 8;
        float v = M1[(size_t)r * N_NODES + c0 + tx];
        t[ty + j * 8][tx] = v * dis[r] * dj;
    }
    __syncthreads();
    #pragma unroll
    for (int j = 0; j < 4; ++j) {
        int c = c0 + ty + j * 8;
        AnT[(size_t)c * N_NODES + r0 + tx] = __float2bfloat16(t[tx][ty + j * 8]);
    }
}

// ---------------- transpose fp32 [R,C] -> bf16 [C,R] ----------------
__global__ void transposeb_kernel(const float* __restrict__ in, __nv_bfloat16* __restrict__ out,
                                  int R, int C)
{
    __shared__ float t[32][33];
    int r0 = blockIdx.y * 32, c0 = blockIdx.x * 32;
    int tx = threadIdx.x, ty = threadIdx.y;
    #pragma unroll
    for (int j = 0; j < 4; ++j) {
        int r = r0 + ty + j * 8;
        t[ty + j * 8][tx] = in[(size_t)r * C + c0 + tx];
    }
    __syncthreads();
    #pragma unroll
    for (int j = 0; j < 4; ++j) {
        int c = c0 + ty + j * 8;
        out[(size_t)c * R + r0 + tx] = __float2bfloat16(t[tx][ty + j * 8]);
    }
}

// ---------------- host ----------------
extern "C" void kernel_launch(void* const* d_in, const int* in_sizes, int n_in,
                              void* d_out, int out_size)
{
    const float* x        = (const float*)d_in[0];
    const float* new_edge = (const float*)d_in[1];
    const float* beta     = (const float*)d_in[2];
    const float* delta    = (const float*)d_in[3];
    const float* eps      = (const float*)d_in[4];
    const float* Wm       = (const float*)d_in[5];
    const float* bm       = (const float*)d_in[6];
    const float* Ws       = (const float*)d_in[7];
    const float* bs       = (const float*)d_in[8];
    const float* mW0      = (const float*)d_in[9];
    const float* mb0      = (const float*)d_in[10];
    const float* mW1      = (const float*)d_in[11];
    const float* mb1      = (const float*)d_in[12];
    const float* sW0      = (const float*)d_in[13];
    const float* sb0      = (const float*)d_in[14];
    const float* sW1      = (const float*)d_in[15];
    const float* sb1      = (const float*)d_in[16];
    float* out = (float*)d_out;

    float *xm, *xs, *t0, *t1, *t2, *M1, *M2, *sq, *csum, *rn, *dis, *degpart;
    __nv_bfloat16 *mb_, *csb, *t0T, *t2T, *AnT;
    cudaGetSymbolAddress((void**)&xm, g_xm);
    cudaGetSymbolAddress((void**)&xs, g_xs);
    cudaGetSymbolAddress((void**)&mb_, g_mb);
    cudaGetSymbolAddress((void**)&csb, g_csb);
    cudaGetSymbolAddress((void**)&t0, g_t0);
    cudaGetSymbolAddress((void**)&t1, g_t1);
    cudaGetSymbolAddress((void**)&t2, g_t2);
    cudaGetSymbolAddress((void**)&t0T, g_t0T);
    cudaGetSymbolAddress((void**)&t2T, g_t2T);
    cudaGetSymbolAddress((void**)&AnT, g_AnT);
    cudaGetSymbolAddress((void**)&M1, g_M1);
    cudaGetSymbolAddress((void**)&M2, g_M2);
    cudaGetSymbolAddress((void**)&sq, g_sq);
    cudaGetSymbolAddress((void**)&csum, g_csum);
    cudaGetSymbolAddress((void**)&rn, g_rn);
    cudaGetSymbolAddress((void**)&dis, g_dis);
    cudaGetSymbolAddress((void**)&degpart, g_degpart);

    dim3 blk(256);
    dim3 tpb(32, 8);
    const int EW_BLOCKS = (N_NODES * (size_t)N_NODES) / 256;   // 65536

    // 1) feature projections (fp32 SIMT — precision-critical, feeds exp())
    gemm_nn<true><<<dim3(F_DIM / 128, N_NODES / 128), blk>>>(x, Wm, xm, N_NODES, F_DIM, F_DIM, bm);
    gemm_nn<true><<<dim3(F_DIM / 128, N_NODES / 128), blk>>>(x, Ws, xs, N_NODES, F_DIM, F_DIM, bs);

    // 2) row statistics / normalized bf16 features
    rowstats_kernel<<<N_NODES, 256>>>(xm, xs, mb_, csb, sq, csum);

    // 3) pairwise gram matrices on tensor cores (bf16 in, fp32 out)
    mma_gemm_nt<false, false><<<dim3(32, 32), blk>>>(mb_, mb_, M1, N_NODES, N_NODES, F_DIM, nullptr);
    mma_gemm_nt<false, false><<<dim3(32, 32), blk>>>(csb, csb, M2, N_NODES, N_NODES, F_DIM, nullptr);

    // 4) ws, row-normalize, adjacency
    ws_kernel<<<EW_BLOCKS, 256>>>(M1, M2, sq, csum);
    rownorm_kernel<<<N_NODES, 256>>>(M1, rn);
    adj_kernel<<<EW_BLOCKS, 256>>>(M1, rn, new_edge, eps, beta, delta);

    // 5) GCN degree norm + transposed bf16 adjacency
    colsum1_kernel<<<dim3(N_NODES / 256, 32), blk>>>(M1, degpart);
    colsum2_kernel<<<N_NODES / 256, blk>>>(degpart, dis);
    scaleT_kernel<<<dim3(128, 128), tpb>>>(M1, dis, AnT);

    // 6) mean encoder: relu(An^T (xm W0) + b0) -> relu(An^T (h W1) + b1)
    gemm_nn<false><<<dim3(H2_DIM / 128, N_NODES / 128), blk>>>(xm, mW0, t0, N_NODES, H2_DIM, F_DIM, nullptr);
    transposeb_kernel<<<dim3(H2_DIM / 32, N_NODES / 32), tpb>>>(t0, t0T, N_NODES, H2_DIM);
    mma_gemm_nt<true, true><<<dim3(H2_DIM / 128, 32), blk>>>(AnT, t0T, t1, N_NODES, H2_DIM, N_NODES, mb0);
    gemm_nn<false><<<dim3(H_DIM / 128, N_NODES / 128), blk>>>(t1, mW1, t2, N_NODES, H_DIM, H2_DIM, nullptr);
    transposeb_kernel<<<dim3(H_DIM / 32, N_NODES / 32), tpb>>>(t2, t2T, N_NODES, H_DIM);
    mma_gemm_nt<true, true><<<dim3(H_DIM / 128, 32), blk>>>(AnT, t2T, out, N_NODES, H_DIM, N_NODES, mb1);

    // 7) std encoder
    gemm_nn<false><<<dim3(H2_DIM / 128, N_NODES / 128), blk>>>(xs, sW0, t0, N_NODES, H2_DIM, F_DIM, nullptr);
    transposeb_kernel<<<dim3(H2_DIM / 32, N_NODES / 32), tpb>>>(t0, t0T, N_NODES, H2_DIM);
    mma_gemm_nt<true, true><<<dim3(H2_DIM / 128, 32), blk>>>(AnT, t0T, t1, N_NODES, H2_DIM, N_NODES, sb0);
    gemm_nn<false><<<dim3(H_DIM / 128, N_NODES / 128), blk>>>(t1, sW1, t2, N_NODES, H_DIM, H2_DIM, nullptr);
    transposeb_kernel<<<dim3(H_DIM / 32, N_NODES / 32), tpb>>>(t2, t2T, N_NODES, H_DIM);
    mma_gemm_nt<true, true><<<dim3(H_DIM / 128, 32), blk>>>(AnT, t2T, out + (size_t)N_NODES * H_DIM, N_NODES, H_DIM, N_NODES, sb1);
}

// round 5
// speedup vs baseline: 3.1547x; 1.0249x over previous
#include <cuda_runtime.h>
#include <cuda_bf16.h>
#include <math.h>
#include <stdint.h>

#define N_NODES 4096
#define F_DIM   512
#define H_DIM   256
#define H2_DIM  512

// ---------------- scratch (static device allocations; no runtime alloc) ----------
__device__ __align__(128) __nv_bfloat16 g_xhi[N_NODES * F_DIM];
__device__ __align__(128) __nv_bfloat16 g_xlo[N_NODES * F_DIM];
__device__ __align__(128) __nv_bfloat16 g_wThi[1310720];
__device__ __align__(128) __nv_bfloat16 g_wTlo[1310720];
__device__ __align__(128) float g_bcat[2560];
__device__ __align__(128) float g_xms[N_NODES * 1024];
__device__ __align__(128) __nv_bfloat16 g_xmshi[N_NODES * 1024];
__device__ __align__(128) __nv_bfloat16 g_xmslo[N_NODES * 1024];
__device__ __align__(128) __nv_bfloat16 g_mb [N_NODES * F_DIM];
__device__ __align__(128) __nv_bfloat16 g_csb[N_NODES * F_DIM];
__device__ __align__(128) float g_M1[(size_t)N_NODES * N_NODES];
__device__ __align__(128) __nv_bfloat16 g_AnT[(size_t)N_NODES * N_NODES];
__device__ __align__(128) float g_t0[N_NODES * 1024];
__device__ __align__(128) __nv_bfloat16 g_t0T[1024 * N_NODES];
__device__ __align__(128) float g_t1[N_NODES * 1024];
__device__ __align__(128) __nv_bfloat16 g_t1hi[N_NODES * 1024];
__device__ __align__(128) __nv_bfloat16 g_t1lo[N_NODES * 1024];
__device__ __align__(128) float g_t2[N_NODES * 512];
__device__ __align__(128) __nv_bfloat16 g_t2T[512 * N_NODES];
__device__ __align__(128) float g_sq[N_NODES];
__device__ __align__(128) float g_csum[N_NODES];
__device__ __align__(128) float g_rn[N_NODES];
__device__ __align__(128) float g_dis[N_NODES];
__device__ __align__(128) float g_degpart[32 * N_NODES];

// ================= low-level helpers (sm_80+ features only) =================
__device__ __forceinline__ uint32_t smem_u32(const void* p) {
    uint32_t a;
    asm("{ .reg .u64 t; cvta.to.shared.u64 t, %1; cvt.u32.u64 %0, t; }" : "=r"(a) : "l"(p));
    return a;
}

#define CP_ASYNC_CG(dst, src) \
    asm volatile("cp.async.cg.shared.global [%0], [%1], 16;" :: "r"(dst), "l"(src))
#define CP_COMMIT() asm volatile("cp.async.commit_group;" ::: "memory")
#define CP_WAIT(n)  asm volatile("cp.async.wait_group %0;" :: "n"(n) : "memory")

__device__ __forceinline__ void ldmat_x4(uint32_t& r0, uint32_t& r1, uint32_t& r2, uint32_t& r3,
                                         uint32_t addr) {
    asm volatile("ldmatrix.sync.aligned.m8n8.x4.shared.b16 {%0,%1,%2,%3}, [%4];"
                 : "=r"(r0), "=r"(r1), "=r"(r2), "=r"(r3) : "r"(addr));
}

__device__ __forceinline__ void mma16816(float* c, const uint32_t* a, const uint32_t* b) {
    asm volatile(
        "mma.sync.aligned.m16n8k16.row.col.f32.bf16.bf16.f32 "
        "{%0,%1,%2,%3}, {%4,%5,%6,%7}, {%8,%9}, {%0,%1,%2,%3};"
        : "+f"(c[0]), "+f"(c[1]), "+f"(c[2]), "+f"(c[3])
        : "r"(a[0]), "r"(a[1]), "r"(a[2]), "r"(b[0]), "r"(b[1]), "r"(a[3]));
}

// NOTE: operand order must be a0..a3 then b0,b1 — fix:
__device__ __forceinline__ void mma16816f(float* c, const uint32_t* a, const uint32_t* b) {
    asm volatile(
        "mma.sync.aligned.m16n8k16.row.col.f32.bf16.bf16.f32 "
        "{%0,%1,%2,%3}, {%4,%5,%6,%7}, {%8,%9}, {%0,%1,%2,%3};"
        : "+f"(c[0]), "+f"(c[1]), "+f"(c[2]), "+f"(c[3])
        : "r"(a[0]), "r"(a[1]), "r"(a[2]), "r"(a[3]), "r"(b[0]), "r"(b[1]));
}

// ================= generalized bf16 HMMA NT GEMM =================
// C[M,N] (+epilogues) = A[M,K] @ B[N,K]^T, bf16 K-major inputs, fp32 out.
// SPLIT==3: A=(Ahi+Alo), B=(Bhi+Blo); computes AhiBhi + AhiBlo + AloBhi (near-fp32).
// EPI: 0=store, 1=+bias, 2=+bias+relu, 3=ws-epilogue (reads C, writes exp(-res)),
//      4=+bias+relu, z-split output (cols<256 -> z_mean, else z_std).
#define BM 128
#define BN 128
#define BK 32
#define LDSH 40   // BK + 8 halves padding

template<int SPLIT, int EPI>
__global__ __launch_bounds__(256)
void mma_nt(const __nv_bfloat16* __restrict__ Ahi, const __nv_bfloat16* __restrict__ Alo,
            const __nv_bfloat16* __restrict__ Bhi, const __nv_bfloat16* __restrict__ Blo,
            float* __restrict__ C, int M, int N, int K, int lda, int ldb, int ldc,
            const float* __restrict__ bias, const float* __restrict__ sq,
            const float* __restrict__ csum)
{
    constexpr int STAGES = (SPLIT == 1) ? 3 : 2;
    constexpr int NARR   = (SPLIT == 1) ? 2 : 4;
    constexpr int TILE   = BM * LDSH;           // halves per tile
    extern __shared__ __nv_bfloat16 smB[];

    const int tid  = threadIdx.x;
    const int wid  = tid >> 5;
    const int lane = tid & 31;
    const int wm = (wid & 1) * 64;
    const int wn = (wid >> 1) * 32;
    const int bm = blockIdx.y * BM;
    const int bn = blockIdx.x * BN;

    const __nv_bfloat16* Ag  = Ahi + (size_t)bm * lda;
    const __nv_bfloat16* Bg  = Bhi + (size_t)bn * ldb;
    const __nv_bfloat16* Agl = (SPLIT == 3) ? Alo + (size_t)bm * lda : nullptr;
    const __nv_bfloat16* Bgl = (SPLIT == 3) ? Blo + (size_t)bn * ldb : nullptr;

    const uint32_t s_base = smem_u32(smB);
    const int lr0 = tid >> 2;
    const int lc  = (tid & 3) * 8;

    float acc[4][4][4];
    #pragma unroll
    for (int i = 0; i < 4; ++i)
        #pragma unroll
        for (int j = 0; j < 4; ++j)
            #pragma unroll
            for (int q = 0; q < 4; ++q) acc[i][j][q] = 0.f;

    const int nt = K / BK;

    auto load_stage = [&](int st, int t) {
        const size_t kb = (size_t)t * BK + lc;
        const uint32_t sb = s_base + (uint32_t)(st * NARR * TILE) * 2;
        #pragma unroll
        for (int h = 0; h < 2; ++h) {
            const int r = lr0 + h * 64;
            const uint32_t so = (uint32_t)(r * LDSH + lc) * 2;
            CP_ASYNC_CG(sb + so, Ag + (size_t)r * lda + kb);
            CP_ASYNC_CG(sb + (uint32_t)TILE * 2 + so, Bg + (size_t)r * ldb + kb);
            if (SPLIT == 3) {
                CP_ASYNC_CG(sb + (uint32_t)TILE * 4 + so, Agl + (size_t)r * lda + kb);
                CP_ASYNC_CG(sb + (uint32_t)TILE * 6 + so, Bgl + (size_t)r * ldb + kb);
            }
        }
    };

    #pragma unroll
    for (int s = 0; s < STAGES - 1; ++s) { load_stage(s, s); CP_COMMIT(); }

    for (int t = 0; t < nt; ++t) {
        CP_WAIT(STAGES - 2);
        __syncthreads();
        if (t + STAGES - 1 < nt) { load_stage((t + STAGES - 1) % STAGES, t + STAGES - 1); CP_COMMIT(); }

        const uint32_t sb = s_base + (uint32_t)((t % STAGES) * NARR * TILE) * 2;
        #pragma unroll
        for (int kk = 0; kk < BK; kk += 16) {
            uint32_t ah[4][4], al[4][4];
            #pragma unroll
            for (int mf = 0; mf < 4; ++mf) {
                int row = wm + mf * 16 + (lane & 15);
                uint32_t off = (uint32_t)(row * LDSH + kk + ((lane >> 4) << 3)) * 2;
                ldmat_x4(ah[mf][0], ah[mf][1], ah[mf][2], ah[mf][3], sb + off);
                if (SPLIT == 3)
                    ldmat_x4(al[mf][0], al[mf][1], al[mf][2], al[mf][3],
                             sb + (uint32_t)TILE * 4 + off);
            }
            uint32_t bh[4][2], bl[4][2];
            #pragma unroll
            for (int nf2 = 0; nf2 < 2; ++nf2) {
                int row = wn + nf2 * 16 + (lane & 7) + (((lane >> 4) & 1) << 3);
                uint32_t off = (uint32_t)(row * LDSH + kk + (((lane >> 3) & 1) << 3)) * 2;
                uint32_t r0, r1, r2, r3;
                ldmat_x4(r0, r1, r2, r3, sb + (uint32_t)TILE * 2 + off);
                bh[nf2 * 2 + 0][0] = r0; bh[nf2 * 2 + 0][1] = r1;
                bh[nf2 * 2 + 1][0] = r2; bh[nf2 * 2 + 1][1] = r3;
                if (SPLIT == 3) {
                    ldmat_x4(r0, r1, r2, r3, sb + (uint32_t)TILE * 6 + off);
                    bl[nf2 * 2 + 0][0] = r0; bl[nf2 * 2 + 0][1] = r1;
                    bl[nf2 * 2 + 1][0] = r2; bl[nf2 * 2 + 1][1] = r3;
                }
            }
            #pragma unroll
            for (int mf = 0; mf < 4; ++mf)
                #pragma unroll
                for (int nf = 0; nf < 4; ++nf) {
                    mma16816f(acc[mf][nf], ah[mf], bh[nf]);
                    if (SPLIT == 3) {
                        mma16816f(acc[mf][nf], ah[mf], bl[nf]);
                        mma16816f(acc[mf][nf], al[mf], bh[nf]);
                    }
                }
        }
        __syncthreads();
    }

    // ---- epilogue ----
    #pragma unroll
    for (int mf = 0; mf < 4; ++mf) {
        #pragma unroll
        for (int nf = 0; nf < 4; ++nf) {
            int rg = bm + wm + mf * 16 + (lane >> 2);
            int cg = bn + wn + nf * 8 + (lane & 3) * 2;
            float v0 = acc[mf][nf][0], v1 = acc[mf][nf][1];
            float v2 = acc[mf][nf][2], v3 = acc[mf][nf][3];
            if (EPI == 1 || EPI == 2 || EPI == 4) {
                float b0 = bias[cg], b1 = bias[cg + 1];
                v0 += b0; v1 += b1; v2 += b0; v3 += b1;
            }
            if (EPI == 2 || EPI == 4) {
                v0 = fmaxf(v0, 0.f); v1 = fmaxf(v1, 0.f);
                v2 = fmaxf(v2, 0.f); v3 = fmaxf(v3, 0.f);
            }
            if (EPI == 3) {
                // ws: d2 = max(sq_i+sq_j-2*G1,0); res = d2+csum_i+csum_j-2*acc; exp(-res)
                float sqc0 = sq[cg], sqc1 = sq[cg + 1];
                float csc0 = csum[cg], csc1 = csum[cg + 1];
                float sqr0 = sq[rg], sqr1 = sq[rg + 8];
                float csr0 = csum[rg], csr1 = csum[rg + 8];
                float2 g1a = *(const float2*)(C + (size_t)rg * ldc + cg);
                float2 g1b = *(const float2*)(C + (size_t)(rg + 8) * ldc + cg);
                float d;
                d = fmaxf(sqr0 + sqc0 - 2.f * g1a.x, 0.f); v0 = expf(-(d + csr0 + csc0 - 2.f * v0));
                d = fmaxf(sqr0 + sqc1 - 2.f * g1a.y, 0.f); v1 = expf(-(d + csr0 + csc1 - 2.f * v1));
                d = fmaxf(sqr1 + sqc0 - 2.f * g1b.x, 0.f); v2 = expf(-(d + csr1 + csc0 - 2.f * v2));
                d = fmaxf(sqr1 + sqc1 - 2.f * g1b.y, 0.f); v3 = expf(-(d + csr1 + csc1 - 2.f * v3));
            }
            float2 p0; p0.x = v0; p0.y = v1;
            float2 p1; p1.x = v2; p1.y = v3;
            if (EPI == 4) {
                size_t part = (size_t)(cg >> 8) * ((size_t)N_NODES * H_DIM);
                int col = cg & 255;
                *(float2*)(C + part + (size_t)rg * H_DIM + col) = p0;
                *(float2*)(C + part + (size_t)(rg + 8) * H_DIM + col) = p1;
            } else {
                *(float2*)(C + (size_t)rg * ldc + cg) = p0;
                *(float2*)(C + (size_t)(rg + 8) * ldc + cg) = p1;
            }
        }
    }
}

// ---------------- prep kernels ----------------
// transpose + split: in fp32 [R,C] -> hi/lo bf16 [C,R]
__global__ void transpose_split_kernel(const float* __restrict__ in,
                                       __nv_bfloat16* __restrict__ ohi,
                                       __nv_bfloat16* __restrict__ olo, int R, int C)
{
    __shared__ float t[32][33];
    int r0 = blockIdx.y * 32, c0 = blockIdx.x * 32;
    int tx = threadIdx.x, ty = threadIdx.y;
    #pragma unroll
    for (int j = 0; j < 4; ++j)
        t[ty + j * 8][tx] = in[(size_t)(r0 + ty + j * 8) * C + c0 + tx];
    __syncthreads();
    #pragma unroll
    for (int j = 0; j < 4; ++j) {
        int c = c0 + ty + j * 8;
        float v = t[tx][ty + j * 8];
        __nv_bfloat16 h = __float2bfloat16(v);
        __nv_bfloat16 l = __float2bfloat16(v - __bfloat162float(h));
        ohi[(size_t)c * R + r0 + tx] = h;
        olo[(size_t)c * R + r0 + tx] = l;
    }
}

// split fp32 -> hi/lo bf16 (same layout)
__global__ void split_kernel(const float* __restrict__ in, __nv_bfloat16* __restrict__ ohi,
                             __nv_bfloat16* __restrict__ olo, int n)
{
    int idx = blockIdx.x * 256 + threadIdx.x;
    if (idx < n) {
        float v = in[idx];
        __nv_bfloat16 h = __float2bfloat16(v);
        ohi[idx] = h;
        olo[idx] = __float2bfloat16(v - __bfloat162float(h));
    }
}

__global__ void concat_bias_kernel(const float* bm, const float* bs, const float* mb0,
                                   const float* sb0, const float* mb1, const float* sb1,
                                   float* __restrict__ bcat)
{
    for (int i = threadIdx.x; i < 2560; i += blockDim.x) {
        float v;
        if (i < 512)        v = bm[i];
        else if (i < 1024)  v = bs[i - 512];
        else if (i < 1536)  v = mb0[i - 1024];
        else if (i < 2048)  v = sb0[i - 1536];
        else if (i < 2304)  v = mb1[i - 2048];
        else                v = sb1[i - 2304];
        bcat[i] = v;
    }
}

// ---------------- block reduction ----------------
__device__ __forceinline__ float blockReduceSum(float v, float* sh) {
    __syncthreads();
    int lane = threadIdx.x & 31, wid = threadIdx.x >> 5;
    #pragma unroll
    for (int o = 16; o; o >>= 1) v += __shfl_down_sync(0xffffffffu, v, o);
    if (lane == 0) sh[wid] = v;
    __syncthreads();
    if (wid == 0) {
        float r = (lane < ((blockDim.x + 31) >> 5)) ? sh[lane] : 0.f;
        #pragma unroll
        for (int o = 16; o; o >>= 1) r += __shfl_down_sync(0xffffffffu, r, o);
        if (lane == 0) sh[0] = r;
    }
    __syncthreads();
    return sh[0];
}

// ---------------- per-row stats from xms=[xm||xs] (stride 1024) ----------------
__global__ void rowstats_kernel(const float* __restrict__ xms,
                                __nv_bfloat16* __restrict__ m, __nv_bfloat16* __restrict__ cs,
                                float* __restrict__ sq, float* __restrict__ csum)
{
    __shared__ float sh[32];
    int row = blockIdx.x;
    const float* xmr = xms + (size_t)row * 1024;
    const float* xsr = xmr + 512;
    float s1 = 0.f, s2 = 0.f, s3 = 0.f;
    for (int j = threadIdx.x; j < F_DIM; j += blockDim.x) {
        float a = xmr[j]; s1 = fmaf(a, a, s1);
        float e = expf(xsr[j]); s2 = fmaf(e, e, s2); s3 += e;
    }
    s1 = blockReduceSum(s1, sh);
    s2 = blockReduceSum(s2, sh);
    s3 = blockReduceSum(s3, sh);
    float dm = fmaxf(sqrtf(s1), 1e-12f);
    float dc = fmaxf(sqrtf(s2), 1e-12f);
    if (threadIdx.x == 0) {
        sq[row] = s1 / (dm * dm);
        csum[row] = s3 / dc;
    }
    for (int j = threadIdx.x; j < F_DIM; j += blockDim.x) {
        m[(size_t)row * F_DIM + j]  = __float2bfloat16(xmr[j] / dm);
        cs[(size_t)row * F_DIM + j] = __float2bfloat16(sqrtf(expf(xsr[j]) / dc));
    }
}

__global__ void rownorm_kernel(const float* __restrict__ M1, float* __restrict__ rn) {
    __shared__ float sh[32];
    int row = blockIdx.x;
    const float* r = M1 + (size_t)row * N_NODES;
    float s = 0.f;
    for (int j = threadIdx.x; j < N_NODES; j += blockDim.x) { float v = r[j]; s = fmaf(v, v, s); }
    s = blockReduceSum(s, sh);
    if (threadIdx.x == 0) rn[row] = fmaxf(sqrtf(s), 1e-12f);
}

// ---------------- adjacency: mix, logit trick, sigmoid, threshold, self-loops ----
__global__ void adj_kernel(float* __restrict__ M1, const float* __restrict__ rn,
                           const float* __restrict__ ne, const float* __restrict__ epsm,
                           const float* __restrict__ beta, const float* __restrict__ delta)
{
    size_t idx = (size_t)blockIdx.x * 256 + threadIdx.x;
    int i = (int)(idx >> 12), j = (int)(idx & 4095);
    float b = beta[0], d = delta[0];
    float w = M1[idx] / rn[i];
    float t = (1.f - b) * w + b * ne[idx];
    t = fminf(fmaxf(t, 1e-6f), 1.f - 1e-6f);
    float e = fminf(fmaxf(epsm[idx], 1e-6f), 1.f - 1e-6f);
    float num = t * e;
    float s = num / (num + (1.f - t) * (1.f - e));
    float a = (s > d) ? s : 0.f;
    if (i == j && !(a > 0.f)) a += 1.f;   // add_remaining_self_loops(fill=1)
    M1[idx] = a;
}

// ---------------- column sums (deterministic two-pass, no atomics) ----------------
__global__ void colsum1_kernel(const float* __restrict__ A, float* __restrict__ part) {
    int j = blockIdx.x * 256 + threadIdx.x;
    int i0 = blockIdx.y * 128;
    float s = 0.f;
    for (int i = 0; i < 128; ++i) s += A[(size_t)(i0 + i) * N_NODES + j];
    part[(size_t)blockIdx.y * N_NODES + j] = s;
}

__global__ void colsum2_kernel(const float* __restrict__ part, float* __restrict__ dis) {
    int j = blockIdx.x * 256 + threadIdx.x;
    float s = 0.f;
    #pragma unroll
    for (int p = 0; p < 32; ++p) s += part[(size_t)p * N_NODES + j];
    dis[j] = (s > 0.f) ? (1.f / sqrtf(s)) : 0.f;
}

// ---------------- fuse: An = dis_i * M1 * dis_j, write TRANSPOSED bf16 (AnT[j][i]) ----
__global__ void scaleT_kernel(const float* __restrict__ M1, const float* __restrict__ dis,
                              __nv_bfloat16* __restrict__ AnT)
{
    __shared__ float t[32][33];
    int r0 = blockIdx.y * 32, c0 = blockIdx.x * 32;
    int tx = threadIdx.x, ty = threadIdx.y;
    float dj = dis[c0 + tx];
    #pragma unroll
    for (int j = 0; j < 4; ++j) {
        int r = r0 + ty + j * 8;
        float v = M1[(size_t)r * N_NODES + c0 + tx];
        t[ty + j * 8][tx] = v * dis[r] * dj;
    }
    __syncthreads();
    #pragma unroll
    for (int j = 0; j < 4; ++j) {
        int c = c0 + ty + j * 8;
        AnT[(size_t)c * N_NODES + r0 + tx] = __float2bfloat16(t[tx][ty + j * 8]);
    }
}

// ---------------- transpose fp32 [R,C] -> bf16 [C,R] ----------------
__global__ void transposeb_kernel(const float* __restrict__ in, __nv_bfloat16* __restrict__ out,
                                  int R, int C)
{
    __shared__ float t[32][33];
    int r0 = blockIdx.y * 32, c0 = blockIdx.x * 32;
    int tx = threadIdx.x, ty = threadIdx.y;
    #pragma unroll
    for (int j = 0; j < 4; ++j)
        t[ty + j * 8][tx] = in[(size_t)(r0 + ty + j * 8) * C + c0 + tx];
    __syncthreads();
    #pragma unroll
    for (int j = 0; j < 4; ++j) {
        int c = c0 + ty + j * 8;
        out[(size_t)c * R + r0 + tx] = __float2bfloat16(t[tx][ty + j * 8]);
    }
}

// ---------------- host ----------------
extern "C" void kernel_launch(void* const* d_in, const int* in_sizes, int n_in,
                              void* d_out, int out_size)
{
    const float* x        = (const float*)d_in[0];
    const float* new_edge = (const float*)d_in[1];
    const float* beta     = (const float*)d_in[2];
    const float* delta    = (const float*)d_in[3];
    const float* eps      = (const float*)d_in[4];
    const float* Wm       = (const float*)d_in[5];
    const float* bm       = (const float*)d_in[6];
    const float* Ws       = (const float*)d_in[7];
    const float* bs       = (const float*)d_in[8];
    const float* mW0      = (const float*)d_in[9];
    const float* mb0      = (const float*)d_in[10];
    const float* mW1      = (const float*)d_in[11];
    const float* mb1      = (const float*)d_in[12];
    const float* sW0      = (const float*)d_in[13];
    const float* sb0      = (const float*)d_in[14];
    const float* sW1      = (const float*)d_in[15];
    const float* sb1      = (const float*)d_in[16];
    float* out = (float*)d_out;

    float *xms, *M1, *t0, *t1, *t2, *sq, *csum, *rn, *dis, *degpart, *bcat;
    __nv_bfloat16 *xhi, *xlo, *wThi, *wTlo, *xmshi, *xmslo, *mb_, *csb, *AnT, *t0T, *t1hi, *t1lo, *t2T;
    cudaGetSymbolAddress((void**)&xhi, g_xhi);
    cudaGetSymbolAddress((void**)&xlo, g_xlo);
    cudaGetSymbolAddress((void**)&wThi, g_wThi);
    cudaGetSymbolAddress((void**)&wTlo, g_wTlo);
    cudaGetSymbolAddress((void**)&bcat, g_bcat);
    cudaGetSymbolAddress((void**)&xms, g_xms);
    cudaGetSymbolAddress((void**)&xmshi, g_xmshi);
    cudaGetSymbolAddress((void**)&xmslo, g_xmslo);
    cudaGetSymbolAddress((void**)&mb_, g_mb);
    cudaGetSymbolAddress((void**)&csb, g_csb);
    cudaGetSymbolAddress((void**)&M1, g_M1);
    cudaGetSymbolAddress((void**)&AnT, g_AnT);
    cudaGetSymbolAddress((void**)&t0, g_t0);
    cudaGetSymbolAddress((void**)&t0T, g_t0T);
    cudaGetSymbolAddress((void**)&t1, g_t1);
    cudaGetSymbolAddress((void**)&t1hi, g_t1hi);
    cudaGetSymbolAddress((void**)&t1lo, g_t1lo);
    cudaGetSymbolAddress((void**)&t2, g_t2);
    cudaGetSymbolAddress((void**)&t2T, g_t2T);
    cudaGetSymbolAddress((void**)&sq, g_sq);
    cudaGetSymbolAddress((void**)&csum, g_csum);
    cudaGetSymbolAddress((void**)&rn, g_rn);
    cudaGetSymbolAddress((void**)&dis, g_dis);
    cudaGetSymbolAddress((void**)&degpart, g_degpart);

    const int SM_PLAIN = 3 * 2 * BM * LDSH * 2;   // 61440
    const int SM_SPLIT = 2 * 4 * BM * LDSH * 2;   // 81920
    cudaFuncSetAttribute(mma_nt<3,1>, cudaFuncAttributeMaxDynamicSharedMemorySize, SM_SPLIT);
    cudaFuncSetAttribute(mma_nt<3,0>, cudaFuncAttributeMaxDynamicSharedMemorySize, SM_SPLIT);
    cudaFuncSetAttribute(mma_nt<1,0>, cudaFuncAttributeMaxDynamicSharedMemorySize, SM_PLAIN);
    cudaFuncSetAttribute(mma_nt<1,2>, cudaFuncAttributeMaxDynamicSharedMemorySize, SM_PLAIN);
    cudaFuncSetAttribute(mma_nt<1,3>, cudaFuncAttributeMaxDynamicSharedMemorySize, SM_PLAIN);
    cudaFuncSetAttribute(mma_nt<1,4>, cudaFuncAttributeMaxDynamicSharedMemorySize, SM_PLAIN);

    dim3 blk(256);
    dim3 tpb(32, 8);
    const int EW_BLOCKS = (N_NODES * (size_t)N_NODES) / 256;   // 65536

    // ---- prep: biases, transposed+split weights, split x ----
    concat_bias_kernel<<<1, 256>>>(bm, bs, mb0, sb0, mb1, sb1, bcat);
    transpose_split_kernel<<<dim3(16, 16), tpb>>>(Wm,  wThi + 0,       wTlo + 0,       512, 512);
    transpose_split_kernel<<<dim3(16, 16), tpb>>>(Ws,  wThi + 262144,  wTlo + 262144,  512, 512);
    transpose_split_kernel<<<dim3(16, 16), tpb>>>(mW0, wThi + 524288,  wTlo + 524288,  512, 512);
    transpose_split_kernel<<<dim3(16, 16), tpb>>>(sW0, wThi + 786432,  wTlo + 786432,  512, 512);
    transpose_split_kernel<<<dim3(8, 16),  tpb>>>(mW1, wThi + 1048576, wTlo + 1048576, 512, 256);
    transpose_split_kernel<<<dim3(8, 16),  tpb>>>(sW1, wThi + 1179648, wTlo + 1179648, 512, 256);
    split_kernel<<<(N_NODES * F_DIM) / 256, blk>>>(x, xhi, xlo, N_NODES * F_DIM);

    // ---- fused projection: xms = x @ [Wm||Ws] + [bm||bs]  (split-bf16, near fp32) ----
    mma_nt<3,1><<<dim3(8, 32), blk, SM_SPLIT>>>(xhi, xlo, wThi, wTlo, xms,
        N_NODES, 1024, 512, 512, 512, 1024, bcat, nullptr, nullptr);

    // ---- row statistics + normalized bf16 features ----
    rowstats_kernel<<<N_NODES, 256>>>(xms, mb_, csb, sq, csum);

    // ---- gram(m) -> M1; gram(cs) with fused ws epilogue -> M1 ----
    mma_nt<1,0><<<dim3(32, 32), blk, SM_PLAIN>>>(mb_, nullptr, mb_, nullptr, M1,
        N_NODES, N_NODES, 512, 512, 512, N_NODES, nullptr, nullptr, nullptr);
    mma_nt<1,3><<<dim3(32, 32), blk, SM_PLAIN>>>(csb, nullptr, csb, nullptr, M1,
        N_NODES, N_NODES, 512, 512, 512, N_NODES, nullptr, sq, csum);

    // ---- row-normalize ws, adjacency construction ----
    rownorm_kernel<<<N_NODES, 256>>>(M1, rn);
    adj_kernel<<<EW_BLOCKS, 256>>>(M1, rn, new_edge, eps, beta, delta);

    // ---- GCN degree norm + transposed bf16 adjacency ----
    colsum1_kernel<<<dim3(N_NODES / 256, 32), blk>>>(M1, degpart);
    colsum2_kernel<<<N_NODES / 256, blk>>>(degpart, dis);
    scaleT_kernel<<<dim3(128, 128), tpb>>>(M1, dis, AnT);

    // ---- encoder layer 1 (mean+std fused along N) ----
    split_kernel<<<(N_NODES * 1024) / 256, blk>>>(xms, xmshi, xmslo, N_NODES * 1024);
    mma_nt<3,0><<<dim3(4, 32), blk, SM_SPLIT>>>(xmshi, xmslo, wThi + 524288, wTlo + 524288,
        t0, N_NODES, 512, 512, 1024, 512, 1024, nullptr, nullptr, nullptr);
    mma_nt<3,0><<<dim3(4, 32), blk, SM_SPLIT>>>(xmshi + 512, xmslo + 512, wThi + 786432, wTlo + 786432,
        t0 + 512, N_NODES, 512, 512, 1024, 512, 1024, nullptr, nullptr, nullptr);
    transposeb_kernel<<<dim3(32, 128), tpb>>>(t0, t0T, N_NODES, 1024);
    mma_nt<1,2><<<dim3(8, 32), blk, SM_PLAIN>>>(AnT, nullptr, t0T, nullptr, t1,
        N_NODES, 1024, N_NODES, N_NODES, N_NODES, 1024, bcat + 1024, nullptr, nullptr);

    // ---- encoder layer 2 (mean+std fused along N) ----
    split_kernel<<<(N_NODES * 1024) / 256, blk>>>(t1, t1hi, t1lo, N_NODES * 1024);
    mma_nt<3,0><<<dim3(2, 32), blk, SM_SPLIT>>>(t1hi, t1lo, wThi + 1048576, wTlo + 1048576,
        t2, N_NODES, 256, 512, 1024, 512, 512, nullptr, nullptr, nullptr);
    mma_nt<3,0><<<dim3(2, 32), blk, SM_SPLIT>>>(t1hi + 512, t1lo + 512, wThi + 1179648, wTlo + 1179648,
        t2 + 256, N_NODES, 256, 512, 1024, 512, 512, nullptr, nullptr, nullptr);
    transposeb_kernel<<<dim3(16, 128), tpb>>>(t2, t2T, N_NODES, 512);
    mma_nt<1,4><<<dim3(4, 32), blk, SM_PLAIN>>>(AnT, nullptr, t2T, nullptr, out,
        N_NODES, 512, N_NODES, N_NODES, N_NODES, H_DIM, bcat + 2048, nullptr, nullptr);
}

// round 7
// speedup vs baseline: 4.0481x; 1.2832x over previous
#include <cuda_runtime.h>
#include <cuda_bf16.h>
#include <math.h>
#include <stdint.h>

#define N_NODES 4096
#define F_DIM   512
#define H_DIM   256

// ---------------- scratch (static device allocations; no runtime alloc) ----------
__device__ __align__(128) __nv_bfloat16 g_xhi[N_NODES * F_DIM];
__device__ __align__(128) __nv_bfloat16 g_xlo[N_NODES * F_DIM];
__device__ __align__(128) __nv_bfloat16 g_wThi[1310720];
__device__ __align__(128) __nv_bfloat16 g_wTlo[1310720];
__device__ __align__(128) float g_bcat[2560];
__device__ __align__(128) float g_xms[N_NODES * 1024];
__device__ __align__(128) __nv_bfloat16 g_xmshi[N_NODES * 1024];
__device__ __align__(128) __nv_bfloat16 g_xmslo[N_NODES * 1024];
__device__ __align__(128) __nv_bfloat16 g_mb [N_NODES * F_DIM];
__device__ __align__(128) __nv_bfloat16 g_csb[N_NODES * F_DIM];
__device__ __align__(128) float g_M1[(size_t)N_NODES * N_NODES];
__device__ __align__(128) __nv_bfloat16 g_AnT[(size_t)N_NODES * N_NODES];
__device__ __align__(128) float g_t0[N_NODES * 1024];
__device__ __align__(128) __nv_bfloat16 g_t0T[1024 * N_NODES];
__device__ __align__(128) float g_t1[N_NODES * 1024];
__device__ __align__(128) __nv_bfloat16 g_t1hi[N_NODES * 1024];
__device__ __align__(128) __nv_bfloat16 g_t1lo[N_NODES * 1024];
__device__ __align__(128) float g_t2[N_NODES * 512];
__device__ __align__(128) __nv_bfloat16 g_t2T[512 * N_NODES];
__device__ __align__(128) float g_sq[N_NODES];
__device__ __align__(128) float g_csum[N_NODES];
__device__ __align__(128) float g_rn[N_NODES];
__device__ __align__(128) float g_dis[N_NODES];
__device__ __align__(128) float g_degpart[32 * N_NODES];

// ================= low-level helpers (sm_80+ features only) =================
__device__ __forceinline__ uint32_t smem_u32(const void* p) {
    uint32_t a;
    asm("{ .reg .u64 t; cvta.to.shared.u64 t, %1; cvt.u32.u64 %0, t; }" : "=r"(a) : "l"(p));
    return a;
}

#define CP_ASYNC_CG(dst, src) \
    asm volatile("cp.async.cg.shared.global [%0], [%1], 16;" :: "r"(dst), "l"(src))
#define CP_COMMIT() asm volatile("cp.async.commit_group;" ::: "memory")
#define CP_WAIT(n)  asm volatile("cp.async.wait_group %0;" :: "n"(n) : "memory")

__device__ __forceinline__ void ldmat_x4(uint32_t& r0, uint32_t& r1, uint32_t& r2, uint32_t& r3,
                                         uint32_t addr) {
    asm volatile("ldmatrix.sync.aligned.m8n8.x4.shared.b16 {%0,%1,%2,%3}, [%4];"
                 : "=r"(r0), "=r"(r1), "=r"(r2), "=r"(r3) : "r"(addr));
}

__device__ __forceinline__ void mma16816f(float* c, const uint32_t* a, const uint32_t* b) {
    asm volatile(
        "mma.sync.aligned.m16n8k16.row.col.f32.bf16.bf16.f32 "
        "{%0,%1,%2,%3}, {%4,%5,%6,%7}, {%8,%9}, {%0,%1,%2,%3};"
        : "+f"(c[0]), "+f"(c[1]), "+f"(c[2]), "+f"(c[3])
        : "r"(a[0]), "r"(a[1]), "r"(a[2]), "r"(a[3]), "r"(b[0]), "r"(b[1]));
}

// ================= generalized bf16 HMMA NT GEMM =================
// C[M,N] = A[M,K] @ B[N,K]^T (+epilogues). bf16 K-major inputs, fp32 out.
// SPLIT==3: near-fp32 via AhiBhi + AhiBlo + AloBhi (narrow tile only).
// BNT: 128 (warp 64x32) or 256 (warp 64x64, SPLIT==1 only).
// EPI: 0=store, 1=+bias, 2=+bias+relu, 3=ws-epilogue (reads C, writes exp(-res)).
// zA/zB/zC: flat element offsets applied per blockIdx.z.
#define BM 128
#define BK 32
#define LDSH 40   // BK + 8 halves padding

template<int SPLIT, int EPI, int BNT>
__global__ __launch_bounds__(256)
void mma_nt(const __nv_bfloat16* __restrict__ Ahi, const __nv_bfloat16* __restrict__ Alo,
            const __nv_bfloat16* __restrict__ Bhi, const __nv_bfloat16* __restrict__ Blo,
            float* __restrict__ C, int M, int N, int K, int lda, int ldb, int ldc,
            const float* __restrict__ bias, const float* __restrict__ sq,
            const float* __restrict__ csum, long zA, long zB, long zC)
{
    constexpr int STAGES = (SPLIT == 1) ? 3 : 2;
    constexpr int WN     = BNT / 4;      // warp n-tile
    constexpr int NFR    = WN / 8;       // b fragments per warp
    constexpr int TILEA  = BM * LDSH;
    constexpr int TILEB  = BNT * LDSH;
    constexpr int STAGE  = ((SPLIT == 3) ? 2 : 1) * (TILEA + TILEB);  // halves
    extern __shared__ __nv_bfloat16 smB[];

    const int tid  = threadIdx.x;
    const int wid  = tid >> 5;
    const int lane = tid & 31;
    const int wm = (wid & 1) * 64;
    const int wn = (wid >> 1) * WN;
    const int bm = blockIdx.y * BM;
    const int bn = blockIdx.x * BNT;

    const __nv_bfloat16* Ag  = Ahi + (size_t)blockIdx.z * zA + (size_t)bm * lda;
    const __nv_bfloat16* Bg  = Bhi + (size_t)blockIdx.z * zB + (size_t)bn * ldb;
    const __nv_bfloat16* Agl = (SPLIT == 3) ? Alo + (size_t)blockIdx.z * zA + (size_t)bm * lda : nullptr;
    const __nv_bfloat16* Bgl = (SPLIT == 3) ? Blo + (size_t)blockIdx.z * zB + (size_t)bn * ldb : nullptr;
    float* Cz = C + (size_t)blockIdx.z * zC;

    const uint32_t s_base = smem_u32(smB);
    const int lr0 = tid >> 2;
    const int lc  = (tid & 3) * 8;

    float acc[4][NFR][4];
    #pragma unroll
    for (int i = 0; i < 4; ++i)
        #pragma unroll
        for (int j = 0; j < NFR; ++j)
            #pragma unroll
            for (int q = 0; q < 4; ++q) acc[i][j][q] = 0.f;

    const int nt = K / BK;

    auto load_stage = [&](int st, int t) {
        const size_t kb = (size_t)t * BK + lc;
        const uint32_t sb = s_base + (uint32_t)(st * STAGE) * 2;
        #pragma unroll
        for (int h = 0; h < 2; ++h) {
            const int r = lr0 + h * 64;
            const uint32_t so = (uint32_t)(r * LDSH + lc) * 2;
            CP_ASYNC_CG(sb + so, Ag + (size_t)r * lda + kb);
            if (SPLIT == 3)
                CP_ASYNC_CG(sb + (uint32_t)(TILEA + TILEB) * 2 + so, Agl + (size_t)r * lda + kb);
        }
        #pragma unroll
        for (int h = 0; h < BNT / 64; ++h) {
            const int r = lr0 + h * 64;
            const uint32_t so = (uint32_t)(TILEA + r * LDSH + lc) * 2;
            CP_ASYNC_CG(sb + so, Bg + (size_t)r * ldb + kb);
            if (SPLIT == 3)
                CP_ASYNC_CG(sb + (uint32_t)(TILEA + TILEB) * 2 + so, Bgl + (size_t)r * ldb + kb);
        }
    };

    #pragma unroll
    for (int s = 0; s < STAGES - 1; ++s) { load_stage(s, s); CP_COMMIT(); }

    for (int t = 0; t < nt; ++t) {
        CP_WAIT(STAGES - 2);
        __syncthreads();
        if (t + STAGES - 1 < nt) { load_stage((t + STAGES - 1) % STAGES, t + STAGES - 1); CP_COMMIT(); }

        const uint32_t sb = s_base + (uint32_t)((t % STAGES) * STAGE) * 2;
        #pragma unroll
        for (int kk = 0; kk < BK; kk += 16) {
            uint32_t ah[4][4], al[4][4];
            #pragma unroll
            for (int mf = 0; mf < 4; ++mf) {
                int row = wm + mf * 16 + (lane & 15);
                uint32_t off = (uint32_t)(row * LDSH + kk + ((lane >> 4) << 3)) * 2;
                ldmat_x4(ah[mf][0], ah[mf][1], ah[mf][2], ah[mf][3], sb + off);
                if (SPLIT == 3)
                    ldmat_x4(al[mf][0], al[mf][1], al[mf][2], al[mf][3],
                             sb + (uint32_t)(TILEA + TILEB) * 2 + off);
            }
            uint32_t bh[NFR][2], bl[NFR][2];
            #pragma unroll
            for (int nf2 = 0; nf2 < NFR / 2; ++nf2) {
                int row = wn + nf2 * 16 + (lane & 7) + (((lane >> 4) & 1) << 3);
                uint32_t off = (uint32_t)(TILEA + row * LDSH + kk + (((lane >> 3) & 1) << 3)) * 2;
                uint32_t r0, r1, r2, r3;
                ldmat_x4(r0, r1, r2, r3, sb + off);
                bh[nf2 * 2 + 0][0] = r0; bh[nf2 * 2 + 0][1] = r1;
                bh[nf2 * 2 + 1][0] = r2; bh[nf2 * 2 + 1][1] = r3;
                if (SPLIT == 3) {
                    ldmat_x4(r0, r1, r2, r3, sb + (uint32_t)(TILEA + TILEB) * 2 + off);
                    bl[nf2 * 2 + 0][0] = r0; bl[nf2 * 2 + 0][1] = r1;
                    bl[nf2 * 2 + 1][0] = r2; bl[nf2 * 2 + 1][1] = r3;
                }
            }
            #pragma unroll
            for (int mf = 0; mf < 4; ++mf)
                #pragma unroll
                for (int nf = 0; nf < NFR; ++nf) {
                    mma16816f(acc[mf][nf], ah[mf], bh[nf]);
                    if (SPLIT == 3) {
                        mma16816f(acc[mf][nf], ah[mf], bl[nf]);
                        mma16816f(acc[mf][nf], al[mf], bh[nf]);
                    }
                }
        }
        __syncthreads();
    }

    // ---- epilogue ----
    #pragma unroll
    for (int mf = 0; mf < 4; ++mf) {
        #pragma unroll
        for (int nf = 0; nf < NFR; ++nf) {
            int rg = bm + wm + mf * 16 + (lane >> 2);
            int cg = bn + wn + nf * 8 + (lane & 3) * 2;
            float v0 = acc[mf][nf][0], v1 = acc[mf][nf][1];
            float v2 = acc[mf][nf][2], v3 = acc[mf][nf][3];
            if (EPI == 1 || EPI == 2) {
                float b0 = bias[cg], b1 = bias[cg + 1];
                v0 += b0; v1 += b1; v2 += b0; v3 += b1;
            }
            if (EPI == 2) {
                v0 = fmaxf(v0, 0.f); v1 = fmaxf(v1, 0.f);
                v2 = fmaxf(v2, 0.f); v3 = fmaxf(v3, 0.f);
            }
            if (EPI == 3) {
                float sqc0 = sq[cg], sqc1 = sq[cg + 1];
                float csc0 = csum[cg], csc1 = csum[cg + 1];
                float sqr0 = sq[rg], sqr1 = sq[rg + 8];
                float csr0 = csum[rg], csr1 = csum[rg + 8];
                float2 g1a = *(const float2*)(Cz + (size_t)rg * ldc + cg);
                float2 g1b = *(const float2*)(Cz + (size_t)(rg + 8) * ldc + cg);
                float d;
                d = fmaxf(sqr0 + sqc0 - 2.f * g1a.x, 0.f); v0 = expf(-(d + csr0 + csc0 - 2.f * v0));
                d = fmaxf(sqr0 + sqc1 - 2.f * g1a.y, 0.f); v1 = expf(-(d + csr0 + csc1 - 2.f * v1));
                d = fmaxf(sqr1 + sqc0 - 2.f * g1b.x, 0.f); v2 = expf(-(d + csr1 + csc0 - 2.f * v2));
                d = fmaxf(sqr1 + sqc1 - 2.f * g1b.y, 0.f); v3 = expf(-(d + csr1 + csc1 - 2.f * v3));
            }
            float2 p0; p0.x = v0; p0.y = v1;
            float2 p1; p1.x = v2; p1.y = v3;
            *(float2*)(Cz + (size_t)rg * ldc + cg) = p0;
            *(float2*)(Cz + (size_t)(rg + 8) * ldc + cg) = p1;
        }
    }
}

// ---------------- prep kernels ----------------
__global__ void transpose_split_kernel(const float* __restrict__ in,
                                       __nv_bfloat16* __restrict__ ohi,
                                       __nv_bfloat16* __restrict__ olo, int R, int C)
{
    __shared__ float t[32][33];
    int r0 = blockIdx.y * 32, c0 = blockIdx.x * 32;
    int tx = threadIdx.x, ty = threadIdx.y;
    #pragma unroll
    for (int j = 0; j < 4; ++j)
        t[ty + j * 8][tx] = in[(size_t)(r0 + ty + j * 8) * C + c0 + tx];
    __syncthreads();
    #pragma unroll
    for (int j = 0; j < 4; ++j) {
        int c = c0 + ty + j * 8;
        float v = t[tx][ty + j * 8];
        __nv_bfloat16 h = __float2bfloat16(v);
        __nv_bfloat16 l = __float2bfloat16(v - __bfloat162float(h));
        ohi[(size_t)c * R + r0 + tx] = h;
        olo[(size_t)c * R + r0 + tx] = l;
    }
}

__global__ void split_kernel(const float* __restrict__ in, __nv_bfloat16* __restrict__ ohi,
                             __nv_bfloat16* __restrict__ olo, int n)
{
    int idx = blockIdx.x * 256 + threadIdx.x;
    if (idx < n) {
        float v = in[idx];
        __nv_bfloat16 h = __float2bfloat16(v);
        ohi[idx] = h;
        olo[idx] = __float2bfloat16(v - __bfloat162float(h));
    }
}

__global__ void concat_bias_kernel(const float* bm, const float* bs, const float* mb0,
                                   const float* sb0, const float* mb1, const float* sb1,
                                   float* __restrict__ bcat)
{
    for (int i = threadIdx.x; i < 2560; i += blockDim.x) {
        float v;
        if (i < 512)        v = bm[i];
        else if (i < 1024)  v = bs[i - 512];
        else if (i < 1536)  v = mb0[i - 1024];
        else if (i < 2048)  v = sb0[i - 1536];
        else if (i < 2304)  v = mb1[i - 2048];
        else                v = sb1[i - 2304];
        bcat[i] = v;
    }
}

// ---------------- block reduction ----------------
__device__ __forceinline__ float blockReduceSum(float v, float* sh) {
    __syncthreads();
    int lane = threadIdx.x & 31, wid = threadIdx.x >> 5;
    #pragma unroll
    for (int o = 16; o; o >>= 1) v += __shfl_down_sync(0xffffffffu, v, o);
    if (lane == 0) sh[wid] = v;
    __syncthreads();
    if (wid == 0) {
        float r = (lane < ((blockDim.x + 31) >> 5)) ? sh[lane] : 0.f;
        #pragma unroll
        for (int o = 16; o; o >>= 1) r += __shfl_down_sync(0xffffffffu, r, o);
        if (lane == 0) sh[0] = r;
    }
    __syncthreads();
    return sh[0];
}

// ---------------- per-row stats from xms=[xm||xs] (stride 1024) ----------------
__global__ void rowstats_kernel(const float* __restrict__ xms,
                                __nv_bfloat16* __restrict__ m, __nv_bfloat16* __restrict__ cs,
                                float* __restrict__ sq, float* __restrict__ csum)
{
    __shared__ float sh[32];
    int row = blockIdx.x;
    const float* xmr = xms + (size_t)row * 1024;
    const float* xsr = xmr + 512;
    float s1 = 0.f, s2 = 0.f, s3 = 0.f;
    for (int j = threadIdx.x; j < F_DIM; j += blockDim.x) {
        float a = xmr[j]; s1 = fmaf(a, a, s1);
        float e = expf(xsr[j]); s2 = fmaf(e, e, s2); s3 += e;
    }
    s1 = blockReduceSum(s1, sh);
    s2 = blockReduceSum(s2, sh);
    s3 = blockReduceSum(s3, sh);
    float dm = fmaxf(sqrtf(s1), 1e-12f);
    float dc = fmaxf(sqrtf(s2), 1e-12f);
    if (threadIdx.x == 0) {
        sq[row] = s1 / (dm * dm);
        csum[row] = s3 / dc;
    }
    for (int j = threadIdx.x; j < F_DIM; j += blockDim.x) {
        m[(size_t)row * F_DIM + j]  = __float2bfloat16(xmr[j] / dm);
        cs[(size_t)row * F_DIM + j] = __float2bfloat16(sqrtf(expf(xsr[j]) / dc));
    }
}

__global__ void rownorm_kernel(const float* __restrict__ M1, float* __restrict__ rn) {
    __shared__ float sh[32];
    int row = blockIdx.x;
    const float4* r = (const float4*)(M1 + (size_t)row * N_NODES);
    float s = 0.f;
    for (int j = threadIdx.x; j < N_NODES / 4; j += blockDim.x) {
        float4 v = r[j];
        s = fmaf(v.x, v.x, s); s = fmaf(v.y, v.y, s);
        s = fmaf(v.z, v.z, s); s = fmaf(v.w, v.w, s);
    }
    s = blockReduceSum(s, sh);
    if (threadIdx.x == 0) rn[row] = fmaxf(sqrtf(s), 1e-12f);
}

// ---------------- fused adjacency + column-sum partials ----------------
__global__ void adjcol_kernel(float* __restrict__ M1, const float* __restrict__ rn,
                              const float* __restrict__ ne, const float* __restrict__ epsm,
                              const float* __restrict__ beta, const float* __restrict__ delta,
                              float* __restrict__ part)
{
    const int j = blockIdx.x * 256 + threadIdx.x;
    const int i0 = blockIdx.y * 128;
    const float b = beta[0], d = delta[0];
    float s = 0.f;
    for (int i = 0; i < 128; ++i) {
        const int row = i0 + i;
        const size_t idx = (size_t)row * N_NODES + j;
        float w = M1[idx] / rn[row];
        float t = (1.f - b) * w + b * ne[idx];
        t = fminf(fmaxf(t, 1e-6f), 1.f - 1e-6f);
        float e = fminf(fmaxf(epsm[idx], 1e-6f), 1.f - 1e-6f);
        float num = t * e;
        float sg = num / (num + (1.f - t) * (1.f - e));
        float a = (sg > d) ? sg : 0.f;
        if (row == j && !(a > 0.f)) a += 1.f;
        M1[idx] = a;
        s += a;
    }
    part[(size_t)blockIdx.y * N_NODES + j] = s;
}

__global__ void colsum2_kernel(const float* __restrict__ part, float* __restrict__ dis) {
    int j = blockIdx.x * 256 + threadIdx.x;
    float s = 0.f;
    #pragma unroll
    for (int p = 0; p < 32; ++p) s += part[(size_t)p * N_NODES + j];
    dis[j] = (s > 0.f) ? (1.f / sqrtf(s)) : 0.f;
}

// ---------------- fuse: An = dis_i * M1 * dis_j, write TRANSPOSED bf16 ----------------
__global__ void scaleT_kernel(const float* __restrict__ M1, const float* __restrict__ dis,
                              __nv_bfloat16* __restrict__ AnT)
{
    __shared__ float t[32][33];
    int r0 = blockIdx.y * 32, c0 = blockIdx.x * 32;
    int tx = threadIdx.x, ty = threadIdx.y;
    float dj = dis[c0 + tx];
    #pragma unroll
    for (int j = 0; j < 4; ++j) {
        int r = r0 + ty + j * 8;
        float v = M1[(size_t)r * N_NODES + c0 + tx];
        t[ty + j * 8][tx] = v * dis[r] * dj;
    }
    __syncthreads();
    #pragma unroll
    for (int j = 0; j < 4; ++j) {
        int c = c0 + ty + j * 8;
        AnT[(size_t)c * N_NODES + r0 + tx] = __float2bfloat16(t[tx][ty + j * 8]);
    }
}

// ---------------- transpose fp32 [R,C] -> bf16 [C,R] ----------------
__global__ void transposeb_kernel(const float* __restrict__ in, __nv_bfloat16* __restrict__ out,
                                  int R, int C)
{
    __shared__ float t[32][33];
    int r0 = blockIdx.y * 32, c0 = blockIdx.x * 32;
    int tx = threadIdx.x, ty = threadIdx.y;
    #pragma unroll
    for (int j = 0; j < 4; ++j)
        t[ty + j * 8][tx] = in[(size_t)(r0 + ty + j * 8) * C + c0 + tx];
    __syncthreads();
    #pragma unroll
    for (int j = 0; j < 4; ++j) {
        int c = c0 + ty + j * 8;
        out[(size_t)c * R + r0 + tx] = __float2bfloat16(t[tx][ty + j * 8]);
    }
}

// ---------------- split-K reduce + bias + relu + z-split output ----------------
__global__ void reduce_out_kernel(const float* __restrict__ part, const float* __restrict__ bias,
                                  float* __restrict__ out)
{
    int idx = blockIdx.x * 256 + threadIdx.x;   // over 4096*512
    int row = idx >> 9, col = idx & 511;
    float v = part[idx] + part[idx + N_NODES * 512] + bias[col];
    v = fmaxf(v, 0.f);
    out[(size_t)(col >> 8) * (N_NODES * H_DIM) + (size_t)row * H_DIM + (col & 255)] = v;
}

// ---------------- host ----------------
extern "C" void kernel_launch(void* const* d_in, const int* in_sizes, int n_in,
                              void* d_out, int out_size)
{
    const float* x        = (const float*)d_in[0];
    const float* new_edge = (const float*)d_in[1];
    const float* beta     = (const float*)d_in[2];
    const float* delta    = (const float*)d_in[3];
    const float* eps      = (const float*)d_in[4];
    const float* Wm       = (const float*)d_in[5];
    const float* bm       = (const float*)d_in[6];
    const float* Ws       = (const float*)d_in[7];
    const float* bs       = (const float*)d_in[8];
    const float* mW0      = (const float*)d_in[9];
    const float* mW1      = (const float*)d_in[11];
    const float* sW0      = (const float*)d_in[13];
    const float* sW1      = (const float*)d_in[15];
    const float* mb0      = (const float*)d_in[10];
    const float* mb1      = (const float*)d_in[12];
    const float* sb0      = (const float*)d_in[14];
    const float* sb1      = (const float*)d_in[16];
    float* out = (float*)d_out;

    float *xms, *M1, *t0, *t1, *t2, *sq, *csum, *rn, *dis, *degpart, *bcat;
    __nv_bfloat16 *xhi, *xlo, *wThi, *wTlo, *xmshi, *xmslo, *mb_, *csb, *AnT, *t0T, *t1hi, *t1lo, *t2T;
    cudaGetSymbolAddress((void**)&xhi, g_xhi);
    cudaGetSymbolAddress((void**)&xlo, g_xlo);
    cudaGetSymbolAddress((void**)&wThi, g_wThi);
    cudaGetSymbolAddress((void**)&wTlo, g_wTlo);
    cudaGetSymbolAddress((void**)&bcat, g_bcat);
    cudaGetSymbolAddress((void**)&xms, g_xms);
    cudaGetSymbolAddress((void**)&xmshi, g_xmshi);
    cudaGetSymbolAddress((void**)&xmslo, g_xmslo);
    cudaGetSymbolAddress((void**)&mb_, g_mb);
    cudaGetSymbolAddress((void**)&csb, g_csb);
    cudaGetSymbolAddress((void**)&M1, g_M1);
    cudaGetSymbolAddress((void**)&AnT, g_AnT);
    cudaGetSymbolAddress((void**)&t0, g_t0);
    cudaGetSymbolAddress((void**)&t0T, g_t0T);
    cudaGetSymbolAddress((void**)&t1, g_t1);
    cudaGetSymbolAddress((void**)&t1hi, g_t1hi);
    cudaGetSymbolAddress((void**)&t1lo, g_t1lo);
    cudaGetSymbolAddress((void**)&t2, g_t2);
    cudaGetSymbolAddress((void**)&t2T, g_t2T);
    cudaGetSymbolAddress((void**)&sq, g_sq);
    cudaGetSymbolAddress((void**)&csum, g_csum);
    cudaGetSymbolAddress((void**)&rn, g_rn);
    cudaGetSymbolAddress((void**)&dis, g_dis);
    cudaGetSymbolAddress((void**)&degpart, g_degpart);

    const int SM_N_SPLIT = 2 * 2 * (128 + 128) * LDSH * 2;   // 81920
    const int SM_W_PLAIN = 3 * (128 + 256) * LDSH * 2;       // 92160
    cudaFuncSetAttribute(mma_nt<3,1,128>, cudaFuncAttributeMaxDynamicSharedMemorySize, SM_N_SPLIT);
    cudaFuncSetAttribute(mma_nt<3,0,128>, cudaFuncAttributeMaxDynamicSharedMemorySize, SM_N_SPLIT);
    cudaFuncSetAttribute(mma_nt<1,0,256>, cudaFuncAttributeMaxDynamicSharedMemorySize, SM_W_PLAIN);
    cudaFuncSetAttribute(mma_nt<1,2,256>, cudaFuncAttributeMaxDynamicSharedMemorySize, SM_W_PLAIN);
    cudaFuncSetAttribute(mma_nt<1,3,256>, cudaFuncAttributeMaxDynamicSharedMemorySize, SM_W_PLAIN);

    dim3 blk(256);
    dim3 tpb(32, 8);

    // ---- prep ----
    concat_bias_kernel<<<1, 256>>>(bm, bs, mb0, sb0, mb1, sb1, bcat);
    transpose_split_kernel<<<dim3(16, 16), tpb>>>(Wm,  wThi + 0,       wTlo + 0,       512, 512);
    transpose_split_kernel<<<dim3(16, 16), tpb>>>(Ws,  wThi + 262144,  wTlo + 262144,  512, 512);
    transpose_split_kernel<<<dim3(16, 16), tpb>>>(mW0, wThi + 524288,  wTlo + 524288,  512, 512);
    transpose_split_kernel<<<dim3(16, 16), tpb>>>(sW0, wThi + 786432,  wTlo + 786432,  512, 512);
    transpose_split_kernel<<<dim3(8, 16),  tpb>>>(mW1, wThi + 1048576, wTlo + 1048576, 512, 256);
    transpose_split_kernel<<<dim3(8, 16),  tpb>>>(sW1, wThi + 1179648, wTlo + 1179648, 512, 256);
    split_kernel<<<(N_NODES * F_DIM) / 256, blk>>>(x, xhi, xlo, N_NODES * F_DIM);

    // ---- projection: xms = x @ [Wm||Ws] + [bm||bs] (split-bf16) ----
    mma_nt<3,1,128><<<dim3(8, 32), blk, SM_N_SPLIT>>>(xhi, xlo, wThi, wTlo, xms,
        N_NODES, 1024, 512, 512, 512, 1024, bcat, nullptr, nullptr, 0, 0, 0);

    // ---- row statistics + normalized bf16 features ----
    rowstats_kernel<<<N_NODES, 256>>>(xms, mb_, csb, sq, csum);

    // ---- gram(m) -> M1; gram(cs) with fused ws epilogue -> M1 (wide tiles) ----
    mma_nt<1,0,256><<<dim3(16, 32), blk, SM_W_PLAIN>>>(mb_, nullptr, mb_, nullptr, M1,
        N_NODES, N_NODES, 512, 512, 512, N_NODES, nullptr, nullptr, nullptr, 0, 0, 0);
    mma_nt<1,3,256><<<dim3(16, 32), blk, SM_W_PLAIN>>>(csb, nullptr, csb, nullptr, M1,
        N_NODES, N_NODES, 512, 512, 512, N_NODES, nullptr, sq, csum, 0, 0, 0);

    // ---- row-normalize ws, adjacency + column partials (fused) ----
    rownorm_kernel<<<N_NODES, 256>>>(M1, rn);
    adjcol_kernel<<<dim3(16, 32), blk>>>(M1, rn, new_edge, eps, beta, delta, degpart);
    colsum2_kernel<<<N_NODES / 256, blk>>>(degpart, dis);
    scaleT_kernel<<<dim3(128, 128), tpb>>>(M1, dis, AnT);

    // ---- encoder layer 1 ----
    split_kernel<<<(N_NODES * 1024) / 256, blk>>>(xms, xmshi, xmslo, N_NODES * 1024);
    mma_nt<3,0,128><<<dim3(4, 32, 2), blk, SM_N_SPLIT>>>(xmshi, xmslo, wThi + 524288, wTlo + 524288,
        t0, N_NODES, 512, 512, 1024, 512, 1024, nullptr, nullptr, nullptr, 512, 262144, 512);
    transposeb_kernel<<<dim3(32, 128), tpb>>>(t0, t0T, N_NODES, 1024);
    mma_nt<1,2,256><<<dim3(4, 32), blk, SM_W_PLAIN>>>(AnT, nullptr, t0T, nullptr, t1,
        N_NODES, 1024, N_NODES, N_NODES, N_NODES, 1024, bcat + 1024, nullptr, nullptr, 0, 0, 0);

    // ---- encoder layer 2 ----
    split_kernel<<<(N_NODES * 1024) / 256, blk>>>(t1, t1hi, t1lo, N_NODES * 1024);
    mma_nt<3,0,128><<<dim3(2, 32, 2), blk, SM_N_SPLIT>>>(t1hi, t1lo, wThi + 1048576, wTlo + 1048576,
        t2, N_NODES, 256, 512, 1024, 512, 512, nullptr, nullptr, nullptr, 512, 131072, 256);
    transposeb_kernel<<<dim3(16, 128), tpb>>>(t2, t2T, N_NODES, 512);
    // split-K x2 adjacency aggregation -> partials in t0 (scratch reuse)
    mma_nt<1,0,256><<<dim3(2, 32, 2), blk, SM_W_PLAIN>>>(AnT, nullptr, t2T, nullptr, t0,
        N_NODES, 512, 2048, N_NODES, N_NODES, 512, nullptr, nullptr, nullptr,
        2048, 2048, (long)N_NODES * 512);
    reduce_out_kernel<<<(N_NODES * 512) / 256, blk>>>(t0, bcat + 2048, out);
}

// round 8
// speedup vs baseline: 5.4707x; 1.3514x over previous
#include <cuda_runtime.h>
#include <cuda_bf16.h>
#include <math.h>
#include <stdint.h>

#define N_NODES 4096
#define F_DIM   512
#define H_DIM   256

// ---------------- scratch (static device allocations; no runtime alloc) ----------
__device__ __align__(128) __nv_bfloat16 g_xhi[N_NODES * F_DIM];
__device__ __align__(128) __nv_bfloat16 g_xlo[N_NODES * F_DIM];
__device__ __align__(128) __nv_bfloat16 g_wThi[1310720];
__device__ __align__(128) __nv_bfloat16 g_wTlo[1310720];
__device__ __align__(128) float g_bcat[2560];
__device__ __align__(128) float g_xms[N_NODES * 1024];
__device__ __align__(128) __nv_bfloat16 g_xmshi[N_NODES * 1024];
__device__ __align__(128) __nv_bfloat16 g_xmslo[N_NODES * 1024];
__device__ __align__(128) __nv_bfloat16 g_fcat[N_NODES * 1024];
__device__ __align__(128) float g_M1[(size_t)N_NODES * N_NODES];
__device__ __align__(128) __nv_bfloat16 g_AnT[(size_t)N_NODES * N_NODES];
__device__ __align__(128) float g_t0[N_NODES * 1024];
__device__ __align__(128) __nv_bfloat16 g_t0T[1024 * N_NODES];
__device__ __align__(128) __nv_bfloat16 g_t1hi[N_NODES * 1024];
__device__ __align__(128) __nv_bfloat16 g_t1lo[N_NODES * 1024];
__device__ __align__(128) float g_t2[N_NODES * 512];
__device__ __align__(128) __nv_bfloat16 g_t2T[512 * N_NODES];
__device__ __align__(128) float g_ssum[N_NODES];
__device__ __align__(128) float g_rn[N_NODES];
__device__ __align__(128) float g_dis[N_NODES];
__device__ __align__(128) float g_rnpart[64 * N_NODES];
__device__ __align__(128) float g_colpart[256 * N_NODES];

// ================= low-level helpers (sm_80+ features only) =================
__device__ __forceinline__ uint32_t smem_u32(const void* p) {
    uint32_t a;
    asm("{ .reg .u64 t; cvta.to.shared.u64 t, %1; cvt.u32.u64 %0, t; }" : "=r"(a) : "l"(p));
    return a;
}

#define CP_ASYNC_CG(dst, src) \
    asm volatile("cp.async.cg.shared.global [%0], [%1], 16;" :: "r"(dst), "l"(src))
#define CP_COMMIT() asm volatile("cp.async.commit_group;" ::: "memory")
#define CP_WAIT(n)  asm volatile("cp.async.wait_group %0;" :: "n"(n) : "memory")

__device__ __forceinline__ void ldmat_x4(uint32_t& r0, uint32_t& r1, uint32_t& r2, uint32_t& r3,
                                         uint32_t addr) {
    asm volatile("ldmatrix.sync.aligned.m8n8.x4.shared.b16 {%0,%1,%2,%3}, [%4];"
                 : "=r"(r0), "=r"(r1), "=r"(r2), "=r"(r3) : "r"(addr));
}

__device__ __forceinline__ void mma16816f(float* c, const uint32_t* a, const uint32_t* b) {
    asm volatile(
        "mma.sync.aligned.m16n8k16.row.col.f32.bf16.bf16.f32 "
        "{%0,%1,%2,%3}, {%4,%5,%6,%7}, {%8,%9}, {%0,%1,%2,%3};"
        : "+f"(c[0]), "+f"(c[1]), "+f"(c[2]), "+f"(c[3])
        : "r"(a[0]), "r"(a[1]), "r"(a[2]), "r"(a[3]), "r"(b[0]), "r"(b[1]));
}

// ================= generalized bf16 HMMA NT GEMM =================
// C[M,N] = A[M,K] @ B[N,K]^T. bf16 K-major inputs.
// SPLIT==3: near-fp32 via AhiBhi + AhiBlo + AloBhi (BNT=128 only).
// EPI: 0=store fp32
//      3=ws epilogue: C=exp(-(ssum_i+ssum_j-2acc)) + rnpart row-sumsq partials
//      5=+bias, store fp32 AND hi/lo bf16
//      6=*dis[row]+bias+relu, store hi/lo bf16 only
#define BM 128
#define BK 32
#define LDSH 40   // BK + 8 halves padding

template<int SPLIT, int EPI, int BNT>
__global__ __launch_bounds__(256)
void mma_nt(const __nv_bfloat16* __restrict__ Ahi, const __nv_bfloat16* __restrict__ Alo,
            const __nv_bfloat16* __restrict__ Bhi, const __nv_bfloat16* __restrict__ Blo,
            float* __restrict__ C, __nv_bfloat16* __restrict__ Ohi, __nv_bfloat16* __restrict__ Olo,
            int M, int N, int K, int lda, int ldb, int ldc,
            const float* __restrict__ bias, const float* __restrict__ ssum,
            const float* __restrict__ dis, float* __restrict__ rnpart,
            long zA, long zB, long zC)
{
    constexpr int STAGES = (SPLIT == 1) ? 3 : 2;
    constexpr int WN     = BNT / 4;
    constexpr int NFR    = WN / 8;
    constexpr int TILEA  = BM * LDSH;
    constexpr int TILEB  = BNT * LDSH;
    constexpr int STAGE  = ((SPLIT == 3) ? 2 : 1) * (TILEA + TILEB);
    extern __shared__ __nv_bfloat16 smB[];

    const int tid  = threadIdx.x;
    const int wid  = tid >> 5;
    const int lane = tid & 31;
    const int wm = (wid & 1) * 64;
    const int wn = (wid >> 1) * WN;
    const int bm = blockIdx.y * BM;
    const int bn = blockIdx.x * BNT;

    const __nv_bfloat16* Ag  = Ahi + (size_t)blockIdx.z * zA + (size_t)bm * lda;
    const __nv_bfloat16* Bg  = Bhi + (size_t)blockIdx.z * zB + (size_t)bn * ldb;
    const __nv_bfloat16* Agl = (SPLIT == 3) ? Alo + (size_t)blockIdx.z * zA + (size_t)bm * lda : nullptr;
    const __nv_bfloat16* Bgl = (SPLIT == 3) ? Blo + (size_t)blockIdx.z * zB + (size_t)bn * ldb : nullptr;
    float* Cz = C + (size_t)blockIdx.z * zC;

    const uint32_t s_base = smem_u32(smB);
    const int lr0 = tid >> 2;
    const int lc  = (tid & 3) * 8;

    float acc[4][NFR][4];
    #pragma unroll
    for (int i = 0; i < 4; ++i)
        #pragma unroll
        for (int j = 0; j < NFR; ++j)
            #pragma unroll
            for (int q = 0; q < 4; ++q) acc[i][j][q] = 0.f;

    const int nt = K / BK;

    auto load_stage = [&](int st, int t) {
        const size_t kb = (size_t)t * BK + lc;
        const uint32_t sb = s_base + (uint32_t)(st * STAGE) * 2;
        #pragma unroll
        for (int h = 0; h < 2; ++h) {
            const int r = lr0 + h * 64;
            const uint32_t so = (uint32_t)(r * LDSH + lc) * 2;
            CP_ASYNC_CG(sb + so, Ag + (size_t)r * lda + kb);
            if (SPLIT == 3)
                CP_ASYNC_CG(sb + (uint32_t)(TILEA + TILEB) * 2 + so, Agl + (size_t)r * lda + kb);
        }
        #pragma unroll
        for (int h = 0; h < BNT / 64; ++h) {
            const int r = lr0 + h * 64;
            const uint32_t so = (uint32_t)(TILEA + r * LDSH + lc) * 2;
            CP_ASYNC_CG(sb + so, Bg + (size_t)r * ldb + kb);
            if (SPLIT == 3)
                CP_ASYNC_CG(sb + (uint32_t)(TILEA + TILEB) * 2 + so, Bgl + (size_t)r * ldb + kb);
        }
    };

    #pragma unroll
    for (int s = 0; s < STAGES - 1; ++s) { load_stage(s, s); CP_COMMIT(); }

    for (int t = 0; t < nt; ++t) {
        CP_WAIT(STAGES - 2);
        __syncthreads();
        if (t + STAGES - 1 < nt) { load_stage((t + STAGES - 1) % STAGES, t + STAGES - 1); CP_COMMIT(); }

        const uint32_t sb = s_base + (uint32_t)((t % STAGES) * STAGE) * 2;
        #pragma unroll
        for (int kk = 0; kk < BK; kk += 16) {
            uint32_t ah[4][4], al[4][4];
            #pragma unroll
            for (int mf = 0; mf < 4; ++mf) {
                int row = wm + mf * 16 + (lane & 15);
                uint32_t off = (uint32_t)(row * LDSH + kk + ((lane >> 4) << 3)) * 2;
                ldmat_x4(ah[mf][0], ah[mf][1], ah[mf][2], ah[mf][3], sb + off);
                if (SPLIT == 3)
                    ldmat_x4(al[mf][0], al[mf][1], al[mf][2], al[mf][3],
                             sb + (uint32_t)(TILEA + TILEB) * 2 + off);
            }
            uint32_t bh[NFR][2], bl[NFR][2];
            #pragma unroll
            for (int nf2 = 0; nf2 < NFR / 2; ++nf2) {
                int row = wn + nf2 * 16 + (lane & 7) + (((lane >> 4) & 1) << 3);
                uint32_t off = (uint32_t)(TILEA + row * LDSH + kk + (((lane >> 3) & 1) << 3)) * 2;
                uint32_t r0, r1, r2, r3;
                ldmat_x4(r0, r1, r2, r3, sb + off);
                bh[nf2 * 2 + 0][0] = r0; bh[nf2 * 2 + 0][1] = r1;
                bh[nf2 * 2 + 1][0] = r2; bh[nf2 * 2 + 1][1] = r3;
                if (SPLIT == 3) {
                    ldmat_x4(r0, r1, r2, r3, sb + (uint32_t)(TILEA + TILEB) * 2 + off);
                    bl[nf2 * 2 + 0][0] = r0; bl[nf2 * 2 + 0][1] = r1;
                    bl[nf2 * 2 + 1][0] = r2; bl[nf2 * 2 + 1][1] = r3;
                }
            }
            #pragma unroll
            for (int mf = 0; mf < 4; ++mf)
                #pragma unroll
                for (int nf = 0; nf < NFR; ++nf) {
                    mma16816f(acc[mf][nf], ah[mf], bh[nf]);
                    if (SPLIT == 3) {
                        mma16816f(acc[mf][nf], ah[mf], bl[nf]);
                        mma16816f(acc[mf][nf], al[mf], bh[nf]);
                    }
                }
        }
        __syncthreads();
    }

    // ---- epilogue ----
    float rs[8];
    if (EPI == 3) {
        #pragma unroll
        for (int i = 0; i < 8; ++i) rs[i] = 0.f;
    }
    #pragma unroll
    for (int mf = 0; mf < 4; ++mf) {
        #pragma unroll
        for (int nf = 0; nf < NFR; ++nf) {
            int rg = bm + wm + mf * 16 + (lane >> 2);
            int cg = bn + wn + nf * 8 + (lane & 3) * 2;
            float v0 = acc[mf][nf][0], v1 = acc[mf][nf][1];
            float v2 = acc[mf][nf][2], v3 = acc[mf][nf][3];
            if (EPI == 5) {
                float b0 = bias[cg], b1 = bias[cg + 1];
                v0 += b0; v1 += b1; v2 += b0; v3 += b1;
            }
            if (EPI == 6) {
                float d0 = dis[rg], d1 = dis[rg + 8];
                float b0 = bias[cg], b1 = bias[cg + 1];
                v0 = fmaxf(fmaf(v0, d0, b0), 0.f);
                v1 = fmaxf(fmaf(v1, d0, b1), 0.f);
                v2 = fmaxf(fmaf(v2, d1, b0), 0.f);
                v3 = fmaxf(fmaf(v3, d1, b1), 0.f);
            }
            if (EPI == 3) {
                float sc0 = ssum[cg], sc1 = ssum[cg + 1];
                float sr0 = ssum[rg], sr1 = ssum[rg + 8];
                v0 = expf(-(sr0 + sc0 - 2.f * v0));
                v1 = expf(-(sr0 + sc1 - 2.f * v1));
                v2 = expf(-(sr1 + sc0 - 2.f * v2));
                v3 = expf(-(sr1 + sc1 - 2.f * v3));
                rs[mf * 2 + 0] = fmaf(v0, v0, fmaf(v1, v1, rs[mf * 2 + 0]));
                rs[mf * 2 + 1] = fmaf(v2, v2, fmaf(v3, v3, rs[mf * 2 + 1]));
            }
            if (EPI == 6) {
                __nv_bfloat162 h01, l01, h23, l23;
                h01.x = __float2bfloat16(v0); h01.y = __float2bfloat16(v1);
                l01.x = __float2bfloat16(v0 - __bfloat162float(h01.x));
                l01.y = __float2bfloat16(v1 - __bfloat162float(h01.y));
                h23.x = __float2bfloat16(v2); h23.y = __float2bfloat16(v3);
                l23.x = __float2bfloat16(v2 - __bfloat162float(h23.x));
                l23.y = __float2bfloat16(v3 - __bfloat162float(h23.y));
                *(__nv_bfloat162*)(Ohi + (size_t)rg * ldc + cg) = h01;
                *(__nv_bfloat162*)(Olo + (size_t)rg * ldc + cg) = l01;
                *(__nv_bfloat162*)(Ohi + (size_t)(rg + 8) * ldc + cg) = h23;
                *(__nv_bfloat162*)(Olo + (size_t)(rg + 8) * ldc + cg) = l23;
            } else {
                float2 p0; p0.x = v0; p0.y = v1;
                float2 p1; p1.x = v2; p1.y = v3;
                *(float2*)(Cz + (size_t)rg * ldc + cg) = p0;
                *(float2*)(Cz + (size_t)(rg + 8) * ldc + cg) = p1;
                if (EPI == 5) {
                    __nv_bfloat162 h01, l01, h23, l23;
                    h01.x = __float2bfloat16(v0); h01.y = __float2bfloat16(v1);
                    l01.x = __float2bfloat16(v0 - __bfloat162float(h01.x));
                    l01.y = __float2bfloat16(v1 - __bfloat162float(h01.y));
                    h23.x = __float2bfloat16(v2); h23.y = __float2bfloat16(v3);
                    l23.x = __float2bfloat16(v2 - __bfloat162float(h23.x));
                    l23.y = __float2bfloat16(v3 - __bfloat162float(h23.y));
                    *(__nv_bfloat162*)(Ohi + (size_t)rg * ldc + cg) = h01;
                    *(__nv_bfloat162*)(Olo + (size_t)rg * ldc + cg) = l01;
                    *(__nv_bfloat162*)(Ohi + (size_t)(rg + 8) * ldc + cg) = h23;
                    *(__nv_bfloat162*)(Olo + (size_t)(rg + 8) * ldc + cg) = l23;
                }
            }
        }
    }
    if (EPI == 3) {
        // reduce ws row sum-of-squares across 4-lane groups, write partials
        #pragma unroll
        for (int i = 0; i < 8; ++i) {
            rs[i] += __shfl_xor_sync(0xffffffffu, rs[i], 1);
            rs[i] += __shfl_xor_sync(0xffffffffu, rs[i], 2);
        }
        if ((lane & 3) == 0) {
            int p = blockIdx.x * 4 + (wid >> 1);
            #pragma unroll
            for (int mf = 0; mf < 4; ++mf) {
                int row = bm + wm + mf * 16 + (lane >> 2);
                rnpart[(size_t)p * N_NODES + row] = rs[mf * 2 + 0];
                rnpart[(size_t)p * N_NODES + row + 8] = rs[mf * 2 + 1];
            }
        }
    }
}

// ---------------- prep kernels ----------------
__global__ void transpose_split_kernel(const float* __restrict__ in,
                                       __nv_bfloat16* __restrict__ ohi,
                                       __nv_bfloat16* __restrict__ olo, int R, int C)
{
    __shared__ float t[32][33];
    int r0 = blockIdx.y * 32, c0 = blockIdx.x * 32;
    int tx = threadIdx.x, ty = threadIdx.y;
    #pragma unroll
    for (int j = 0; j < 4; ++j)
        t[ty + j * 8][tx] = in[(size_t)(r0 + ty + j * 8) * C + c0 + tx];
    __syncthreads();
    #pragma unroll
    for (int j = 0; j < 4; ++j) {
        int c = c0 + ty + j * 8;
        float v = t[tx][ty + j * 8];
        __nv_bfloat16 h = __float2bfloat16(v);
        __nv_bfloat16 l = __float2bfloat16(v - __bfloat162float(h));
        ohi[(size_t)c * R + r0 + tx] = h;
        olo[(size_t)c * R + r0 + tx] = l;
    }
}

__global__ void split_kernel(const float* __restrict__ in, __nv_bfloat16* __restrict__ ohi,
                             __nv_bfloat16* __restrict__ olo, int n)
{
    int idx = blockIdx.x * 256 + threadIdx.x;
    if (idx < n) {
        float v = in[idx];
        __nv_bfloat16 h = __float2bfloat16(v);
        ohi[idx] = h;
        olo[idx] = __float2bfloat16(v - __bfloat162float(h));
    }
}

__global__ void concat_bias_kernel(const float* bm, const float* bs, const float* mb0,
                                   const float* sb0, const float* mb1, const float* sb1,
                                   float* __restrict__ bcat)
{
    for (int i = threadIdx.x; i < 2560; i += blockDim.x) {
        float v;
        if (i < 512)        v = bm[i];
        else if (i < 1024)  v = bs[i - 512];
        else if (i < 1536)  v = mb0[i - 1024];
        else if (i < 2048)  v = sb0[i - 1536];
        else if (i < 2304)  v = mb1[i - 2048];
        else                v = sb1[i - 2304];
        bcat[i] = v;
    }
}

// ---------------- block reduction ----------------
__device__ __forceinline__ float blockReduceSum(float v, float* sh) {
    __syncthreads();
    int lane = threadIdx.x & 31, wid = threadIdx.x >> 5;
    #pragma unroll
    for (int o = 16; o; o >>= 1) v += __shfl_down_sync(0xffffffffu, v, o);
    if (lane == 0) sh[wid] = v;
    __syncthreads();
    if (wid == 0) {
        float r = (lane < ((blockDim.x + 31) >> 5)) ? sh[lane] : 0.f;
        #pragma unroll
        for (int o = 16; o; o >>= 1) r += __shfl_down_sync(0xffffffffu, r, o);
        if (lane == 0) sh[0] = r;
    }
    __syncthreads();
    return sh[0];
}

// ---------------- per-row stats: fcat = [m_hat || cs_hat] bf16, ssum = sq + csum ----
__global__ void rowstats_kernel(const float* __restrict__ xms,
                                __nv_bfloat16* __restrict__ fcat, float* __restrict__ ssum)
{
    __shared__ float sh[32];
    int row = blockIdx.x;
    const float* xmr = xms + (size_t)row * 1024;
    const float* xsr = xmr + 512;
    float s1 = 0.f, s2 = 0.f, s3 = 0.f;
    for (int j = threadIdx.x; j < F_DIM; j += blockDim.x) {
        float a = xmr[j]; s1 = fmaf(a, a, s1);
        float e = expf(xsr[j]); s2 = fmaf(e, e, s2); s3 += e;
    }
    s1 = blockReduceSum(s1, sh);
    s2 = blockReduceSum(s2, sh);
    s3 = blockReduceSum(s3, sh);
    float dm = fmaxf(sqrtf(s1), 1e-12f);
    float dc = fmaxf(sqrtf(s2), 1e-12f);
    if (threadIdx.x == 0) ssum[row] = s1 / (dm * dm) + s3 / dc;
    for (int j = threadIdx.x; j < F_DIM; j += blockDim.x) {
        fcat[(size_t)row * 1024 + j]       = __float2bfloat16(xmr[j] / dm);
        fcat[(size_t)row * 1024 + 512 + j] = __float2bfloat16(sqrtf(expf(xsr[j]) / dc));
    }
}

__global__ void rnreduce_kernel(const float* __restrict__ rnpart, float* __restrict__ rn) {
    int row = blockIdx.x * 256 + threadIdx.x;
    float s = 0.f;
    #pragma unroll
    for (int p = 0; p < 64; ++p) s += rnpart[(size_t)p * N_NODES + row];
    rn[row] = fmaxf(sqrtf(s), 1e-12f);
}

// ---------------- fused adjacency + bf16-transpose + column partials ----------------
__global__ __launch_bounds__(256)
void adjT_kernel(const float* __restrict__ M1, const float* __restrict__ rn,
                 const float* __restrict__ ne, const float* __restrict__ epsm,
                 const float* __restrict__ beta, const float* __restrict__ delta,
                 __nv_bfloat16* __restrict__ AnT, float* __restrict__ colpart)
{
    __shared__ __nv_bfloat16 tileT[64][66];
    const int c0 = blockIdx.x * 64, r0 = blockIdx.y * 64;
    const int t = threadIdx.x;
    const int jl = t & 63, ig = t >> 6;
    const int j = c0 + jl;
    const float b = beta[0], d = delta[0];
    float s = 0.f;
    #pragma unroll 4
    for (int k = 0; k < 16; ++k) {
        const int il = ig + 4 * k;
        const int i = r0 + il;
        const size_t idx = (size_t)i * N_NODES + j;
        float w = M1[idx] / rn[i];
        float tt = (1.f - b) * w + b * ne[idx];
        tt = fminf(fmaxf(tt, 1e-6f), 1.f - 1e-6f);
        float e = fminf(fmaxf(epsm[idx], 1e-6f), 1.f - 1e-6f);
        float num = tt * e;
        float sg = num / (num + (1.f - tt) * (1.f - e));
        float a = (sg > d) ? sg : 0.f;
        if (i == j && !(a > 0.f)) a += 1.f;
        tileT[il][jl] = __float2bfloat16(a);
        s += a;
    }
    colpart[(size_t)(blockIdx.y * 4 + ig) * N_NODES + j] = s;
    __syncthreads();
    const int il2 = t & 63;
    #pragma unroll
    for (int jj = t >> 6; jj < 64; jj += 4)
        AnT[(size_t)(c0 + jj) * N_NODES + r0 + il2] = tileT[il2][jj];
}

__global__ void colsum2_kernel(const float* __restrict__ part, float* __restrict__ dis) {
    int j = blockIdx.x * 256 + threadIdx.x;
    float s = 0.f;
    for (int p = 0; p < 256; ++p) s += part[(size_t)p * N_NODES + j];
    dis[j] = (s > 0.f) ? (1.f / sqrtf(s)) : 0.f;
}

// ---------------- transpose fp32 [R,C] -> bf16 [C,R], optional row scaling by dis[r] ----
template<bool SC>
__global__ void transposeb_kernel(const float* __restrict__ in, __nv_bfloat16* __restrict__ out,
                                  int R, int C, const float* __restrict__ dis)
{
    __shared__ float t[32][33];
    int r0 = blockIdx.y * 32, c0 = blockIdx.x * 32;
    int tx = threadIdx.x, ty = threadIdx.y;
    #pragma unroll
    for (int j = 0; j < 4; ++j)
        t[ty + j * 8][tx] = in[(size_t)(r0 + ty + j * 8) * C + c0 + tx];
    __syncthreads();
    float dr = SC ? dis[r0 + tx] : 1.f;
    #pragma unroll
    for (int j = 0; j < 4; ++j) {
        int c = c0 + ty + j * 8;
        float v = t[tx][ty + j * 8];
        out[(size_t)c * R + r0 + tx] = __float2bfloat16(SC ? v * dr : v);
    }
}

// ---------------- split-K reduce + dis + bias + relu + z-split output ----------------
__global__ void reduce_out_kernel(const float* __restrict__ part, const float* __restrict__ bias,
                                  const float* __restrict__ dis, float* __restrict__ out)
{
    int idx = blockIdx.x * 256 + threadIdx.x;   // over 4096*512
    int row = idx >> 9, col = idx & 511;
    float v = fmaf(part[idx] + part[idx + N_NODES * 512], dis[row], bias[col]);
    v = fmaxf(v, 0.f);
    out[(size_t)(col >> 8) * (N_NODES * H_DIM) + (size_t)row * H_DIM + (col & 255)] = v;
}

// ---------------- host ----------------
extern "C" void kernel_launch(void* const* d_in, const int* in_sizes, int n_in,
                              void* d_out, int out_size)
{
    const float* x        = (const float*)d_in[0];
    const float* new_edge = (const float*)d_in[1];
    const float* beta     = (const float*)d_in[2];
    const float* delta    = (const float*)d_in[3];
    const float* eps      = (const float*)d_in[4];
    const float* Wm       = (const float*)d_in[5];
    const float* bm       = (const float*)d_in[6];
    const float* Ws       = (const float*)d_in[7];
    const float* bs       = (const float*)d_in[8];
    const float* mW0      = (const float*)d_in[9];
    const float* mb0      = (const float*)d_in[10];
    const float* mW1      = (const float*)d_in[11];
    const float* mb1      = (const float*)d_in[12];
    const float* sW0      = (const float*)d_in[13];
    const float* sb0      = (const float*)d_in[14];
    const float* sW1      = (const float*)d_in[15];
    const float* sb1      = (const float*)d_in[16];
    float* out = (float*)d_out;

    float *xms, *M1, *t0, *t2, *ssum, *rn, *dis, *rnpart, *colpart, *bcat;
    __nv_bfloat16 *xhi, *xlo, *wThi, *wTlo, *xmshi, *xmslo, *fcat, *AnT, *t0T, *t1hi, *t1lo, *t2T;
    cudaGetSymbolAddress((void**)&xhi, g_xhi);
    cudaGetSymbolAddress((void**)&xlo, g_xlo);
    cudaGetSymbolAddress((void**)&wThi, g_wThi);
    cudaGetSymbolAddress((void**)&wTlo, g_wTlo);
    cudaGetSymbolAddress((void**)&bcat, g_bcat);
    cudaGetSymbolAddress((void**)&xms, g_xms);
    cudaGetSymbolAddress((void**)&xmshi, g_xmshi);
    cudaGetSymbolAddress((void**)&xmslo, g_xmslo);
    cudaGetSymbolAddress((void**)&fcat, g_fcat);
    cudaGetSymbolAddress((void**)&M1, g_M1);
    cudaGetSymbolAddress((void**)&AnT, g_AnT);
    cudaGetSymbolAddress((void**)&t0, g_t0);
    cudaGetSymbolAddress((void**)&t0T, g_t0T);
    cudaGetSymbolAddress((void**)&t1hi, g_t1hi);
    cudaGetSymbolAddress((void**)&t1lo, g_t1lo);
    cudaGetSymbolAddress((void**)&t2, g_t2);
    cudaGetSymbolAddress((void**)&t2T, g_t2T);
    cudaGetSymbolAddress((void**)&ssum, g_ssum);
    cudaGetSymbolAddress((void**)&rn, g_rn);
    cudaGetSymbolAddress((void**)&dis, g_dis);
    cudaGetSymbolAddress((void**)&rnpart, g_rnpart);
    cudaGetSymbolAddress((void**)&colpart, g_colpart);

    const int SM_N_SPLIT = 2 * 2 * (128 + 128) * LDSH * 2;   // 81920
    const int SM_W_PLAIN = 3 * (128 + 256) * LDSH * 2;       // 92160
    cudaFuncSetAttribute(mma_nt<3,5,128>, cudaFuncAttributeMaxDynamicSharedMemorySize, SM_N_SPLIT);
    cudaFuncSetAttribute(mma_nt<3,0,128>, cudaFuncAttributeMaxDynamicSharedMemorySize, SM_N_SPLIT);
    cudaFuncSetAttribute(mma_nt<1,0,256>, cudaFuncAttributeMaxDynamicSharedMemorySize, SM_W_PLAIN);
    cudaFuncSetAttribute(mma_nt<1,3,256>, cudaFuncAttributeMaxDynamicSharedMemorySize, SM_W_PLAIN);
    cudaFuncSetAttribute(mma_nt<1,6,256>, cudaFuncAttributeMaxDynamicSharedMemorySize, SM_W_PLAIN);

    dim3 blk(256);
    dim3 tpb(32, 8);

    // ---- prep ----
    concat_bias_kernel<<<1, 256>>>(bm, bs, mb0, sb0, mb1, sb1, bcat);
    transpose_split_kernel<<<dim3(16, 16), tpb>>>(Wm,  wThi + 0,       wTlo + 0,       512, 512);
    transpose_split_kernel<<<dim3(16, 16), tpb>>>(Ws,  wThi + 262144,  wTlo + 262144,  512, 512);
    transpose_split_kernel<<<dim3(16, 16), tpb>>>(mW0, wThi + 524288,  wTlo + 524288,  512, 512);
    transpose_split_kernel<<<dim3(16, 16), tpb>>>(sW0, wThi + 786432,  wTlo + 786432,  512, 512);
    transpose_split_kernel<<<dim3(8, 16),  tpb>>>(mW1, wThi + 1048576, wTlo + 1048576, 512, 256);
    transpose_split_kernel<<<dim3(8, 16),  tpb>>>(sW1, wThi + 1179648, wTlo + 1179648, 512, 256);
    split_kernel<<<(N_NODES * F_DIM) / 256, blk>>>(x, xhi, xlo, N_NODES * F_DIM);

    // ---- projection: xms = x @ [Wm||Ws] + [bm||bs]; also writes hi/lo bf16 ----
    mma_nt<3,5,128><<<dim3(8, 32), blk, SM_N_SPLIT>>>(xhi, xlo, wThi, wTlo, xms, xmshi, xmslo,
        N_NODES, 1024, 512, 512, 512, 1024, bcat, nullptr, nullptr, nullptr, 0, 0, 0);

    // ---- row statistics -> fcat [m||cs], ssum ----
    rowstats_kernel<<<N_NODES, 256>>>(xms, fcat, ssum);

    // ---- single concatenated gram (K=1024) with fused ws + rn partials ----
    mma_nt<1,3,256><<<dim3(16, 32), blk, SM_W_PLAIN>>>(fcat, nullptr, fcat, nullptr, M1,
        nullptr, nullptr, N_NODES, N_NODES, 1024, 1024, 1024, N_NODES,
        nullptr, ssum, nullptr, rnpart, 0, 0, 0);
    rnreduce_kernel<<<N_NODES / 256, blk>>>(rnpart, rn);

    // ---- adjacency: adj + transpose-to-bf16 + colsum partials (fused) ----
    adjT_kernel<<<dim3(64, 64), blk>>>(M1, rn, new_edge, eps, beta, delta, AnT, colpart);
    colsum2_kernel<<<N_NODES / 256, blk>>>(colpart, dis);

    // ---- encoder layer 1 ----
    mma_nt<3,0,128><<<dim3(4, 32, 2), blk, SM_N_SPLIT>>>(xmshi, xmslo, wThi + 524288, wTlo + 524288,
        t0, nullptr, nullptr, N_NODES, 512, 512, 1024, 512, 1024,
        nullptr, nullptr, nullptr, nullptr, 512, 262144, 512);
    transposeb_kernel<true><<<dim3(32, 128), tpb>>>(t0, t0T, N_NODES, 1024, dis);
    mma_nt<1,6,256><<<dim3(4, 32), blk, SM_W_PLAIN>>>(AnT, nullptr, t0T, nullptr, nullptr,
        t1hi, t1lo, N_NODES, 1024, N_NODES, N_NODES, N_NODES, 1024,
        bcat + 1024, nullptr, dis, nullptr, 0, 0, 0);

    // ---- encoder layer 2 ----
    mma_nt<3,0,128><<<dim3(2, 32, 2), blk, SM_N_SPLIT>>>(t1hi, t1lo, wThi + 1048576, wTlo + 1048576,
        t2, nullptr, nullptr, N_NODES, 256, 512, 1024, 512, 512,
        nullptr, nullptr, nullptr, nullptr, 512, 131072, 256);
    transposeb_kernel<true><<<dim3(16, 128), tpb>>>(t2, t2T, N_NODES, 512, dis);
    // split-K x2 adjacency aggregation -> partials in t0 (scratch reuse)
    mma_nt<1,0,256><<<dim3(2, 32, 2), blk, SM_W_PLAIN>>>(AnT, nullptr, t2T, nullptr, t0,
        nullptr, nullptr, N_NODES, 512, 2048, N_NODES, N_NODES, 512,
        nullptr, nullptr, nullptr, nullptr, 2048, 2048, (long)N_NODES * 512);
    reduce_out_kernel<<<(N_NODES * 512) / 256, blk>>>(t0, bcat + 2048, dis, out);
}

// round 9
// speedup vs baseline: 5.8223x; 1.0643x over previous
#include <cuda_runtime.h>
#include <cuda_bf16.h>
#include <math.h>
#include <stdint.h>

#define N_NODES 4096
#define F_DIM   512
#define H_DIM   256

// ---------------- scratch (static device allocations; no runtime alloc) ----------
__device__ __align__(128) __nv_bfloat16 g_xhi[N_NODES * F_DIM];
__device__ __align__(128) __nv_bfloat16 g_xlo[N_NODES * F_DIM];
__device__ __align__(128) __nv_bfloat16 g_wThi[1310720];
__device__ __align__(128) __nv_bfloat16 g_wTlo[1310720];
__device__ __align__(128) float g_bcat[2560];
__device__ __align__(128) float g_xms[N_NODES * 1024];
__device__ __align__(128) __nv_bfloat16 g_xmshi[N_NODES * 1024];
__device__ __align__(128) __nv_bfloat16 g_xmslo[N_NODES * 1024];
__device__ __align__(128) __nv_bfloat16 g_fcat[N_NODES * 1024];
__device__ __align__(128) __nv_bfloat16 g_M1b[(size_t)N_NODES * N_NODES];
__device__ __align__(128) __nv_bfloat16 g_AnT[(size_t)N_NODES * N_NODES];
__device__ __align__(128) float g_t0[N_NODES * 1024];
__device__ __align__(128) __nv_bfloat16 g_t0T[1024 * N_NODES];
__device__ __align__(128) __nv_bfloat16 g_t1hi[N_NODES * 1024];
__device__ __align__(128) __nv_bfloat16 g_t1lo[N_NODES * 1024];
__device__ __align__(128) float g_t2[N_NODES * 512];
__device__ __align__(128) __nv_bfloat16 g_t2T[512 * N_NODES];
__device__ __align__(128) float g_ssum[N_NODES];
__device__ __align__(128) float g_rn[N_NODES];
__device__ __align__(128) float g_dis[N_NODES];
__device__ __align__(128) float g_rnpart[64 * N_NODES];
__device__ __align__(128) float g_colpart[256 * N_NODES];

// ================= low-level helpers (sm_80+ features only) =================
__device__ __forceinline__ uint32_t smem_u32(const void* p) {
    uint32_t a;
    asm("{ .reg .u64 t; cvta.to.shared.u64 t, %1; cvt.u32.u64 %0, t; }" : "=r"(a) : "l"(p));
    return a;
}

#define CP_ASYNC_CG(dst, src) \
    asm volatile("cp.async.cg.shared.global [%0], [%1], 16;" :: "r"(dst), "l"(src))
#define CP_COMMIT() asm volatile("cp.async.commit_group;" ::: "memory")
#define CP_WAIT(n)  asm volatile("cp.async.wait_group %0;" :: "n"(n) : "memory")

__device__ __forceinline__ void ldmat_x4(uint32_t& r0, uint32_t& r1, uint32_t& r2, uint32_t& r3,
                                         uint32_t addr) {
    asm volatile("ldmatrix.sync.aligned.m8n8.x4.shared.b16 {%0,%1,%2,%3}, [%4];"
                 : "=r"(r0), "=r"(r1), "=r"(r2), "=r"(r3) : "r"(addr));
}

__device__ __forceinline__ void mma16816f(float* c, const uint32_t* a, const uint32_t* b) {
    asm volatile(
        "mma.sync.aligned.m16n8k16.row.col.f32.bf16.bf16.f32 "
        "{%0,%1,%2,%3}, {%4,%5,%6,%7}, {%8,%9}, {%0,%1,%2,%3};"
        : "+f"(c[0]), "+f"(c[1]), "+f"(c[2]), "+f"(c[3])
        : "r"(a[0]), "r"(a[1]), "r"(a[2]), "r"(a[3]), "r"(b[0]), "r"(b[1]));
}

// ================= generalized bf16 HMMA NT GEMM =================
// C[M,N] = A[M,K] @ B[N,K]^T. bf16 K-major inputs.
// SPLIT==3: near-fp32 via AhiBhi + AhiBlo + AloBhi (BNT=128 only).
// EPI: 0=store fp32
//      3=ws epilogue: bf16 out = exp(-(ssum_i+ssum_j-2acc)) + rnpart row-sumsq partials
//      5=+bias, store fp32 AND hi/lo bf16
//      6=*dis[row]+bias+relu, store hi/lo bf16 only
#define BM 128
#define BK 32
#define LDSH 40   // BK + 8 halves padding

template<int SPLIT, int EPI, int BNT>
__global__ __launch_bounds__(256)
void mma_nt(const __nv_bfloat16* __restrict__ Ahi, const __nv_bfloat16* __restrict__ Alo,
            const __nv_bfloat16* __restrict__ Bhi, const __nv_bfloat16* __restrict__ Blo,
            float* __restrict__ C, __nv_bfloat16* __restrict__ Ohi, __nv_bfloat16* __restrict__ Olo,
            int M, int N, int K, int lda, int ldb, int ldc,
            const float* __restrict__ bias, const float* __restrict__ ssum,
            const float* __restrict__ dis, float* __restrict__ rnpart,
            long zA, long zB, long zC)
{
    constexpr int STAGES = (SPLIT == 1) ? 3 : 2;
    constexpr int WN     = BNT / 4;
    constexpr int NFR    = WN / 8;
    constexpr int TILEA  = BM * LDSH;
    constexpr int TILEB  = BNT * LDSH;
    constexpr int STAGE  = ((SPLIT == 3) ? 2 : 1) * (TILEA + TILEB);
    extern __shared__ __nv_bfloat16 smB[];

    const int tid  = threadIdx.x;
    const int wid  = tid >> 5;
    const int lane = tid & 31;
    const int wm = (wid & 1) * 64;
    const int wn = (wid >> 1) * WN;
    const int bm = blockIdx.y * BM;
    const int bn = blockIdx.x * BNT;

    const __nv_bfloat16* Ag  = Ahi + (size_t)blockIdx.z * zA + (size_t)bm * lda;
    const __nv_bfloat16* Bg  = Bhi + (size_t)blockIdx.z * zB + (size_t)bn * ldb;
    const __nv_bfloat16* Agl = (SPLIT == 3) ? Alo + (size_t)blockIdx.z * zA + (size_t)bm * lda : nullptr;
    const __nv_bfloat16* Bgl = (SPLIT == 3) ? Blo + (size_t)blockIdx.z * zB + (size_t)bn * ldb : nullptr;
    float* Cz = C + (size_t)blockIdx.z * zC;

    const uint32_t s_base = smem_u32(smB);
    const int lr0 = tid >> 2;
    const int lc  = (tid & 3) * 8;

    float acc[4][NFR][4];
    #pragma unroll
    for (int i = 0; i < 4; ++i)
        #pragma unroll
        for (int j = 0; j < NFR; ++j)
            #pragma unroll
            for (int q = 0; q < 4; ++q) acc[i][j][q] = 0.f;

    const int nt = K / BK;

    auto load_stage = [&](int st, int t) {
        const size_t kb = (size_t)t * BK + lc;
        const uint32_t sb = s_base + (uint32_t)(st * STAGE) * 2;
        #pragma unroll
        for (int h = 0; h < 2; ++h) {
            const int r = lr0 + h * 64;
            const uint32_t so = (uint32_t)(r * LDSH + lc) * 2;
            CP_ASYNC_CG(sb + so, Ag + (size_t)r * lda + kb);
            if (SPLIT == 3)
                CP_ASYNC_CG(sb + (uint32_t)(TILEA + TILEB) * 2 + so, Agl + (size_t)r * lda + kb);
        }
        #pragma unroll
        for (int h = 0; h < BNT / 64; ++h) {
            const int r = lr0 + h * 64;
            const uint32_t so = (uint32_t)(TILEA + r * LDSH + lc) * 2;
            CP_ASYNC_CG(sb + so, Bg + (size_t)r * ldb + kb);
            if (SPLIT == 3)
                CP_ASYNC_CG(sb + (uint32_t)(TILEA + TILEB) * 2 + so, Bgl + (size_t)r * ldb + kb);
        }
    };

    #pragma unroll
    for (int s = 0; s < STAGES - 1; ++s) { load_stage(s, s); CP_COMMIT(); }

    for (int t = 0; t < nt; ++t) {
        CP_WAIT(STAGES - 2);
        __syncthreads();
        if (t + STAGES - 1 < nt) { load_stage((t + STAGES - 1) % STAGES, t + STAGES - 1); CP_COMMIT(); }

        const uint32_t sb = s_base + (uint32_t)((t % STAGES) * STAGE) * 2;
        #pragma unroll
        for (int kk = 0; kk < BK; kk += 16) {
            uint32_t ah[4][4], al[4][4];
            #pragma unroll
            for (int mf = 0; mf < 4; ++mf) {
                int row = wm + mf * 16 + (lane & 15);
                uint32_t off = (uint32_t)(row * LDSH + kk + ((lane >> 4) << 3)) * 2;
                ldmat_x4(ah[mf][0], ah[mf][1], ah[mf][2], ah[mf][3], sb + off);
                if (SPLIT == 3)
                    ldmat_x4(al[mf][0], al[mf][1], al[mf][2], al[mf][3],
                             sb + (uint32_t)(TILEA + TILEB) * 2 + off);
            }
            uint32_t bh[NFR][2], bl[NFR][2];
            #pragma unroll
            for (int nf2 = 0; nf2 < NFR / 2; ++nf2) {
                int row = wn + nf2 * 16 + (lane & 7) + (((lane >> 4) & 1) << 3);
                uint32_t off = (uint32_t)(TILEA + row * LDSH + kk + (((lane >> 3) & 1) << 3)) * 2;
                uint32_t r0, r1, r2, r3;
                ldmat_x4(r0, r1, r2, r3, sb + off);
                bh[nf2 * 2 + 0][0] = r0; bh[nf2 * 2 + 0][1] = r1;
                bh[nf2 * 2 + 1][0] = r2; bh[nf2 * 2 + 1][1] = r3;
                if (SPLIT == 3) {
                    ldmat_x4(r0, r1, r2, r3, sb + (uint32_t)(TILEA + TILEB) * 2 + off);
                    bl[nf2 * 2 + 0][0] = r0; bl[nf2 * 2 + 0][1] = r1;
                    bl[nf2 * 2 + 1][0] = r2; bl[nf2 * 2 + 1][1] = r3;
                }
            }
            #pragma unroll
            for (int mf = 0; mf < 4; ++mf)
                #pragma unroll
                for (int nf = 0; nf < NFR; ++nf) {
                    mma16816f(acc[mf][nf], ah[mf], bh[nf]);
                    if (SPLIT == 3) {
                        mma16816f(acc[mf][nf], ah[mf], bl[nf]);
                        mma16816f(acc[mf][nf], al[mf], bh[nf]);
                    }
                }
        }
        __syncthreads();
    }

    // ---- epilogue ----
    float rs[8];
    if (EPI == 3) {
        #pragma unroll
        for (int i = 0; i < 8; ++i) rs[i] = 0.f;
    }
    #pragma unroll
    for (int mf = 0; mf < 4; ++mf) {
        #pragma unroll
        for (int nf = 0; nf < NFR; ++nf) {
            int rg = bm + wm + mf * 16 + (lane >> 2);
            int cg = bn + wn + nf * 8 + (lane & 3) * 2;
            float v0 = acc[mf][nf][0], v1 = acc[mf][nf][1];
            float v2 = acc[mf][nf][2], v3 = acc[mf][nf][3];
            if (EPI == 5) {
                float b0 = bias[cg], b1 = bias[cg + 1];
                v0 += b0; v1 += b1; v2 += b0; v3 += b1;
            }
            if (EPI == 6) {
                float d0 = dis[rg], d1 = dis[rg + 8];
                float b0 = bias[cg], b1 = bias[cg + 1];
                v0 = fmaxf(fmaf(v0, d0, b0), 0.f);
                v1 = fmaxf(fmaf(v1, d0, b1), 0.f);
                v2 = fmaxf(fmaf(v2, d1, b0), 0.f);
                v3 = fmaxf(fmaf(v3, d1, b1), 0.f);
            }
            if (EPI == 3) {
                float sc0 = ssum[cg], sc1 = ssum[cg + 1];
                float sr0 = ssum[rg], sr1 = ssum[rg + 8];
                v0 = expf(2.f * v0 - sr0 - sc0);
                v1 = expf(2.f * v1 - sr0 - sc1);
                v2 = expf(2.f * v2 - sr1 - sc0);
                v3 = expf(2.f * v3 - sr1 - sc1);
                rs[mf * 2 + 0] = fmaf(v0, v0, fmaf(v1, v1, rs[mf * 2 + 0]));
                rs[mf * 2 + 1] = fmaf(v2, v2, fmaf(v3, v3, rs[mf * 2 + 1]));
            }
            if (EPI == 3) {
                // bf16 ws store only (rnpart carries fp32 row sums)
                __nv_bfloat162 h01, h23;
                h01.x = __float2bfloat16(v0); h01.y = __float2bfloat16(v1);
                h23.x = __float2bfloat16(v2); h23.y = __float2bfloat16(v3);
                *(__nv_bfloat162*)(Ohi + (size_t)rg * ldc + cg) = h01;
                *(__nv_bfloat162*)(Ohi + (size_t)(rg + 8) * ldc + cg) = h23;
            } else if (EPI == 6) {
                __nv_bfloat162 h01, l01, h23, l23;
                h01.x = __float2bfloat16(v0); h01.y = __float2bfloat16(v1);
                l01.x = __float2bfloat16(v0 - __bfloat162float(h01.x));
                l01.y = __float2bfloat16(v1 - __bfloat162float(h01.y));
                h23.x = __float2bfloat16(v2); h23.y = __float2bfloat16(v3);
                l23.x = __float2bfloat16(v2 - __bfloat162float(h23.x));
                l23.y = __float2bfloat16(v3 - __bfloat162float(h23.y));
                *(__nv_bfloat162*)(Ohi + (size_t)rg * ldc + cg) = h01;
                *(__nv_bfloat162*)(Olo + (size_t)rg * ldc + cg) = l01;
                *(__nv_bfloat162*)(Ohi + (size_t)(rg + 8) * ldc + cg) = h23;
                *(__nv_bfloat162*)(Olo + (size_t)(rg + 8) * ldc + cg) = l23;
            } else {
                float2 p0; p0.x = v0; p0.y = v1;
                float2 p1; p1.x = v2; p1.y = v3;
                *(float2*)(Cz + (size_t)rg * ldc + cg) = p0;
                *(float2*)(Cz + (size_t)(rg + 8) * ldc + cg) = p1;
                if (EPI == 5) {
                    __nv_bfloat162 h01, l01, h23, l23;
                    h01.x = __float2bfloat16(v0); h01.y = __float2bfloat16(v1);
                    l01.x = __float2bfloat16(v0 - __bfloat162float(h01.x));
                    l01.y = __float2bfloat16(v1 - __bfloat162float(h01.y));
                    h23.x = __float2bfloat16(v2); h23.y = __float2bfloat16(v3);
                    l23.x = __float2bfloat16(v2 - __bfloat162float(h23.x));
                    l23.y = __float2bfloat16(v3 - __bfloat162float(h23.y));
                    *(__nv_bfloat162*)(Ohi + (size_t)rg * ldc + cg) = h01;
                    *(__nv_bfloat162*)(Olo + (size_t)rg * ldc + cg) = l01;
                    *(__nv_bfloat162*)(Ohi + (size_t)(rg + 8) * ldc + cg) = h23;
                    *(__nv_bfloat162*)(Olo + (size_t)(rg + 8) * ldc + cg) = l23;
                }
            }
        }
    }
    if (EPI == 3) {
        #pragma unroll
        for (int i = 0; i < 8; ++i) {
            rs[i] += __shfl_xor_sync(0xffffffffu, rs[i], 1);
            rs[i] += __shfl_xor_sync(0xffffffffu, rs[i], 2);
        }
        if ((lane & 3) == 0) {
            int p = blockIdx.x * 4 + (wid >> 1);
            #pragma unroll
            for (int mf = 0; mf < 4; ++mf) {
                int row = bm + wm + mf * 16 + (lane >> 2);
                rnpart[(size_t)p * N_NODES + row] = rs[mf * 2 + 0];
                rnpart[(size_t)p * N_NODES + row + 8] = rs[mf * 2 + 1];
            }
        }
    }
}

// ---------------- batched weight prep: 6 transposes+splits in one launch ----------------
__global__ void wprep_kernel(const float* __restrict__ Wm, const float* __restrict__ Ws,
                             const float* __restrict__ mW0, const float* __restrict__ sW0,
                             const float* __restrict__ mW1, const float* __restrict__ sW1,
                             __nv_bfloat16* __restrict__ wThi, __nv_bfloat16* __restrict__ wTlo)
{
    const int z = blockIdx.z;
    const float* in; int C; long off;
    switch (z) {
        case 0:  in = Wm;  C = 512; off = 0;       break;
        case 1:  in = Ws;  C = 512; off = 262144;  break;
        case 2:  in = mW0; C = 512; off = 524288;  break;
        case 3:  in = sW0; C = 512; off = 786432;  break;
        case 4:  in = mW1; C = 256; off = 1048576; break;
        default: in = sW1; C = 256; off = 1179648; break;
    }
    if (blockIdx.x * 32 >= C) return;
    const int R = 512;
    __shared__ float t[32][33];
    int r0 = blockIdx.y * 32, c0 = blockIdx.x * 32;
    int tx = threadIdx.x, ty = threadIdx.y;
    #pragma unroll
    for (int j = 0; j < 4; ++j)
        t[ty + j * 8][tx] = in[(size_t)(r0 + ty + j * 8) * C + c0 + tx];
    __syncthreads();
    #pragma unroll
    for (int j = 0; j < 4; ++j) {
        int c = c0 + ty + j * 8;
        float v = t[tx][ty + j * 8];
        __nv_bfloat16 h = __float2bfloat16(v);
        __nv_bfloat16 l = __float2bfloat16(v - __bfloat162float(h));
        wThi[off + (size_t)c * R + r0 + tx] = h;
        wTlo[off + (size_t)c * R + r0 + tx] = l;
    }
}

__global__ void split_kernel(const float* __restrict__ in, __nv_bfloat16* __restrict__ ohi,
                             __nv_bfloat16* __restrict__ olo, int n)
{
    int idx = blockIdx.x * 256 + threadIdx.x;
    if (idx < n) {
        float v = in[idx];
        __nv_bfloat16 h = __float2bfloat16(v);
        ohi[idx] = h;
        olo[idx] = __float2bfloat16(v - __bfloat162float(h));
    }
}

__global__ void concat_bias_kernel(const float* bm, const float* bs, const float* mb0,
                                   const float* sb0, const float* mb1, const float* sb1,
                                   float* __restrict__ bcat)
{
    for (int i = threadIdx.x; i < 2560; i += blockDim.x) {
        float v;
        if (i < 512)        v = bm[i];
        else if (i < 1024)  v = bs[i - 512];
        else if (i < 1536)  v = mb0[i - 1024];
        else if (i < 2048)  v = sb0[i - 1536];
        else if (i < 2304)  v = mb1[i - 2048];
        else                v = sb1[i - 2304];
        bcat[i] = v;
    }
}

// ---------------- block reduction ----------------
__device__ __forceinline__ float blockReduceSum(float v, float* sh) {
    __syncthreads();
    int lane = threadIdx.x & 31, wid = threadIdx.x >> 5;
    #pragma unroll
    for (int o = 16; o; o >>= 1) v += __shfl_down_sync(0xffffffffu, v, o);
    if (lane == 0) sh[wid] = v;
    __syncthreads();
    if (wid == 0) {
        float r = (lane < ((blockDim.x + 31) >> 5)) ? sh[lane] : 0.f;
        #pragma unroll
        for (int o = 16; o; o >>= 1) r += __shfl_down_sync(0xffffffffu, r, o);
        if (lane == 0) sh[0] = r;
    }
    __syncthreads();
    return sh[0];
}

// ---------------- per-row stats: fcat = [m_hat || cs_hat] bf16, ssum = sq + csum ----
__global__ void rowstats_kernel(const float* __restrict__ xms,
                                __nv_bfloat16* __restrict__ fcat, float* __restrict__ ssum)
{
    __shared__ float sh[32];
    int row = blockIdx.x;
    const float* xmr = xms + (size_t)row * 1024;
    const float* xsr = xmr + 512;
    float s1 = 0.f, s2 = 0.f, s3 = 0.f;
    for (int j = threadIdx.x; j < F_DIM; j += blockDim.x) {
        float a = xmr[j]; s1 = fmaf(a, a, s1);
        float e = expf(xsr[j]); s2 = fmaf(e, e, s2); s3 += e;
    }
    s1 = blockReduceSum(s1, sh);
    s2 = blockReduceSum(s2, sh);
    s3 = blockReduceSum(s3, sh);
    float dm = fmaxf(sqrtf(s1), 1e-12f);
    float dc = fmaxf(sqrtf(s2), 1e-12f);
    if (threadIdx.x == 0) ssum[row] = s1 / (dm * dm) + s3 / dc;
    float rdm = 1.f / dm;
    float rqc = rsqrtf(dc);   // cs = sqrt(e/dc) = exp(0.5 x) * dc^-0.5
    for (int j = threadIdx.x; j < F_DIM; j += blockDim.x) {
        fcat[(size_t)row * 1024 + j]       = __float2bfloat16(xmr[j] * rdm);
        fcat[(size_t)row * 1024 + 512 + j] = __float2bfloat16(expf(0.5f * xsr[j]) * rqc);
    }
}

__global__ void rnreduce_kernel(const float* __restrict__ rnpart, float* __restrict__ rn) {
    int row = blockIdx.x * 256 + threadIdx.x;
    float s = 0.f;
    #pragma unroll
    for (int p = 0; p < 64; ++p) s += rnpart[(size_t)p * N_NODES + row];
    rn[row] = 1.f / fmaxf(sqrtf(s), 1e-12f);   // store reciprocal
}

// ---------------- fused adjacency + bf16-transpose + column partials ----------------
__global__ __launch_bounds__(256)
void adjT_kernel(const __nv_bfloat16* __restrict__ M1b, const float* __restrict__ rn,
                 const float* __restrict__ ne, const float* __restrict__ epsm,
                 const float* __restrict__ beta, const float* __restrict__ delta,
                 __nv_bfloat16* __restrict__ AnT, float* __restrict__ colpart)
{
    __shared__ __nv_bfloat16 tileT[64][66];
    const int c0 = blockIdx.x * 64, r0 = blockIdx.y * 64;
    const int t = threadIdx.x;
    const int jl = t & 63, ig = t >> 6;
    const int j = c0 + jl;
    const float b = beta[0], d = delta[0];
    float s = 0.f;
    #pragma unroll 4
    for (int k = 0; k < 16; ++k) {
        const int il = ig + 4 * k;
        const int i = r0 + il;
        const size_t idx = (size_t)i * N_NODES + j;
        float w = __bfloat162float(M1b[idx]) * rn[i];
        float tt = (1.f - b) * w + b * ne[idx];
        tt = fminf(fmaxf(tt, 1e-6f), 1.f - 1e-6f);
        float e = fminf(fmaxf(epsm[idx], 1e-6f), 1.f - 1e-6f);
        float num = tt * e;
        float sg = num / (num + (1.f - tt) * (1.f - e));
        float a = (sg > d) ? sg : 0.f;
        if (i == j && !(a > 0.f)) a += 1.f;
        tileT[il][jl] = __float2bfloat16(a);
        s += a;
    }
    colpart[(size_t)(blockIdx.y * 4 + ig) * N_NODES + j] = s;
    __syncthreads();
    const int il2 = t & 63;
    #pragma unroll
    for (int jj = t >> 6; jj < 64; jj += 4)
        AnT[(size_t)(c0 + jj) * N_NODES + r0 + il2] = tileT[il2][jj];
}

__global__ void colsum2_kernel(const float* __restrict__ part, float* __restrict__ dis) {
    int j = blockIdx.x * 256 + threadIdx.x;
    float s = 0.f;
    for (int p = 0; p < 256; ++p) s += part[(size_t)p * N_NODES + j];
    dis[j] = (s > 0.f) ? (1.f / sqrtf(s)) : 0.f;
}

// ---------------- transpose fp32 [R,C] -> bf16 [C,R], row scaling by dis[r] ----
template<bool SC>
__global__ void transposeb_kernel(const float* __restrict__ in, __nv_bfloat16* __restrict__ out,
                                  int R, int C, const float* __restrict__ dis)
{
    __shared__ float t[32][33];
    int r0 = blockIdx.y * 32, c0 = blockIdx.x * 32;
    int tx = threadIdx.x, ty = threadIdx.y;
    #pragma unroll
    for (int j = 0; j < 4; ++j)
        t[ty + j * 8][tx] = in[(size_t)(r0 + ty + j * 8) * C + c0 + tx];
    __syncthreads();
    float dr = SC ? dis[r0 + tx] : 1.f;
    #pragma unroll
    for (int j = 0; j < 4; ++j) {
        int c = c0 + ty + j * 8;
        float v = t[tx][ty + j * 8];
        out[(size_t)c * R + r0 + tx] = __float2bfloat16(SC ? v * dr : v);
    }
}

// ---------------- split-K reduce + dis + bias + relu + z-split output ----------------
__global__ void reduce_out_kernel(const float* __restrict__ part, const float* __restrict__ bias,
                                  const float* __restrict__ dis, float* __restrict__ out)
{
    int idx = blockIdx.x * 256 + threadIdx.x;   // over 4096*512
    int row = idx >> 9, col = idx & 511;
    float v = fmaf(part[idx] + part[idx + N_NODES * 512], dis[row], bias[col]);
    v = fmaxf(v, 0.f);
    out[(size_t)(col >> 8) * (N_NODES * H_DIM) + (size_t)row * H_DIM + (col & 255)] = v;
}

// ---------------- host ----------------
extern "C" void kernel_launch(void* const* d_in, const int* in_sizes, int n_in,
                              void* d_out, int out_size)
{
    const float* x        = (const float*)d_in[0];
    const float* new_edge = (const float*)d_in[1];
    const float* beta     = (const float*)d_in[2];
    const float* delta    = (const float*)d_in[3];
    const float* eps      = (const float*)d_in[4];
    const float* Wm       = (const float*)d_in[5];
    const float* bm       = (const float*)d_in[6];
    const float* Ws       = (const float*)d_in[7];
    const float* bs       = (const float*)d_in[8];
    const float* mW0      = (const float*)d_in[9];
    const float* mb0      = (const float*)d_in[10];
    const float* mW1      = (const float*)d_in[11];
    const float* mb1      = (const float*)d_in[12];
    const float* sW0      = (const float*)d_in[13];
    const float* sb0      = (const float*)d_in[14];
    const float* sW1      = (const float*)d_in[15];
    const float* sb1      = (const float*)d_in[16];
    float* out = (float*)d_out;

    float *xms, *t0, *t2, *ssum, *rn, *dis, *rnpart, *colpart, *bcat;
    __nv_bfloat16 *xhi, *xlo, *wThi, *wTlo, *xmshi, *xmslo, *fcat, *M1b, *AnT, *t0T, *t1hi, *t1lo, *t2T;
    cudaGetSymbolAddress((void**)&xhi, g_xhi);
    cudaGetSymbolAddress((void**)&xlo, g_xlo);
    cudaGetSymbolAddress((void**)&wThi, g_wThi);
    cudaGetSymbolAddress((void**)&wTlo, g_wTlo);
    cudaGetSymbolAddress((void**)&bcat, g_bcat);
    cudaGetSymbolAddress((void**)&xms, g_xms);
    cudaGetSymbolAddress((void**)&xmshi, g_xmshi);
    cudaGetSymbolAddress((void**)&xmslo, g_xmslo);
    cudaGetSymbolAddress((void**)&fcat, g_fcat);
    cudaGetSymbolAddress((void**)&M1b, g_M1b);
    cudaGetSymbolAddress((void**)&AnT, g_AnT);
    cudaGetSymbolAddress((void**)&t0, g_t0);
    cudaGetSymbolAddress((void**)&t0T, g_t0T);
    cudaGetSymbolAddress((void**)&t1hi, g_t1hi);
    cudaGetSymbolAddress((void**)&t1lo, g_t1lo);
    cudaGetSymbolAddress((void**)&t2, g_t2);
    cudaGetSymbolAddress((void**)&t2T, g_t2T);
    cudaGetSymbolAddress((void**)&ssum, g_ssum);
    cudaGetSymbolAddress((void**)&rn, g_rn);
    cudaGetSymbolAddress((void**)&dis, g_dis);
    cudaGetSymbolAddress((void**)&rnpart, g_rnpart);
    cudaGetSymbolAddress((void**)&colpart, g_colpart);

    const int SM_N_SPLIT = 2 * 2 * (128 + 128) * LDSH * 2;   // 81920
    const int SM_W_PLAIN = 3 * (128 + 256) * LDSH * 2;       // 92160
    cudaFuncSetAttribute(mma_nt<3,5,128>, cudaFuncAttributeMaxDynamicSharedMemorySize, SM_N_SPLIT);
    cudaFuncSetAttribute(mma_nt<3,0,128>, cudaFuncAttributeMaxDynamicSharedMemorySize, SM_N_SPLIT);
    cudaFuncSetAttribute(mma_nt<1,0,256>, cudaFuncAttributeMaxDynamicSharedMemorySize, SM_W_PLAIN);
    cudaFuncSetAttribute(mma_nt<1,3,256>, cudaFuncAttributeMaxDynamicSharedMemorySize, SM_W_PLAIN);
    cudaFuncSetAttribute(mma_nt<1,6,256>, cudaFuncAttributeMaxDynamicSharedMemorySize, SM_W_PLAIN);

    dim3 blk(256);
    dim3 tpb(32, 8);

    // ---- prep (batched) ----
    concat_bias_kernel<<<1, 256>>>(bm, bs, mb0, sb0, mb1, sb1, bcat);
    wprep_kernel<<<dim3(16, 16, 6), tpb>>>(Wm, Ws, mW0, sW0, mW1, sW1, wThi, wTlo);
    split_kernel<<<(N_NODES * F_DIM) / 256, blk>>>(x, xhi, xlo, N_NODES * F_DIM);

    // ---- projection: xms = x @ [Wm||Ws] + [bm||bs]; also writes hi/lo bf16 ----
    mma_nt<3,5,128><<<dim3(8, 32), blk, SM_N_SPLIT>>>(xhi, xlo, wThi, wTlo, xms, xmshi, xmslo,
        N_NODES, 1024, 512, 512, 512, 1024, bcat, nullptr, nullptr, nullptr, 0, 0, 0);

    // ---- row statistics -> fcat [m||cs], ssum ----
    rowstats_kernel<<<N_NODES, 256>>>(xms, fcat, ssum);

    // ---- single concatenated gram (K=1024) with fused ws (bf16 out) + rn partials ----
    mma_nt<1,3,256><<<dim3(16, 32), blk, SM_W_PLAIN>>>(fcat, nullptr, fcat, nullptr, nullptr,
        M1b, nullptr, N_NODES, N_NODES, 1024, 1024, 1024, N_NODES,
        nullptr, ssum, nullptr, rnpart, 0, 0, 0);
    rnreduce_kernel<<<N_NODES / 256, blk>>>(rnpart, rn);

    // ---- adjacency: adj + transpose-to-bf16 + colsum partials (fused) ----
    adjT_kernel<<<dim3(64, 64), blk>>>(M1b, rn, new_edge, eps, beta, delta, AnT, colpart);
    colsum2_kernel<<<N_NODES / 256, blk>>>(colpart, dis);

    // ---- encoder layer 1 ----
    mma_nt<3,0,128><<<dim3(4, 32, 2), blk, SM_N_SPLIT>>>(xmshi, xmslo, wThi + 524288, wTlo + 524288,
        t0, nullptr, nullptr, N_NODES, 512, 512, 1024, 512, 1024,
        nullptr, nullptr, nullptr, nullptr, 512, 262144, 512);
    transposeb_kernel<true><<<dim3(32, 128), tpb>>>(t0, t0T, N_NODES, 1024, dis);
    mma_nt<1,6,256><<<dim3(4, 32), blk, SM_W_PLAIN>>>(AnT, nullptr, t0T, nullptr, nullptr,
        t1hi, t1lo, N_NODES, 1024, N_NODES, N_NODES, N_NODES, 1024,
        bcat + 1024, nullptr, dis, nullptr, 0, 0, 0);

    // ---- encoder layer 2 ----
    mma_nt<3,0,128><<<dim3(2, 32, 2), blk, SM_N_SPLIT>>>(t1hi, t1lo, wThi + 1048576, wTlo + 1048576,
        t2, nullptr, nullptr, N_NODES, 256, 512, 1024, 512, 512,
        nullptr, nullptr, nullptr, nullptr, 512, 131072, 256);
    transposeb_kernel<true><<<dim3(16, 128), tpb>>>(t2, t2T, N_NODES, 512, dis);
    // split-K x2 adjacency aggregation -> partials in t0 (scratch reuse)
    mma_nt<1,0,256><<<dim3(2, 32, 2), blk, SM_W_PLAIN>>>(AnT, nullptr, t2T, nullptr, t0,
        nullptr, nullptr, N_NODES, 512, 2048, N_NODES, N_NODES, 512,
        nullptr, nullptr, nullptr, nullptr, 2048, 2048, (long)N_NODES * 512);
    reduce_out_kernel<<<(N_NODES * 512) / 256, blk>>>(t0, bcat + 2048, dis, out);
}

// round 10
// speedup vs baseline: 6.5480x; 1.1246x over previous
#include <cuda_runtime.h>
#include <cuda_bf16.h>
#include <math.h>
#include <stdint.h>

#define N_NODES 4096
#define F_DIM   512
#define H_DIM   256

// ---------------- scratch (static device allocations; no runtime alloc) ----------
__device__ __align__(128) __nv_bfloat16 g_xhi[N_NODES * F_DIM];
__device__ __align__(128) __nv_bfloat16 g_xlo[N_NODES * F_DIM];
__device__ __align__(128) __nv_bfloat16 g_wThi[1310720];
__device__ __align__(128) __nv_bfloat16 g_wTlo[1310720];
__device__ __align__(128) float g_bcat[2560];
__device__ __align__(128) float g_xms[N_NODES * 1024];
__device__ __align__(128) __nv_bfloat16 g_xmshi[N_NODES * 1024];
__device__ __align__(128) __nv_bfloat16 g_xmslo[N_NODES * 1024];
__device__ __align__(128) __nv_bfloat16 g_fcat[N_NODES * 1024];
__device__ __align__(128) __nv_bfloat16 g_M1b[(size_t)N_NODES * N_NODES];
__device__ __align__(128) __nv_bfloat16 g_AnT[(size_t)N_NODES * N_NODES];
__device__ __align__(128) float g_t0[N_NODES * 1024];
__device__ __align__(128) __nv_bfloat16 g_t0T[1024 * N_NODES];
__device__ __align__(128) __nv_bfloat16 g_t1hi[N_NODES * 1024];
__device__ __align__(128) __nv_bfloat16 g_t1lo[N_NODES * 1024];
__device__ __align__(128) float g_t2[N_NODES * 512];
__device__ __align__(128) __nv_bfloat16 g_t2T[512 * N_NODES];
__device__ __align__(128) float g_ssum[N_NODES];
__device__ __align__(128) float g_rn[N_NODES];
__device__ __align__(128) float g_dis[N_NODES];
__device__ __align__(128) float g_rnpart[64 * N_NODES];
__device__ __align__(128) float g_colsq2[32 * N_NODES];
__device__ __align__(128) float g_colpart[256 * N_NODES];

// ================= low-level helpers (sm_80+ features only) =================
__device__ __forceinline__ uint32_t smem_u32(const void* p) {
    uint32_t a;
    asm("{ .reg .u64 t; cvta.to.shared.u64 t, %1; cvt.u32.u64 %0, t; }" : "=r"(a) : "l"(p));
    return a;
}

#define CP_ASYNC_CG(dst, src) \
    asm volatile("cp.async.cg.shared.global [%0], [%1], 16;" :: "r"(dst), "l"(src))
#define CP_COMMIT() asm volatile("cp.async.commit_group;" ::: "memory")
#define CP_WAIT(n)  asm volatile("cp.async.wait_group %0;" :: "n"(n) : "memory")

__device__ __forceinline__ void ldmat_x4(uint32_t& r0, uint32_t& r1, uint32_t& r2, uint32_t& r3,
                                         uint32_t addr) {
    asm volatile("ldmatrix.sync.aligned.m8n8.x4.shared.b16 {%0,%1,%2,%3}, [%4];"
                 : "=r"(r0), "=r"(r1), "=r"(r2), "=r"(r3) : "r"(addr));
}

__device__ __forceinline__ void mma16816f(float* c, const uint32_t* a, const uint32_t* b) {
    asm volatile(
        "mma.sync.aligned.m16n8k16.row.col.f32.bf16.bf16.f32 "
        "{%0,%1,%2,%3}, {%4,%5,%6,%7}, {%8,%9}, {%0,%1,%2,%3};"
        : "+f"(c[0]), "+f"(c[1]), "+f"(c[2]), "+f"(c[3])
        : "r"(a[0]), "r"(a[1]), "r"(a[2]), "r"(a[3]), "r"(b[0]), "r"(b[1]));
}

// ================= generalized bf16 HMMA NT GEMM =================
// C[M,N] = A[M,K] @ B[N,K]^T. bf16 K-major inputs.
// SPLIT==3: near-fp32 via AhiBhi + AhiBlo + AloBhi (BNT=128 only).
// EPI: 0=store fp32
//      5=+bias, store fp32 AND hi/lo bf16
//      6=*dis[row]+bias+relu, store hi/lo bf16 only
#define BM 128
#define BK 32
#define LDSH 40   // BK + 8 halves padding

template<int SPLIT, int EPI, int BNT>
__global__ __launch_bounds__(256)
void mma_nt(const __nv_bfloat16* __restrict__ Ahi, const __nv_bfloat16* __restrict__ Alo,
            const __nv_bfloat16* __restrict__ Bhi, const __nv_bfloat16* __restrict__ Blo,
            float* __restrict__ C, __nv_bfloat16* __restrict__ Ohi, __nv_bfloat16* __restrict__ Olo,
            int M, int N, int K, int lda, int ldb, int ldc,
            const float* __restrict__ bias, const float* __restrict__ dis,
            long zA, long zB, long zC)
{
    constexpr int STAGES = (SPLIT == 1) ? 3 : 2;
    constexpr int WN     = BNT / 4;
    constexpr int NFR    = WN / 8;
    constexpr int TILEA  = BM * LDSH;
    constexpr int TILEB  = BNT * LDSH;
    constexpr int STAGE  = ((SPLIT == 3) ? 2 : 1) * (TILEA + TILEB);
    extern __shared__ __nv_bfloat16 smB[];

    const int tid  = threadIdx.x;
    const int wid  = tid >> 5;
    const int lane = tid & 31;
    const int wm = (wid & 1) * 64;
    const int wn = (wid >> 1) * WN;
    const int bm = blockIdx.y * BM;
    const int bn = blockIdx.x * BNT;

    const __nv_bfloat16* Ag  = Ahi + (size_t)blockIdx.z * zA + (size_t)bm * lda;
    const __nv_bfloat16* Bg  = Bhi + (size_t)blockIdx.z * zB + (size_t)bn * ldb;
    const __nv_bfloat16* Agl = (SPLIT == 3) ? Alo + (size_t)blockIdx.z * zA + (size_t)bm * lda : nullptr;
    const __nv_bfloat16* Bgl = (SPLIT == 3) ? Blo + (size_t)blockIdx.z * zB + (size_t)bn * ldb : nullptr;
    float* Cz = C + (size_t)blockIdx.z * zC;

    const uint32_t s_base = smem_u32(smB);
    const int lr0 = tid >> 2;
    const int lc  = (tid & 3) * 8;

    float acc[4][NFR][4];
    #pragma unroll
    for (int i = 0; i < 4; ++i)
        #pragma unroll
        for (int j = 0; j < NFR; ++j)
            #pragma unroll
            for (int q = 0; q < 4; ++q) acc[i][j][q] = 0.f;

    const int nt = K / BK;

    auto load_stage = [&](int st, int t) {
        const size_t kb = (size_t)t * BK + lc;
        const uint32_t sb = s_base + (uint32_t)(st * STAGE) * 2;
        #pragma unroll
        for (int h = 0; h < 2; ++h) {
            const int r = lr0 + h * 64;
            const uint32_t so = (uint32_t)(r * LDSH + lc) * 2;
            CP_ASYNC_CG(sb + so, Ag + (size_t)r * lda + kb);
            if (SPLIT == 3)
                CP_ASYNC_CG(sb + (uint32_t)(TILEA + TILEB) * 2 + so, Agl + (size_t)r * lda + kb);
        }
        #pragma unroll
        for (int h = 0; h < BNT / 64; ++h) {
            const int r = lr0 + h * 64;
            const uint32_t so = (uint32_t)(TILEA + r * LDSH + lc) * 2;
            CP_ASYNC_CG(sb + so, Bg + (size_t)r * ldb + kb);
            if (SPLIT == 3)
                CP_ASYNC_CG(sb + (uint32_t)(TILEA + TILEB) * 2 + so, Bgl + (size_t)r * ldb + kb);
        }
    };

    #pragma unroll
    for (int s = 0; s < STAGES - 1; ++s) { load_stage(s, s); CP_COMMIT(); }

    for (int t = 0; t < nt; ++t) {
        CP_WAIT(STAGES - 2);
        __syncthreads();
        if (t + STAGES - 1 < nt) { load_stage((t + STAGES - 1) % STAGES, t + STAGES - 1); CP_COMMIT(); }

        const uint32_t sb = s_base + (uint32_t)((t % STAGES) * STAGE) * 2;
        #pragma unroll
        for (int kk = 0; kk < BK; kk += 16) {
            uint32_t ah[4][4], al[4][4];
            #pragma unroll
            for (int mf = 0; mf < 4; ++mf) {
                int row = wm + mf * 16 + (lane & 15);
                uint32_t off = (uint32_t)(row * LDSH + kk + ((lane >> 4) << 3)) * 2;
                ldmat_x4(ah[mf][0], ah[mf][1], ah[mf][2], ah[mf][3], sb + off);
                if (SPLIT == 3)
                    ldmat_x4(al[mf][0], al[mf][1], al[mf][2], al[mf][3],
                             sb + (uint32_t)(TILEA + TILEB) * 2 + off);
            }
            uint32_t bh[NFR][2], bl[NFR][2];
            #pragma unroll
            for (int nf2 = 0; nf2 < NFR / 2; ++nf2) {
                int row = wn + nf2 * 16 + (lane & 7) + (((lane >> 4) & 1) << 3);
                uint32_t off = (uint32_t)(TILEA + row * LDSH + kk + (((lane >> 3) & 1) << 3)) * 2;
                uint32_t r0, r1, r2, r3;
                ldmat_x4(r0, r1, r2, r3, sb + off);
                bh[nf2 * 2 + 0][0] = r0; bh[nf2 * 2 + 0][1] = r1;
                bh[nf2 * 2 + 1][0] = r2; bh[nf2 * 2 + 1][1] = r3;
                if (SPLIT == 3) {
                    ldmat_x4(r0, r1, r2, r3, sb + (uint32_t)(TILEA + TILEB) * 2 + off);
                    bl[nf2 * 2 + 0][0] = r0; bl[nf2 * 2 + 0][1] = r1;
                    bl[nf2 * 2 + 1][0] = r2; bl[nf2 * 2 + 1][1] = r3;
                }
            }
            #pragma unroll
            for (int mf = 0; mf < 4; ++mf)
                #pragma unroll
                for (int nf = 0; nf < NFR; ++nf) {
                    mma16816f(acc[mf][nf], ah[mf], bh[nf]);
                    if (SPLIT == 3) {
                        mma16816f(acc[mf][nf], ah[mf], bl[nf]);
                        mma16816f(acc[mf][nf], al[mf], bh[nf]);
                    }
                }
        }
        __syncthreads();
    }

    // ---- epilogue ----
    #pragma unroll
    for (int mf = 0; mf < 4; ++mf) {
        #pragma unroll
        for (int nf = 0; nf < NFR; ++nf) {
            int rg = bm + wm + mf * 16 + (lane >> 2);
            int cg = bn + wn + nf * 8 + (lane & 3) * 2;
            float v0 = acc[mf][nf][0], v1 = acc[mf][nf][1];
            float v2 = acc[mf][nf][2], v3 = acc[mf][nf][3];
            if (EPI == 5) {
                float b0 = bias[cg], b1 = bias[cg + 1];
                v0 += b0; v1 += b1; v2 += b0; v3 += b1;
            }
            if (EPI == 6) {
                float d0 = dis[rg], d1 = dis[rg + 8];
                float b0 = bias[cg], b1 = bias[cg + 1];
                v0 = fmaxf(fmaf(v0, d0, b0), 0.f);
                v1 = fmaxf(fmaf(v1, d0, b1), 0.f);
                v2 = fmaxf(fmaf(v2, d1, b0), 0.f);
                v3 = fmaxf(fmaf(v3, d1, b1), 0.f);
            }
            if (EPI == 6) {
                __nv_bfloat162 h01, l01, h23, l23;
                h01.x = __float2bfloat16(v0); h01.y = __float2bfloat16(v1);
                l01.x = __float2bfloat16(v0 - __bfloat162float(h01.x));
                l01.y = __float2bfloat16(v1 - __bfloat162float(h01.y));
                h23.x = __float2bfloat16(v2); h23.y = __float2bfloat16(v3);
                l23.x = __float2bfloat16(v2 - __bfloat162float(h23.x));
                l23.y = __float2bfloat16(v3 - __bfloat162float(h23.y));
                *(__nv_bfloat162*)(Ohi + (size_t)rg * ldc + cg) = h01;
                *(__nv_bfloat162*)(Olo + (size_t)rg * ldc + cg) = l01;
                *(__nv_bfloat162*)(Ohi + (size_t)(rg + 8) * ldc + cg) = h23;
                *(__nv_bfloat162*)(Olo + (size_t)(rg + 8) * ldc + cg) = l23;
            } else {
                float2 p0; p0.x = v0; p0.y = v1;
                float2 p1; p1.x = v2; p1.y = v3;
                *(float2*)(Cz + (size_t)rg * ldc + cg) = p0;
                *(float2*)(Cz + (size_t)(rg + 8) * ldc + cg) = p1;
                if (EPI == 5) {
                    __nv_bfloat162 h01, l01, h23, l23;
                    h01.x = __float2bfloat16(v0); h01.y = __float2bfloat16(v1);
                    l01.x = __float2bfloat16(v0 - __bfloat162float(h01.x));
                    l01.y = __float2bfloat16(v1 - __bfloat162float(h01.y));
                    h23.x = __float2bfloat16(v2); h23.y = __float2bfloat16(v3);
                    l23.x = __float2bfloat16(v2 - __bfloat162float(h23.x));
                    l23.y = __float2bfloat16(v3 - __bfloat162float(h23.y));
                    *(__nv_bfloat162*)(Ohi + (size_t)rg * ldc + cg) = h01;
                    *(__nv_bfloat162*)(Olo + (size_t)rg * ldc + cg) = l01;
                    *(__nv_bfloat162*)(Ohi + (size_t)(rg + 8) * ldc + cg) = h23;
                    *(__nv_bfloat162*)(Olo + (size_t)(rg + 8) * ldc + cg) = l23;
                }
            }
        }
    }
}

// ================= symmetric gram + ws + rn partials (triangle grid) =================
// M1b = exp(2*fcat@fcat^T - ssum_i - ssum_j), bf16 out, symmetric.
// Grid: 272 CTAs covering tiles (m,b) with 2b >= m-1; strictly-above tiles (2b >= m+1)
// also mirror-write their transpose (smem-staged) and column sumsq partials.
__global__ __launch_bounds__(256)
void gram_sym(const __nv_bfloat16* __restrict__ A, __nv_bfloat16* __restrict__ M1b,
              const float* __restrict__ ssum, float* __restrict__ rnpart,
              float* __restrict__ colsq2)
{
    constexpr int BNT = 256, STAGES = 3, NFR = 8;
    constexpr int TILEA = 128 * LDSH, TILEB = 256 * LDSH, STAGE = TILEA + TILEB;
    extern __shared__ __nv_bfloat16 smB[];
    __nv_bfloat16* mir = smB;                              // 256 x 136 halves
    float* colsq = (float*)((char*)smB + 69632);           // 256 floats

    // triangle decode: blockIdx.x -> (m,b)
    int L = blockIdx.x, p = 0;
    while (L >= 2 * (16 - p)) { L -= 2 * (16 - p); ++p; }
    int m, b;
    if (L < 16 - p) { m = 2 * p; b = p + L; }
    else            { m = 2 * p + 1; b = p + L - (16 - p); }
    const int bm = m * 128, bn = b * 256;
    const bool above = (2 * b >= m + 1);

    const int tid  = threadIdx.x;
    const int wid  = tid >> 5;
    const int lane = tid & 31;
    const int wm = (wid & 1) * 64;
    const int wn = (wid >> 1) * 64;

    const __nv_bfloat16* Ag = A + (size_t)bm * 1024;
    const __nv_bfloat16* Bg = A + (size_t)bn * 1024;
    const uint32_t s_base = smem_u32(smB);
    const int lr0 = tid >> 2;
    const int lc  = (tid & 3) * 8;

    float acc[4][NFR][4];
    #pragma unroll
    for (int i = 0; i < 4; ++i)
        #pragma unroll
        for (int j = 0; j < NFR; ++j)
            #pragma unroll
            for (int q = 0; q < 4; ++q) acc[i][j][q] = 0.f;

    auto load_stage = [&](int st, int t) {
        const size_t kb = (size_t)t * BK + lc;
        const uint32_t sb = s_base + (uint32_t)(st * STAGE) * 2;
        #pragma unroll
        for (int h = 0; h < 2; ++h) {
            const int r = lr0 + h * 64;
            CP_ASYNC_CG(sb + (uint32_t)(r * LDSH + lc) * 2, Ag + (size_t)r * 1024 + kb);
        }
        #pragma unroll
        for (int h = 0; h < 4; ++h) {
            const int r = lr0 + h * 64;
            CP_ASYNC_CG(sb + (uint32_t)(TILEA + r * LDSH + lc) * 2, Bg + (size_t)r * 1024 + kb);
        }
    };

    #pragma unroll
    for (int s = 0; s < STAGES - 1; ++s) { load_stage(s, s); CP_COMMIT(); }

    for (int t = 0; t < 32; ++t) {
        CP_WAIT(STAGES - 2);
        __syncthreads();
        if (t + STAGES - 1 < 32) { load_stage((t + STAGES - 1) % STAGES, t + STAGES - 1); CP_COMMIT(); }

        const uint32_t sb = s_base + (uint32_t)((t % STAGES) * STAGE) * 2;
        #pragma unroll
        for (int kk = 0; kk < BK; kk += 16) {
            uint32_t ah[4][4];
            #pragma unroll
            for (int mf = 0; mf < 4; ++mf) {
                int row = wm + mf * 16 + (lane & 15);
                uint32_t off = (uint32_t)(row * LDSH + kk + ((lane >> 4) << 3)) * 2;
                ldmat_x4(ah[mf][0], ah[mf][1], ah[mf][2], ah[mf][3], sb + off);
            }
            uint32_t bh[NFR][2];
            #pragma unroll
            for (int nf2 = 0; nf2 < NFR / 2; ++nf2) {
                int row = wn + nf2 * 16 + (lane & 7) + (((lane >> 4) & 1) << 3);
                uint32_t off = (uint32_t)(TILEA + row * LDSH + kk + (((lane >> 3) & 1) << 3)) * 2;
                uint32_t r0, r1, r2, r3;
                ldmat_x4(r0, r1, r2, r3, sb + off);
                bh[nf2 * 2 + 0][0] = r0; bh[nf2 * 2 + 0][1] = r1;
                bh[nf2 * 2 + 1][0] = r2; bh[nf2 * 2 + 1][1] = r3;
            }
            #pragma unroll
            for (int mf = 0; mf < 4; ++mf)
                #pragma unroll
                for (int nf = 0; nf < NFR; ++nf)
                    mma16816f(acc[mf][nf], ah[mf], bh[nf]);
        }
        __syncthreads();
    }

    // ---- epilogue ----
    if (above) colsq[tid] = 0.f;
    __syncthreads();

    float rs[8];
    #pragma unroll
    for (int i = 0; i < 8; ++i) rs[i] = 0.f;
    float cs0[NFR], cs1[NFR];
    #pragma unroll
    for (int i = 0; i < NFR; ++i) { cs0[i] = 0.f; cs1[i] = 0.f; }

    #pragma unroll
    for (int mf = 0; mf < 4; ++mf) {
        #pragma unroll
        for (int nf = 0; nf < NFR; ++nf) {
            int rl = wm + mf * 16 + (lane >> 2);
            int cl = wn + nf * 8 + (lane & 3) * 2;
            int rg = bm + rl, cg = bn + cl;
            float sc0 = ssum[cg], sc1 = ssum[cg + 1];
            float sr0 = ssum[rg], sr1 = ssum[rg + 8];
            float v0 = expf(2.f * acc[mf][nf][0] - sr0 - sc0);
            float v1 = expf(2.f * acc[mf][nf][1] - sr0 - sc1);
            float v2 = expf(2.f * acc[mf][nf][2] - sr1 - sc0);
            float v3 = expf(2.f * acc[mf][nf][3] - sr1 - sc1);
            rs[mf * 2 + 0] = fmaf(v0, v0, fmaf(v1, v1, rs[mf * 2 + 0]));
            rs[mf * 2 + 1] = fmaf(v2, v2, fmaf(v3, v3, rs[mf * 2 + 1]));
            __nv_bfloat162 h01, h23;
            h01.x = __float2bfloat16(v0); h01.y = __float2bfloat16(v1);
            h23.x = __float2bfloat16(v2); h23.y = __float2bfloat16(v3);
            *(__nv_bfloat162*)(M1b + (size_t)rg * N_NODES + cg) = h01;
            *(__nv_bfloat162*)(M1b + (size_t)(rg + 8) * N_NODES + cg) = h23;
            if (above) {
                cs0[nf] = fmaf(v0, v0, fmaf(v2, v2, cs0[nf]));
                cs1[nf] = fmaf(v1, v1, fmaf(v3, v3, cs1[nf]));
                mir[(cl + 0) * 136 + rl]     = h01.x;
                mir[(cl + 1) * 136 + rl]     = h01.y;
                mir[(cl + 0) * 136 + rl + 8] = h23.x;
                mir[(cl + 1) * 136 + rl + 8] = h23.y;
            }
        }
    }

    // row partials (always)
    #pragma unroll
    for (int i = 0; i < 8; ++i) {
        rs[i] += __shfl_xor_sync(0xffffffffu, rs[i], 1);
        rs[i] += __shfl_xor_sync(0xffffffffu, rs[i], 2);
    }
    if ((lane & 3) == 0) {
        int pidx = b * 4 + (wid >> 1);
        #pragma unroll
        for (int mf = 0; mf < 4; ++mf) {
            int row = bm + wm + mf * 16 + (lane >> 2);
            rnpart[(size_t)pidx * N_NODES + row]     = rs[mf * 2 + 0];
            rnpart[(size_t)pidx * N_NODES + row + 8] = rs[mf * 2 + 1];
        }
    }

    if (above) {
        // column partials: reduce 8 row-groups per warp, combine warp pair via smem atomics
        #pragma unroll
        for (int nf = 0; nf < NFR; ++nf) {
            #pragma unroll
            for (int o = 4; o < 32; o <<= 1) {
                cs0[nf] += __shfl_xor_sync(0xffffffffu, cs0[nf], o);
                cs1[nf] += __shfl_xor_sync(0xffffffffu, cs1[nf], o);
            }
        }
        if (lane < 4) {
            #pragma unroll
            for (int nf = 0; nf < NFR; ++nf) {
                atomicAdd(&colsq[wn + nf * 8 + lane * 2], cs0[nf]);
                atomicAdd(&colsq[wn + nf * 8 + lane * 2 + 1], cs1[nf]);
            }
        }
        __syncthreads();
        // mirror writeout: M1b[bn+c][bm..bm+128) = mir[c][0..128)
        #pragma unroll 4
        for (int it = 0; it < 64; ++it) {
            int c = it * 4 + (tid >> 6);
            uint32_t vv = *(uint32_t*)&mir[c * 136 + (tid & 63) * 2];
            *(uint32_t*)(M1b + (size_t)(bn + c) * N_NODES + bm + (tid & 63) * 2) = vv;
        }
        colsq2[(size_t)m * N_NODES + bn + tid] = colsq[tid];
    }
}

// ---------------- batched weight prep: 6 transposes+splits in one launch ----------------
__global__ void wprep_kernel(const float* __restrict__ Wm, const float* __restrict__ Ws,
                             const float* __restrict__ mW0, const float* __restrict__ sW0,
                             const float* __restrict__ mW1, const float* __restrict__ sW1,
                             __nv_bfloat16* __restrict__ wThi, __nv_bfloat16* __restrict__ wTlo)
{
    const int z = blockIdx.z;
    const float* in; int C; long off;
    switch (z) {
        case 0:  in = Wm;  C = 512; off = 0;       break;
        case 1:  in = Ws;  C = 512; off = 262144;  break;
        case 2:  in = mW0; C = 512; off = 524288;  break;
        case 3:  in = sW0; C = 512; off = 786432;  break;
        case 4:  in = mW1; C = 256; off = 1048576; break;
        default: in = sW1; C = 256; off = 1179648; break;
    }
    if (blockIdx.x * 32 >= C) return;
    const int R = 512;
    __shared__ float t[32][33];
    int r0 = blockIdx.y * 32, c0 = blockIdx.x * 32;
    int tx = threadIdx.x, ty = threadIdx.y;
    #pragma unroll
    for (int j = 0; j < 4; ++j)
        t[ty + j * 8][tx] = in[(size_t)(r0 + ty + j * 8) * C + c0 + tx];
    __syncthreads();
    #pragma unroll
    for (int j = 0; j < 4; ++j) {
        int c = c0 + ty + j * 8;
        float v = t[tx][ty + j * 8];
        __nv_bfloat16 h = __float2bfloat16(v);
        __nv_bfloat16 l = __float2bfloat16(v - __bfloat162float(h));
        wThi[off + (size_t)c * R + r0 + tx] = h;
        wTlo[off + (size_t)c * R + r0 + tx] = l;
    }
}

__global__ void split_kernel(const float* __restrict__ in, __nv_bfloat16* __restrict__ ohi,
                             __nv_bfloat16* __restrict__ olo, int n)
{
    int idx = blockIdx.x * 256 + threadIdx.x;
    if (idx < n) {
        float v = in[idx];
        __nv_bfloat16 h = __float2bfloat16(v);
        ohi[idx] = h;
        olo[idx] = __float2bfloat16(v - __bfloat162float(h));
    }
}

__global__ void concat_bias_kernel(const float* bm, const float* bs, const float* mb0,
                                   const float* sb0, const float* mb1, const float* sb1,
                                   float* __restrict__ bcat)
{
    for (int i = threadIdx.x; i < 2560; i += blockDim.x) {
        float v;
        if (i < 512)        v = bm[i];
        else if (i < 1024)  v = bs[i - 512];
        else if (i < 1536)  v = mb0[i - 1024];
        else if (i < 2048)  v = sb0[i - 1536];
        else if (i < 2304)  v = mb1[i - 2048];
        else                v = sb1[i - 2304];
        bcat[i] = v;
    }
}

// ---------------- block reduction ----------------
__device__ __forceinline__ float blockReduceSum(float v, float* sh) {
    __syncthreads();
    int lane = threadIdx.x & 31, wid = threadIdx.x >> 5;
    #pragma unroll
    for (int o = 16; o; o >>= 1) v += __shfl_down_sync(0xffffffffu, v, o);
    if (lane == 0) sh[wid] = v;
    __syncthreads();
    if (wid == 0) {
        float r = (lane < ((blockDim.x + 31) >> 5)) ? sh[lane] : 0.f;
        #pragma unroll
        for (int o = 16; o; o >>= 1) r += __shfl_down_sync(0xffffffffu, r, o);
        if (lane == 0) sh[0] = r;
    }
    __syncthreads();
    return sh[0];
}

// ---------------- per-row stats: fcat = [m_hat || cs_hat] bf16, ssum = sq + csum ----
__global__ void rowstats_kernel(const float* __restrict__ xms,
                                __nv_bfloat16* __restrict__ fcat, float* __restrict__ ssum)
{
    __shared__ float sh[32];
    int row = blockIdx.x;
    const float* xmr = xms + (size_t)row * 1024;
    const float* xsr = xmr + 512;
    float s1 = 0.f, s2 = 0.f, s3 = 0.f;
    for (int j = threadIdx.x; j < F_DIM; j += blockDim.x) {
        float a = xmr[j]; s1 = fmaf(a, a, s1);
        float e = expf(xsr[j]); s2 = fmaf(e, e, s2); s3 += e;
    }
    s1 = blockReduceSum(s1, sh);
    s2 = blockReduceSum(s2, sh);
    s3 = blockReduceSum(s3, sh);
    float dm = fmaxf(sqrtf(s1), 1e-12f);
    float dc = fmaxf(sqrtf(s2), 1e-12f);
    if (threadIdx.x == 0) ssum[row] = s1 / (dm * dm) + s3 / dc;
    float rdm = 1.f / dm;
    float rqc = rsqrtf(dc);
    for (int j = threadIdx.x; j < F_DIM; j += blockDim.x) {
        fcat[(size_t)row * 1024 + j]       = __float2bfloat16(xmr[j] * rdm);
        fcat[(size_t)row * 1024 + 512 + j] = __float2bfloat16(expf(0.5f * xsr[j]) * rqc);
    }
}

__global__ void rnreduce_kernel(const float* __restrict__ rnpart,
                                const float* __restrict__ colsq2, float* __restrict__ rn) {
    int row = blockIdx.x * 256 + threadIdx.x;
    float s = 0.f;
    #pragma unroll
    for (int p = 0; p < 64; ++p) s += rnpart[(size_t)p * N_NODES + row];
    #pragma unroll
    for (int q = 0; q < 32; ++q) s += colsq2[(size_t)q * N_NODES + row];
    rn[row] = 1.f / fmaxf(sqrtf(s), 1e-12f);
}

// ---------------- fused adjacency + bf16-transpose + column partials ----------------
__global__ __launch_bounds__(256)
void adjT_kernel(const __nv_bfloat16* __restrict__ M1b, const float* __restrict__ rn,
                 const float* __restrict__ ne, const float* __restrict__ epsm,
                 const float* __restrict__ beta, const float* __restrict__ delta,
                 __nv_bfloat16* __restrict__ AnT, float* __restrict__ colpart)
{
    __shared__ __nv_bfloat16 tileT[64][66];
    const int c0 = blockIdx.x * 64, r0 = blockIdx.y * 64;
    const int t = threadIdx.x;
    const int jl = t & 63, ig = t >> 6;
    const int j = c0 + jl;
    const float b = beta[0], d = delta[0];
    float s = 0.f;
    #pragma unroll 4
    for (int k = 0; k < 16; ++k) {
        const int il = ig + 4 * k;
        const int i = r0 + il;
        const size_t idx = (size_t)i * N_NODES + j;
        float w = __bfloat162float(M1b[idx]) * rn[i];
        float tt = (1.f - b) * w + b * ne[idx];
        tt = fminf(fmaxf(tt, 1e-6f), 1.f - 1e-6f);
        float e = fminf(fmaxf(epsm[idx], 1e-6f), 1.f - 1e-6f);
        float num = tt * e;
        float sg = num / (num + (1.f - tt) * (1.f - e));
        float a = (sg > d) ? sg : 0.f;
        if (i == j && !(a > 0.f)) a += 1.f;
        tileT[il][jl] = __float2bfloat16(a);
        s += a;
    }
    colpart[(size_t)(blockIdx.y * 4 + ig) * N_NODES + j] = s;
    __syncthreads();
    const int il2 = t & 63;
    #pragma unroll
    for (int jj = t >> 6; jj < 64; jj += 4)
        AnT[(size_t)(c0 + jj) * N_NODES + r0 + il2] = tileT[il2][jj];
}

__global__ void colsum2_kernel(const float* __restrict__ part, float* __restrict__ dis) {
    int j = blockIdx.x * 256 + threadIdx.x;
    float s = 0.f;
    for (int p = 0; p < 256; ++p) s += part[(size_t)p * N_NODES + j];
    dis[j] = (s > 0.f) ? (1.f / sqrtf(s)) : 0.f;
}

// ---------------- transpose fp32 [R,C] -> bf16 [C,R], row scaling by dis[r] ----
template<bool SC>
__global__ void transposeb_kernel(const float* __restrict__ in, __nv_bfloat16* __restrict__ out,
                                  int R, int C, const float* __restrict__ dis)
{
    __shared__ float t[32][33];
    int r0 = blockIdx.y * 32, c0 = blockIdx.x * 32;
    int tx = threadIdx.x, ty = threadIdx.y;
    #pragma unroll
    for (int j = 0; j < 4; ++j)
        t[ty + j * 8][tx] = in[(size_t)(r0 + ty + j * 8) * C + c0 + tx];
    __syncthreads();
    float dr = SC ? dis[r0 + tx] : 1.f;
    #pragma unroll
    for (int j = 0; j < 4; ++j) {
        int c = c0 + ty + j * 8;
        float v = t[tx][ty + j * 8];
        out[(size_t)c * R + r0 + tx] = __float2bfloat16(SC ? v * dr : v);
    }
}

// ---------------- split-K reduce + dis + bias + relu + z-split output ----------------
__global__ void reduce_out_kernel(const float* __restrict__ part, const float* __restrict__ bias,
                                  const float* __restrict__ dis, float* __restrict__ out)
{
    int idx = blockIdx.x * 256 + threadIdx.x;   // over 4096*512
    int row = idx >> 9, col = idx & 511;
    float v = fmaf(part[idx] + part[idx + N_NODES * 512], dis[row], bias[col]);
    v = fmaxf(v, 0.f);
    out[(size_t)(col >> 8) * (N_NODES * H_DIM) + (size_t)row * H_DIM + (col & 255)] = v;
}

// ---------------- host ----------------
extern "C" void kernel_launch(void* const* d_in, const int* in_sizes, int n_in,
                              void* d_out, int out_size)
{
    const float* x        = (const float*)d_in[0];
    const float* new_edge = (const float*)d_in[1];
    const float* beta     = (const float*)d_in[2];
    const float* delta    = (const float*)d_in[3];
    const float* eps      = (const float*)d_in[4];
    const float* Wm       = (const float*)d_in[5];
    const float* bm       = (const float*)d_in[6];
    const float* Ws       = (const float*)d_in[7];
    const float* bs       = (const float*)d_in[8];
    const float* mW0      = (const float*)d_in[9];
    const float* mb0      = (const float*)d_in[10];
    const float* mW1      = (const float*)d_in[11];
    const float* mb1      = (const float*)d_in[12];
    const float* sW0      = (const float*)d_in[13];
    const float* sb0      = (const float*)d_in[14];
    const float* sW1      = (const float*)d_in[15];
    const float* sb1      = (const float*)d_in[16];
    float* out = (float*)d_out;

    float *xms, *t0, *t2, *ssum, *rn, *dis, *rnpart, *colsq2, *colpart, *bcat;
    __nv_bfloat16 *xhi, *xlo, *wThi, *wTlo, *xmshi, *xmslo, *fcat, *M1b, *AnT, *t0T, *t1hi, *t1lo, *t2T;
    cudaGetSymbolAddress((void**)&xhi, g_xhi);
    cudaGetSymbolAddress((void**)&xlo, g_xlo);
    cudaGetSymbolAddress((void**)&wThi, g_wThi);
    cudaGetSymbolAddress((void**)&wTlo, g_wTlo);
    cudaGetSymbolAddress((void**)&bcat, g_bcat);
    cudaGetSymbolAddress((void**)&xms, g_xms);
    cudaGetSymbolAddress((void**)&xmshi, g_xmshi);
    cudaGetSymbolAddress((void**)&xmslo, g_xmslo);
    cudaGetSymbolAddress((void**)&fcat, g_fcat);
    cudaGetSymbolAddress((void**)&M1b, g_M1b);
    cudaGetSymbolAddress((void**)&AnT, g_AnT);
    cudaGetSymbolAddress((void**)&t0, g_t0);
    cudaGetSymbolAddress((void**)&t0T, g_t0T);
    cudaGetSymbolAddress((void**)&t1hi, g_t1hi);
    cudaGetSymbolAddress((void**)&t1lo, g_t1lo);
    cudaGetSymbolAddress((void**)&t2, g_t2);
    cudaGetSymbolAddress((void**)&t2T, g_t2T);
    cudaGetSymbolAddress((void**)&ssum, g_ssum);
    cudaGetSymbolAddress((void**)&rn, g_rn);
    cudaGetSymbolAddress((void**)&dis, g_dis);
    cudaGetSymbolAddress((void**)&rnpart, g_rnpart);
    cudaGetSymbolAddress((void**)&colsq2, g_colsq2);
    cudaGetSymbolAddress((void**)&colpart, g_colpart);

    const int SM_N_SPLIT = 2 * 2 * (128 + 128) * LDSH * 2;   // 81920
    const int SM_W_PLAIN = 3 * (128 + 256) * LDSH * 2;       // 92160
    cudaFuncSetAttribute(mma_nt<3,5,128>, cudaFuncAttributeMaxDynamicSharedMemorySize, SM_N_SPLIT);
    cudaFuncSetAttribute(mma_nt<3,0,128>, cudaFuncAttributeMaxDynamicSharedMemorySize, SM_N_SPLIT);
    cudaFuncSetAttribute(mma_nt<1,0,256>, cudaFuncAttributeMaxDynamicSharedMemorySize, SM_W_PLAIN);
    cudaFuncSetAttribute(mma_nt<1,6,256>, cudaFuncAttributeMaxDynamicSharedMemorySize, SM_W_PLAIN);
    cudaFuncSetAttribute(gram_sym, cudaFuncAttributeMaxDynamicSharedMemorySize, SM_W_PLAIN);

    dim3 blk(256);
    dim3 tpb(32, 8);

    // ---- prep (batched) ----
    concat_bias_kernel<<<1, 256>>>(bm, bs, mb0, sb0, mb1, sb1, bcat);
    wprep_kernel<<<dim3(16, 16, 6), tpb>>>(Wm, Ws, mW0, sW0, mW1, sW1, wThi, wTlo);
    split_kernel<<<(N_NODES * F_DIM) / 256, blk>>>(x, xhi, xlo, N_NODES * F_DIM);
    cudaMemsetAsync(rnpart, 0, 64 * N_NODES * sizeof(float));
    cudaMemsetAsync(colsq2, 0, 32 * N_NODES * sizeof(float));

    // ---- projection: xms = x @ [Wm||Ws] + [bm||bs]; also writes hi/lo bf16 ----
    mma_nt<3,5,128><<<dim3(8, 32), blk, SM_N_SPLIT>>>(xhi, xlo, wThi, wTlo, xms, xmshi, xmslo,
        N_NODES, 1024, 512, 512, 512, 1024, bcat, nullptr, 0, 0, 0);

    // ---- row statistics -> fcat [m||cs], ssum ----
    rowstats_kernel<<<N_NODES, 256>>>(xms, fcat, ssum);

    // ---- symmetric gram + fused ws (bf16 out) + rn partials (triangle grid) ----
    gram_sym<<<272, blk, SM_W_PLAIN>>>(fcat, M1b, ssum, rnpart, colsq2);
    rnreduce_kernel<<<N_NODES / 256, blk>>>(rnpart, colsq2, rn);

    // ---- adjacency: adj + transpose-to-bf16 + colsum partials (fused) ----
    adjT_kernel<<<dim3(64, 64), blk>>>(M1b, rn, new_edge, eps, beta, delta, AnT, colpart);
    colsum2_kernel<<<N_NODES / 256, blk>>>(colpart, dis);

    // ---- encoder layer 1 ----
    mma_nt<3,0,128><<<dim3(4, 32, 2), blk, SM_N_SPLIT>>>(xmshi, xmslo, wThi + 524288, wTlo + 524288,
        t0, nullptr, nullptr, N_NODES, 512, 512, 1024, 512, 1024,
        nullptr, nullptr, 512, 262144, 512);
    transposeb_kernel<true><<<dim3(32, 128), tpb>>>(t0, t0T, N_NODES, 1024, dis);
    mma_nt<1,6,256><<<dim3(4, 32), blk, SM_W_PLAIN>>>(AnT, nullptr, t0T, nullptr, nullptr,
        t1hi, t1lo, N_NODES, 1024, N_NODES, N_NODES, N_NODES, 1024,
        bcat + 1024, dis, 0, 0, 0);

    // ---- encoder layer 2 ----
    mma_nt<3,0,128><<<dim3(2, 32, 2), blk, SM_N_SPLIT>>>(t1hi, t1lo, wThi + 1048576, wTlo + 1048576,
        t2, nullptr, nullptr, N_NODES, 256, 512, 1024, 512, 512,
        nullptr, nullptr, 512, 131072, 256);
    transposeb_kernel<true><<<dim3(16, 128), tpb>>>(t2, t2T, N_NODES, 512, dis);
    // split-K x2 adjacency aggregation -> partials in t0 (scratch reuse)
    mma_nt<1,0,256><<<dim3(2, 32, 2), blk, SM_W_PLAIN>>>(AnT, nullptr, t2T, nullptr, t0,
        nullptr, nullptr, N_NODES, 512, 2048, N_NODES, N_NODES, 512,
        nullptr, nullptr, 2048, 2048, (long)N_NODES * 512);
    reduce_out_kernel<<<(N_NODES * 512) / 256, blk>>>(t0, bcat + 2048, dis, out);
}